// round 7
// baseline (speedup 1.0000x reference)
#include <cuda_runtime.h>
#include <cuda_bf16.h>
#include <math.h>
#include <cstdint>

// Problem constants
#define BATCH 8
#define LEN   2048
#define DIM   1024
#define DFF   4096
#define NFFT  4096
#define LN_EPS 1e-5f
#define WFS   2064        // half-spectrum row stride

// ---------------------------------------------------------------------------
// Static device scratch (no allocation allowed)
// ---------------------------------------------------------------------------
__device__ float  g_lnz  [BATCH * LEN * DIM];
__device__ float  g_lnzT [BATCH * DIM * LEN];
__device__ float  g_hfilt[LEN * DIM];
__device__ float  g_hfiltT[DIM * LEN];
__device__ float  g_hidT [DIM * LEN];
__device__ float2 g_wfh  [DIM * WFS];
__device__ float2 g_twd  [1024];
__device__ float  g_znewT[BATCH * DIM * LEN];
__device__ float  g_znew [BATCH * LEN * DIM];
__device__ __nv_bfloat16 g_Xh[BATCH * LEN * DIM];
__device__ __nv_bfloat16 g_Xl[BATCH * LEN * DIM];
__device__ __nv_bfloat16 g_Hh[BATCH * LEN * DFF];
__device__ __nv_bfloat16 g_Hl[BATCH * LEN * DFF];
__device__ __nv_bfloat16 g_posh[LEN * DIM];
__device__ __nv_bfloat16 g_posl[LEN * DIM];
__device__ __nv_bfloat16 g_wp1t_h[DFF * DIM];
__device__ __nv_bfloat16 g_wp1t_l[DFF * DIM];
__device__ __nv_bfloat16 g_wp2t_h[DIM * DFF];
__device__ __nv_bfloat16 g_wp2t_l[DIM * DFF];
__device__ __nv_bfloat16 g_w1t_h[DFF * DIM];
__device__ __nv_bfloat16 g_w1t_l[DFF * DIM];
__device__ __nv_bfloat16 g_w2t_h[DIM * DFF];
__device__ __nv_bfloat16 g_w2t_l[DIM * DFF];

// ---------------------------------------------------------------------------
// PTX wrappers (baseline sm_80+ only)
// ---------------------------------------------------------------------------
__device__ __forceinline__ uint32_t smem_u32(const void* p) {
    uint32_t a;
    asm("{ .reg .u64 t; cvta.to.shared.u64 t, %1; cvt.u32.u64 %0, t; }"
        : "=r"(a) : "l"(p));
    return a;
}
__device__ __forceinline__ void cpasync16(uint32_t s, const void* g) {
    asm volatile("cp.async.cg.shared.global [%0], [%1], 16;"
                 :: "r"(s), "l"(g) : "memory");
}
__device__ __forceinline__ void cp_commit() {
    asm volatile("cp.async.commit_group;" ::: "memory");
}
template <int N>
__device__ __forceinline__ void cp_wait() {
    asm volatile("cp.async.wait_group %0;" :: "n"(N) : "memory");
}
__device__ __forceinline__ void ldm_x4(uint32_t& r0, uint32_t& r1,
                                       uint32_t& r2, uint32_t& r3, uint32_t a) {
    asm volatile("ldmatrix.sync.aligned.m8n8.x4.shared.b16 {%0,%1,%2,%3}, [%4];"
                 : "=r"(r0), "=r"(r1), "=r"(r2), "=r"(r3) : "r"(a));
}
__device__ __forceinline__ void mma_bf16(float4& d, const uint32_t* a,
                                         uint32_t b0, uint32_t b1) {
    asm volatile(
        "mma.sync.aligned.m16n8k16.row.col.f32.bf16.bf16.f32 "
        "{%0,%1,%2,%3}, {%4,%5,%6,%7}, {%8,%9}, {%0,%1,%2,%3};"
        : "+f"(d.x), "+f"(d.y), "+f"(d.z), "+f"(d.w)
        : "r"(a[0]), "r"(a[1]), "r"(a[2]), "r"(a[3]), "r"(b0), "r"(b1));
}

// ---------------------------------------------------------------------------
// HMMA GEMM: C[M,N] = epi( (Ah+Al)[M,K] @ (Bh+Bl)[N,K]^T + bias )
// R4 skeleton: block 128x128, BK=32, 8 warps (4m x 2n), warp tile 32x64,
// 2-stage cp.async pipeline, 80B-padded rows. B loads via ldm_x4 (2 n8/ld).
// ---------------------------------------------------------------------------
#define GBM 128
#define GBN 128
#define GBK 32
#define TPAD 40                      // padded row stride in bf16 elems (80B)
#define TILE_B (128 * TPAD * 2)      // 10240 bytes per matrix tile
#define STAGE_B (4 * TILE_B)         // Ah, Al, Bh, Bl
#define GEMM_SMEM (2 * STAGE_B)      // 81920 bytes

template <int ACT, bool SPLIT_OUT, bool HAS_ADD>
__global__ __launch_bounds__(256)
void gemm_mma(const __nv_bfloat16* __restrict__ Ah, const __nv_bfloat16* __restrict__ Al,
              const __nv_bfloat16* __restrict__ Bh, const __nv_bfloat16* __restrict__ Bl,
              const float* __restrict__ bias, const float* __restrict__ add,
              float* __restrict__ Cf, __nv_bfloat16* __restrict__ Ch,
              __nv_bfloat16* __restrict__ Cl, int M, int N, int K) {
    extern __shared__ char smem[];
    const uint32_t sbase = smem_u32(smem);
    const int tid  = threadIdx.x;
    const int lane = tid & 31;
    const int wid  = tid >> 5;
    const int wm   = wid & 3;        // 4 warp rows (32 M each)
    const int wn   = wid >> 2;       // 2 warp cols (64 N each)
    const int bm = blockIdx.y * GBM;
    const int bn = blockIdx.x * GBN;

    const int r0 = tid >> 2;
    const int c0 = tid & 3;
    const uint32_t so0 = (uint32_t)(r0 * 80 + c0 * 16);
    const uint32_t so1 = (uint32_t)((r0 + 64) * 80 + c0 * 16);

    auto issue_loads = [&](int stage, int k0) {
        const uint32_t sb = sbase + stage * STAGE_B;
        const size_t ga0 = (size_t)(bm + r0) * K + k0 + c0 * 8;
        const size_t ga1 = (size_t)(bm + r0 + 64) * K + k0 + c0 * 8;
        const size_t gb0 = (size_t)(bn + r0) * K + k0 + c0 * 8;
        const size_t gb1 = (size_t)(bn + r0 + 64) * K + k0 + c0 * 8;
        cpasync16(sb + so0,              Ah + ga0);
        cpasync16(sb + so1,              Ah + ga1);
        cpasync16(sb + TILE_B + so0,     Al + ga0);
        cpasync16(sb + TILE_B + so1,     Al + ga1);
        cpasync16(sb + 2 * TILE_B + so0, Bh + gb0);
        cpasync16(sb + 2 * TILE_B + so1, Bh + gb1);
        cpasync16(sb + 3 * TILE_B + so0, Bl + gb0);
        cpasync16(sb + 3 * TILE_B + so1, Bl + gb1);
        cp_commit();
    };

    float4 acc[2][8];
#pragma unroll
    for (int i = 0; i < 2; i++)
#pragma unroll
        for (int j = 0; j < 8; j++) acc[i][j] = make_float4(0.f, 0.f, 0.f, 0.f);

    // ldmatrix lane addressing
    const int a_row = (lane & 7) + ((lane >> 3) & 1) * 8;   // row within 16
    const int a_kc  = ((lane >> 4) & 1) * 8;                // k 0 or 8
    // B x4 mapping: lanes 0-7 -> (n0:8,k0), 8-15 -> (n0:8,k8),
    //               16-23 -> (n8:16,k0), 24-31 -> (n8:16,k8)
    const int b_row = (lane & 7) + ((lane >> 4) & 1) * 8;
    const int b_kc  = ((lane >> 3) & 1) * 8;

    const int NT = K / GBK;
    issue_loads(0, 0);

    for (int kt = 0; kt < NT; kt++) {
        if (kt + 1 < NT) issue_loads((kt + 1) & 1, (kt + 1) * GBK);
        if (kt + 1 < NT) cp_wait<1>(); else cp_wait<0>();
        __syncthreads();

        const uint32_t st = sbase + (kt & 1) * STAGE_B;
        const uint32_t As_h = st;
        const uint32_t As_l = st + TILE_B;
        const uint32_t Bs_h = st + 2 * TILE_B;
        const uint32_t Bs_l = st + 3 * TILE_B;

#pragma unroll
        for (int k16 = 0; k16 < 2; k16++) {
            uint32_t ah[2][4], al[2][4];
#pragma unroll
            for (int i = 0; i < 2; i++) {
                const uint32_t ao =
                    (uint32_t)((wm * 32 + i * 16 + a_row) * 80 +
                               (k16 * 16 + a_kc) * 2);
                ldm_x4(ah[i][0], ah[i][1], ah[i][2], ah[i][3], As_h + ao);
                ldm_x4(al[i][0], al[i][1], al[i][2], al[i][3], As_l + ao);
            }
#pragma unroll
            for (int jj = 0; jj < 4; jj++) {     // two n8 tiles per ldm_x4
                const uint32_t bo =
                    (uint32_t)((wn * 64 + jj * 16 + b_row) * 80 +
                               (k16 * 16 + b_kc) * 2);
                uint32_t bh0, bh1, bh2, bh3, bl0, bl1, bl2, bl3;
                ldm_x4(bh0, bh1, bh2, bh3, Bs_h + bo);
                ldm_x4(bl0, bl1, bl2, bl3, Bs_l + bo);
#pragma unroll
                for (int i = 0; i < 2; i++) {
                    mma_bf16(acc[i][jj * 2], ah[i], bh0, bh1);
                    mma_bf16(acc[i][jj * 2], ah[i], bl0, bl1);
                    mma_bf16(acc[i][jj * 2], al[i], bh0, bh1);
                    mma_bf16(acc[i][jj * 2 + 1], ah[i], bh2, bh3);
                    mma_bf16(acc[i][jj * 2 + 1], ah[i], bl2, bl3);
                    mma_bf16(acc[i][jj * 2 + 1], al[i], bh2, bh3);
                }
            }
        }
        __syncthreads();
    }

    // epilogue: warp tile 32x64 at (bm + wm*32, bn + wn*64)
    const int qr = lane >> 2;
    const int qc = (lane & 3) * 2;
#pragma unroll
    for (int i = 0; i < 2; i++) {
#pragma unroll
        for (int j = 0; j < 8; j++) {
            const int gr0 = bm + wm * 32 + i * 16 + qr;
            const int gc  = bn + wn * 64 + j * 8 + qc;
            const float b0 = bias[gc];
            const float b1 = bias[gc + 1];
            float v00 = acc[i][j].x + b0, v01 = acc[i][j].y + b1;
            float v10 = acc[i][j].z + b0, v11 = acc[i][j].w + b1;
            if (ACT == 1) {
                v00 = v00 / (1.0f + expf(-v00));
                v01 = v01 / (1.0f + expf(-v01));
                v10 = v10 / (1.0f + expf(-v10));
                v11 = v11 / (1.0f + expf(-v11));
            }
            if (HAS_ADD) {
                v00 += add[(size_t)gr0 * N + gc];
                v01 += add[(size_t)gr0 * N + gc + 1];
                v10 += add[(size_t)(gr0 + 8) * N + gc];
                v11 += add[(size_t)(gr0 + 8) * N + gc + 1];
            }
            if (SPLIT_OUT) {
                __nv_bfloat16 h00 = __float2bfloat16(v00);
                __nv_bfloat16 h01 = __float2bfloat16(v01);
                __nv_bfloat16 h10 = __float2bfloat16(v10);
                __nv_bfloat16 h11 = __float2bfloat16(v11);
                *reinterpret_cast<__nv_bfloat162*>(Ch + (size_t)gr0 * N + gc) =
                    __nv_bfloat162(h00, h01);
                *reinterpret_cast<__nv_bfloat162*>(Ch + (size_t)(gr0 + 8) * N + gc) =
                    __nv_bfloat162(h10, h11);
                *reinterpret_cast<__nv_bfloat162*>(Cl + (size_t)gr0 * N + gc) =
                    __nv_bfloat162(__float2bfloat16(v00 - __bfloat162float(h00)),
                                   __float2bfloat16(v01 - __bfloat162float(h01)));
                *reinterpret_cast<__nv_bfloat162*>(Cl + (size_t)(gr0 + 8) * N + gc) =
                    __nv_bfloat162(__float2bfloat16(v10 - __bfloat162float(h10)),
                                   __float2bfloat16(v11 - __bfloat162float(h11)));
            } else {
                *reinterpret_cast<float2*>(Cf + (size_t)gr0 * N + gc) =
                    make_float2(v00, v01);
                *reinterpret_cast<float2*>(Cf + (size_t)(gr0 + 8) * N + gc) =
                    make_float2(v10, v11);
            }
        }
    }
}

// ---------------------------------------------------------------------------
// Prep kernels
// ---------------------------------------------------------------------------
__global__ void transpose_split(const float* __restrict__ W,
                                __nv_bfloat16* __restrict__ Th,
                                __nv_bfloat16* __restrict__ Tl, int K, int N) {
    __shared__ float t[32][33];
    const int n0 = blockIdx.x * 32, k0 = blockIdx.y * 32;
    const int tx = threadIdx.x, ty = threadIdx.y;
#pragma unroll
    for (int dy = 0; dy < 32; dy += 8)
        t[ty + dy][tx] = W[(size_t)(k0 + ty + dy) * N + n0 + tx];
    __syncthreads();
#pragma unroll
    for (int dy = 0; dy < 32; dy += 8) {
        const int n = n0 + ty + dy, k = k0 + tx;
        float v = t[tx][ty + dy];
        __nv_bfloat16 h = __float2bfloat16(v);
        Th[(size_t)n * K + k] = h;
        Tl[(size_t)n * K + k] = __float2bfloat16(v - __bfloat162float(h));
    }
}

__global__ void split_f32(const float* __restrict__ x, __nv_bfloat16* __restrict__ h,
                          __nv_bfloat16* __restrict__ l, int n) {
    int i = blockIdx.x * 256 + threadIdx.x;
    if (i < n) {
        float v = x[i];
        __nv_bfloat16 hh = __float2bfloat16(v);
        h[i] = hh;
        l[i] = __float2bfloat16(v - __bfloat162float(hh));
    }
}

__global__ void transpose32f(const float* __restrict__ in, float* __restrict__ out,
                             int R, int C) {
    __shared__ float t[32][33];
    const size_t boff = (size_t)blockIdx.z * R * C;
    const float* ip = in + boff;
    float* op = out + boff;
    const int r0 = blockIdx.y * 32, c0 = blockIdx.x * 32;
    const int tx = threadIdx.x, ty = threadIdx.y;
#pragma unroll
    for (int dy = 0; dy < 32; dy += 8)
        t[ty + dy][tx] = ip[(size_t)(r0 + ty + dy) * C + c0 + tx];
    __syncthreads();
#pragma unroll
    for (int dy = 0; dy < 32; dy += 8)
        op[(size_t)(c0 + ty + dy) * R + r0 + tx] = t[tx][ty + dy];
}

__global__ void init_twd(float2* __restrict__ twd) {
    int k = blockIdx.x * 256 + threadIdx.x;
    if (k < 1024) {
        double s, c;
        sincos(-6.283185307179586476925286766559 * (double)k / 4096.0, &s, &c);
        twd[k] = make_float2((float)c, (float)s);
    }
}

// ---------------------------------------------------------------------------
// Radix-4 4096-point FFT in smem, 256 threads, padded addressing
// ---------------------------------------------------------------------------
#define PIDX(i) ((i) + ((i) >> 4))

__device__ __forceinline__ float2 cmul(float2 a, float2 b) {
    return make_float2(a.x * b.x - a.y * b.y, a.x * b.y + a.y * b.x);
}

template <int SIGN>
__device__ void fft4096_r4(float2* sm, const float2* tw) {
    const int tid = threadIdx.x;
    __syncthreads();
    for (int i = tid; i < NFFT; i += 256) {
        int b = __brev(i) >> 20;
        int r = ((b & 0x555) << 1) | ((b >> 1) & 0x555);
        if (r > i) {
            float2 t = sm[PIDX(i)];
            sm[PIDX(i)] = sm[PIDX(r)];
            sm[PIDX(r)] = t;
        }
    }
    __syncthreads();
#pragma unroll
    for (int st = 0; st < 6; st++) {
        const int len = 4 << (2 * st);
        const int q   = len >> 2;
        const int S   = NFFT / len;
#pragma unroll
        for (int u = 0; u < 4; u++) {
            const int bf = tid + u * 256;
            const int g  = bf / q;
            const int j  = bf - g * q;
            const int base = g * len + j;
            float2 x0 = sm[PIDX(base)];
            float2 x1 = sm[PIDX(base + q)];
            float2 x2 = sm[PIDX(base + 2 * q)];
            float2 x3 = sm[PIDX(base + 3 * q)];
            float2 w1 = tw[j * S];
            if (SIGN > 0) w1.y = -w1.y;
            float2 w2 = cmul(w1, w1);
            float2 w3 = cmul(w1, w2);
            x1 = cmul(x1, w1);
            x2 = cmul(x2, w2);
            x3 = cmul(x3, w3);
            float2 t0 = make_float2(x0.x + x2.x, x0.y + x2.y);
            float2 t1 = make_float2(x0.x - x2.x, x0.y - x2.y);
            float2 t2 = make_float2(x1.x + x3.x, x1.y + x3.y);
            float2 t3 = make_float2(x1.x - x3.x, x1.y - x3.y);
            sm[PIDX(base)]         = make_float2(t0.x + t2.x, t0.y + t2.y);
            sm[PIDX(base + 2 * q)] = make_float2(t0.x - t2.x, t0.y - t2.y);
            if (SIGN < 0) {
                sm[PIDX(base + q)]     = make_float2(t1.x + t3.y, t1.y - t3.x);
                sm[PIDX(base + 3 * q)] = make_float2(t1.x - t3.y, t1.y + t3.x);
            } else {
                sm[PIDX(base + q)]     = make_float2(t1.x - t3.y, t1.y + t3.x);
                sm[PIDX(base + 3 * q)] = make_float2(t1.x + t3.y, t1.y - t3.x);
            }
        }
        __syncthreads();
    }
}

// ---------------------------------------------------------------------------
// Filter spectra: two channels packed per block
// ---------------------------------------------------------------------------
__global__ __launch_bounds__(256)
void filter_fft_packed(const float* __restrict__ hfiltT,
                       const float* __restrict__ a,
                       float2* __restrict__ wfh,
                       const float2* __restrict__ twd) {
    __shared__ float2 sd[PIDX(NFFT)];
    __shared__ float2 tw[1024];
    const int tid = threadIdx.x;
    const int d0 = blockIdx.x * 2;
    const int d1 = d0 + 1;
    for (int i = tid; i < 1024; i += 256) tw[i] = twd[i];
    const float ea = expf(a[0]);
    for (int t = tid; t < LEN; t += 256) {
        const float w = expf(-(float)t * ea);
        sd[PIDX(t)] = make_float2(hfiltT[(size_t)d0 * LEN + t] * w,
                                  hfiltT[(size_t)d1 * LEN + t] * w);
    }
    for (int t = LEN + tid; t < NFFT; t += 256) sd[PIDX(t)] = make_float2(0.f, 0.f);
    fft4096_r4<-1>(sd, tw);
    for (int k = tid; k <= 2048; k += 256) {
        const int i2 = (NFFT - k) & (NFFT - 1);
        float2 X1 = sd[PIDX(k)];
        float2 X2 = sd[PIDX(i2)];
        float2 A = make_float2(0.5f * (X1.x + X2.x), 0.5f * (X1.y - X2.y));
        float2 B = make_float2(0.5f * (X1.y + X2.y), -0.5f * (X1.x - X2.x));
        wfh[(size_t)d0 * WFS + k] = A;
        wfh[(size_t)d1 * WFS + k] = B;
    }
}

// ---------------------------------------------------------------------------
// FFT convolution: two channels per block, coalesced I/O
// ---------------------------------------------------------------------------
__global__ __launch_bounds__(256)
void fftconv_packed(const float* __restrict__ lnzT,
                    const float2* __restrict__ wfh,
                    const float* __restrict__ hidT,
                    float* __restrict__ znewT,
                    const float2* __restrict__ twd) {
    __shared__ float2 sd[PIDX(NFFT)];
    __shared__ float2 tw[1024];
    const int tid = threadIdx.x;
    const int bp = blockIdx.x;
    const int b  = bp >> 9;
    const int d0 = (bp & 511) * 2;
    const int d1 = d0 + 1;
    for (int i = tid; i < 1024; i += 256) tw[i] = twd[i];
    const float* x0 = lnzT + ((size_t)b * DIM + d0) * LEN;
    const float* x1 = lnzT + ((size_t)b * DIM + d1) * LEN;
    for (int t = tid; t < LEN; t += 256)
        sd[PIDX(t)] = make_float2(x0[t], x1[t]);
    for (int t = LEN + tid; t < NFFT; t += 256) sd[PIDX(t)] = make_float2(0.f, 0.f);

    fft4096_r4<-1>(sd, tw);

    const float2* Fa = wfh + (size_t)d0 * WFS;
    const float2* Fb = wfh + (size_t)d1 * WFS;
    for (int k = tid; k <= 2048; k += 256) {
        const int i2 = (NFFT - k) & (NFFT - 1);
        float2 X1 = sd[PIDX(k)];
        float2 X2 = sd[PIDX(i2)];
        float2 A = make_float2(0.5f * (X1.x + X2.x), 0.5f * (X1.y - X2.y));
        float2 B = make_float2(0.5f * (X1.y + X2.y), -0.5f * (X1.x - X2.x));
        float2 Ya = cmul(A, Fa[k]);
        float2 Yb = cmul(B, Fb[k]);
        sd[PIDX(k)] = make_float2(Ya.x - Yb.y, Ya.y + Yb.x);
        if (k != 0 && k != 2048)
            sd[PIDX(i2)] = make_float2(Ya.x + Yb.y, Yb.x - Ya.y);
    }

    fft4096_r4<1>(sd, tw);

    const float inv = 1.0f / (float)NFFT;
    float* o0 = znewT + ((size_t)b * DIM + d0) * LEN;
    float* o1 = znewT + ((size_t)b * DIM + d1) * LEN;
    const float* h0 = hidT + (size_t)d0 * LEN;
    const float* h1 = hidT + (size_t)d1 * LEN;
    for (int t = tid; t < LEN; t += 256) {
        float2 v = sd[PIDX(t)];
        o0[t] = v.x * inv + h0[t];
        o1[t] = v.y * inv + h1[t];
    }
}

// ---------------------------------------------------------------------------
// LayerNorm kernels
// ---------------------------------------------------------------------------
__global__ void layernorm_rows(const float* __restrict__ x,
                               const float* __restrict__ gvec,
                               const float* __restrict__ bvec,
                               float* __restrict__ y) {
    const int row = blockIdx.x;
    const int tid = threadIdx.x;
    const float4 v = reinterpret_cast<const float4*>(x + (size_t)row * DIM)[tid];
    float s  = v.x + v.y + v.z + v.w;
    float s2 = v.x * v.x + v.y * v.y + v.z * v.z + v.w * v.w;
    __shared__ float rs[256], rs2[256];
    rs[tid] = s; rs2[tid] = s2;
    __syncthreads();
    for (int o = 128; o > 0; o >>= 1) {
        if (tid < o) { rs[tid] += rs[tid + o]; rs2[tid] += rs2[tid + o]; }
        __syncthreads();
    }
    const float mean = rs[0] * (1.0f / DIM);
    const float var  = rs2[0] * (1.0f / DIM) - mean * mean;
    const float rstd = rsqrtf(var + LN_EPS);
    const float4 gg = reinterpret_cast<const float4*>(gvec)[tid];
    const float4 bb = reinterpret_cast<const float4*>(bvec)[tid];
    float4 o;
    o.x = (v.x - mean) * rstd * gg.x + bb.x;
    o.y = (v.y - mean) * rstd * gg.y + bb.y;
    o.z = (v.z - mean) * rstd * gg.z + bb.z;
    o.w = (v.w - mean) * rstd * gg.w + bb.w;
    reinterpret_cast<float4*>(y + (size_t)row * DIM)[tid] = o;
}

__global__ void layernorm_rows_split(const float* __restrict__ x,
                                     const float* __restrict__ gvec,
                                     const float* __restrict__ bvec,
                                     __nv_bfloat16* __restrict__ yh,
                                     __nv_bfloat16* __restrict__ yl) {
    const int row = blockIdx.x;
    const int tid = threadIdx.x;
    const float4 v = reinterpret_cast<const float4*>(x + (size_t)row * DIM)[tid];
    float s  = v.x + v.y + v.z + v.w;
    float s2 = v.x * v.x + v.y * v.y + v.z * v.z + v.w * v.w;
    __shared__ float rs[256], rs2[256];
    rs[tid] = s; rs2[tid] = s2;
    __syncthreads();
    for (int o = 128; o > 0; o >>= 1) {
        if (tid < o) { rs[tid] += rs[tid + o]; rs2[tid] += rs2[tid + o]; }
        __syncthreads();
    }
    const float mean = rs[0] * (1.0f / DIM);
    const float var  = rs2[0] * (1.0f / DIM) - mean * mean;
    const float rstd = rsqrtf(var + LN_EPS);
    const float4 gg = reinterpret_cast<const float4*>(gvec)[tid];
    const float4 bb = reinterpret_cast<const float4*>(bvec)[tid];
    float o[4];
    o[0] = (v.x - mean) * rstd * gg.x + bb.x;
    o[1] = (v.y - mean) * rstd * gg.y + bb.y;
    o[2] = (v.z - mean) * rstd * gg.z + bb.z;
    o[3] = (v.w - mean) * rstd * gg.w + bb.w;
    __nv_bfloat16 hh[4], ll[4];
#pragma unroll
    for (int j = 0; j < 4; j++) {
        hh[j] = __float2bfloat16(o[j]);
        ll[j] = __float2bfloat16(o[j] - __bfloat162float(hh[j]));
    }
    const size_t base = (size_t)row * DIM + tid * 4;
    *reinterpret_cast<ushort4*>(yh + base) = *reinterpret_cast<ushort4*>(hh);
    *reinterpret_cast<ushort4*>(yl + base) = *reinterpret_cast<ushort4*>(ll);
}

// ---------------------------------------------------------------------------
// Launch
// ---------------------------------------------------------------------------
extern "C" void kernel_launch(void* const* d_in, const int* in_sizes, int n_in,
                              void* d_out, int out_size) {
    const float* z      = (const float*)d_in[0];
    const float* pos    = (const float*)d_in[1];
    const float* a      = (const float*)d_in[2];
    const float* hidden = (const float*)d_in[3];
    const float* ln_g   = (const float*)d_in[4];
    const float* ln_b   = (const float*)d_in[5];
    const float* wp1    = (const float*)d_in[6];
    const float* bp1    = (const float*)d_in[7];
    const float* wp2    = (const float*)d_in[8];
    const float* bp2    = (const float*)d_in[9];
    const float* w1     = (const float*)d_in[10];
    const float* b1     = (const float*)d_in[11];
    const float* w2     = (const float*)d_in[12];
    const float* b2     = (const float*)d_in[13];
    float* out = (float*)d_out;

    float *lnz, *lnzT, *hfilt, *hfiltT, *hidT, *znewT, *znew;
    float2 *wfh, *twd;
    __nv_bfloat16 *Xh, *Xl, *Hh, *Hl, *posh, *posl;
    __nv_bfloat16 *wp1t_h, *wp1t_l, *wp2t_h, *wp2t_l, *w1t_h, *w1t_l, *w2t_h, *w2t_l;
    cudaGetSymbolAddress((void**)&lnz,    g_lnz);
    cudaGetSymbolAddress((void**)&lnzT,   g_lnzT);
    cudaGetSymbolAddress((void**)&hfilt,  g_hfilt);
    cudaGetSymbolAddress((void**)&hfiltT, g_hfiltT);
    cudaGetSymbolAddress((void**)&hidT,   g_hidT);
    cudaGetSymbolAddress((void**)&wfh,    g_wfh);
    cudaGetSymbolAddress((void**)&twd,    g_twd);
    cudaGetSymbolAddress((void**)&znewT,  g_znewT);
    cudaGetSymbolAddress((void**)&znew,   g_znew);
    cudaGetSymbolAddress((void**)&Xh,     g_Xh);
    cudaGetSymbolAddress((void**)&Xl,     g_Xl);
    cudaGetSymbolAddress((void**)&Hh,     g_Hh);
    cudaGetSymbolAddress((void**)&Hl,     g_Hl);
    cudaGetSymbolAddress((void**)&posh,   g_posh);
    cudaGetSymbolAddress((void**)&posl,   g_posl);
    cudaGetSymbolAddress((void**)&wp1t_h, g_wp1t_h);
    cudaGetSymbolAddress((void**)&wp1t_l, g_wp1t_l);
    cudaGetSymbolAddress((void**)&wp2t_h, g_wp2t_h);
    cudaGetSymbolAddress((void**)&wp2t_l, g_wp2t_l);
    cudaGetSymbolAddress((void**)&w1t_h,  g_w1t_h);
    cudaGetSymbolAddress((void**)&w1t_l,  g_w1t_l);
    cudaGetSymbolAddress((void**)&w2t_h,  g_w2t_h);
    cudaGetSymbolAddress((void**)&w2t_l,  g_w2t_l);

    cudaFuncSetAttribute(gemm_mma<1, true,  false>,
                         cudaFuncAttributeMaxDynamicSharedMemorySize, GEMM_SMEM);
    cudaFuncSetAttribute(gemm_mma<0, false, false>,
                         cudaFuncAttributeMaxDynamicSharedMemorySize, GEMM_SMEM);
    cudaFuncSetAttribute(gemm_mma<0, false, true>,
                         cudaFuncAttributeMaxDynamicSharedMemorySize, GEMM_SMEM);

    // 0) prep
    transpose_split<<<dim3(DFF / 32, DIM / 32), dim3(32, 8)>>>(wp1, wp1t_h, wp1t_l, DIM, DFF);
    transpose_split<<<dim3(DIM / 32, DFF / 32), dim3(32, 8)>>>(wp2, wp2t_h, wp2t_l, DFF, DIM);
    transpose_split<<<dim3(DFF / 32, DIM / 32), dim3(32, 8)>>>(w1,  w1t_h,  w1t_l,  DIM, DFF);
    transpose_split<<<dim3(DIM / 32, DFF / 32), dim3(32, 8)>>>(w2,  w2t_h,  w2t_l,  DFF, DIM);
    split_f32<<<(LEN * DIM + 255) / 256, 256>>>(pos, posh, posl, LEN * DIM);
    init_twd<<<4, 256>>>(twd);
    transpose32f<<<dim3(DIM / 32, LEN / 32, 1), dim3(32, 8)>>>(hidden, hidT, LEN, DIM);

    // 1) filter FFN
    gemm_mma<1, true, false><<<dim3(DFF / GBN, LEN / GBM), 256, GEMM_SMEM>>>(
        posh, posl, wp1t_h, wp1t_l, bp1, nullptr, nullptr, Hh, Hl, LEN, DFF, DIM);
    gemm_mma<0, false, false><<<dim3(DIM / GBN, LEN / GBM), 256, GEMM_SMEM>>>(
        Hh, Hl, wp2t_h, wp2t_l, bp2, nullptr, hfilt, nullptr, nullptr, LEN, DIM, DFF);
    transpose32f<<<dim3(DIM / 32, LEN / 32, 1), dim3(32, 8)>>>(hfilt, hfiltT, LEN, DIM);

    // 2) filter spectra
    filter_fft_packed<<<DIM / 2, 256>>>(hfiltT, a, wfh, twd);

    // 3) LN(z) + transpose
    layernorm_rows<<<BATCH * LEN, 256>>>(z, ln_g, ln_b, lnz);
    transpose32f<<<dim3(DIM / 32, LEN / 32, BATCH), dim3(32, 8)>>>(lnz, lnzT, LEN, DIM);

    // 4) FFT convolution + hidden residual
    fftconv_packed<<<BATCH * DIM / 2, 256>>>(lnzT, wfh, hidT, znewT, twd);
    transpose32f<<<dim3(LEN / 32, DIM / 32, BATCH), dim3(32, 8)>>>(znewT, znew, DIM, LEN);

    // 5) LN(znew) -> split bf16
    layernorm_rows_split<<<BATCH * LEN, 256>>>(znew, ln_g, ln_b, Xh, Xl);

    // 6) main FFN + residual
    gemm_mma<1, true, false><<<dim3(DFF / GBN, (BATCH * LEN) / GBM), 256, GEMM_SMEM>>>(
        Xh, Xl, w1t_h, w1t_l, b1, nullptr, nullptr, Hh, Hl, BATCH * LEN, DFF, DIM);
    gemm_mma<0, false, true><<<dim3(DIM / GBN, (BATCH * LEN) / GBM), 256, GEMM_SMEM>>>(
        Hh, Hl, w2t_h, w2t_l, b2, znew, out, nullptr, nullptr, BATCH * LEN, DIM, DFF);
}

// round 8
// speedup vs baseline: 1.1948x; 1.1948x over previous
#include <cuda_runtime.h>
#include <cuda_bf16.h>
#include <math.h>
#include <cstdint>

// Problem constants
#define BATCH 8
#define LEN   2048
#define DIM   1024
#define DFF   4096
#define NFFT  4096
#define LN_EPS 1e-5f

// ---------------------------------------------------------------------------
// Static device scratch (no allocation allowed)
// ---------------------------------------------------------------------------
__device__ float  g_lnz  [BATCH * LEN * DIM];
__device__ float  g_lnzT [BATCH * DIM * LEN];
__device__ float  g_hfilt[LEN * DIM];
__device__ float  g_hfiltT[DIM * LEN];
__device__ float  g_hidT [DIM * LEN];
__device__ float2 g_wfh  [DIM * NFFT];            // full spectra, digit-reversed order
__device__ float2 g_twd  [1024];
__device__ float  g_znewT[BATCH * DIM * LEN];
__device__ float  g_znew [BATCH * LEN * DIM];
__device__ __nv_bfloat16 g_Xh[BATCH * LEN * DIM];
__device__ __nv_bfloat16 g_Xl[BATCH * LEN * DIM];
__device__ __nv_bfloat16 g_Hh[BATCH * LEN * DFF];
__device__ __nv_bfloat16 g_Hl[BATCH * LEN * DFF];
__device__ __nv_bfloat16 g_posh[LEN * DIM];
__device__ __nv_bfloat16 g_posl[LEN * DIM];
__device__ __nv_bfloat16 g_wp1t_h[DFF * DIM];
__device__ __nv_bfloat16 g_wp1t_l[DFF * DIM];
__device__ __nv_bfloat16 g_wp2t_h[DIM * DFF];
__device__ __nv_bfloat16 g_wp2t_l[DIM * DFF];
__device__ __nv_bfloat16 g_w1t_h[DFF * DIM];
__device__ __nv_bfloat16 g_w1t_l[DFF * DIM];
__device__ __nv_bfloat16 g_w2t_h[DIM * DFF];
__device__ __nv_bfloat16 g_w2t_l[DIM * DFF];

// ---------------------------------------------------------------------------
// PTX wrappers (baseline sm_80+ only)
// ---------------------------------------------------------------------------
__device__ __forceinline__ uint32_t smem_u32(const void* p) {
    uint32_t a;
    asm("{ .reg .u64 t; cvta.to.shared.u64 t, %1; cvt.u32.u64 %0, t; }"
        : "=r"(a) : "l"(p));
    return a;
}
__device__ __forceinline__ void cpasync16(uint32_t s, const void* g) {
    asm volatile("cp.async.cg.shared.global [%0], [%1], 16;"
                 :: "r"(s), "l"(g) : "memory");
}
__device__ __forceinline__ void cp_commit() {
    asm volatile("cp.async.commit_group;" ::: "memory");
}
template <int N>
__device__ __forceinline__ void cp_wait() {
    asm volatile("cp.async.wait_group %0;" :: "n"(N) : "memory");
}
__device__ __forceinline__ void ldm_x4(uint32_t& r0, uint32_t& r1,
                                       uint32_t& r2, uint32_t& r3, uint32_t a) {
    asm volatile("ldmatrix.sync.aligned.m8n8.x4.shared.b16 {%0,%1,%2,%3}, [%4];"
                 : "=r"(r0), "=r"(r1), "=r"(r2), "=r"(r3) : "r"(a));
}
__device__ __forceinline__ void ldm_x2(uint32_t& r0, uint32_t& r1, uint32_t a) {
    asm volatile("ldmatrix.sync.aligned.m8n8.x2.shared.b16 {%0,%1}, [%2];"
                 : "=r"(r0), "=r"(r1) : "r"(a));
}
__device__ __forceinline__ void mma_bf16(float4& d, const uint32_t* a,
                                         uint32_t b0, uint32_t b1) {
    asm volatile(
        "mma.sync.aligned.m16n8k16.row.col.f32.bf16.bf16.f32 "
        "{%0,%1,%2,%3}, {%4,%5,%6,%7}, {%8,%9}, {%0,%1,%2,%3};"
        : "+f"(d.x), "+f"(d.y), "+f"(d.z), "+f"(d.w)
        : "r"(a[0]), "r"(a[1]), "r"(a[2]), "r"(a[3]), "r"(b0), "r"(b1));
}

// ---------------------------------------------------------------------------
// HMMA GEMM — EXACT R4 configuration (3212us): block 128x128, BK=32,
// 8 warps (4m x 2n), warp tile 32x64, 2-stage cp.async, ldm_x2 for B.
// ---------------------------------------------------------------------------
#define GBM 128
#define GBN 128
#define GBK 32
#define TPAD 40
#define TILE_B (128 * TPAD * 2)
#define STAGE_B (4 * TILE_B)
#define GEMM_SMEM (2 * STAGE_B)

template <int ACT, bool SPLIT_OUT, bool HAS_ADD>
__global__ __launch_bounds__(256)
void gemm_mma(const __nv_bfloat16* __restrict__ Ah, const __nv_bfloat16* __restrict__ Al,
              const __nv_bfloat16* __restrict__ Bh, const __nv_bfloat16* __restrict__ Bl,
              const float* __restrict__ bias, const float* __restrict__ add,
              float* __restrict__ Cf, __nv_bfloat16* __restrict__ Ch,
              __nv_bfloat16* __restrict__ Cl, int M, int N, int K) {
    extern __shared__ char smem[];
    const uint32_t sbase = smem_u32(smem);
    const int tid  = threadIdx.x;
    const int lane = tid & 31;
    const int wid  = tid >> 5;
    const int wm   = wid & 3;
    const int wn   = wid >> 2;
    const int bm = blockIdx.y * GBM;
    const int bn = blockIdx.x * GBN;

    const int r0 = tid >> 2;
    const int c0 = tid & 3;
    const uint32_t so0 = (uint32_t)(r0 * 80 + c0 * 16);
    const uint32_t so1 = (uint32_t)((r0 + 64) * 80 + c0 * 16);

    auto issue_loads = [&](int stage, int k0) {
        const uint32_t sb = sbase + stage * STAGE_B;
        const size_t ga0 = (size_t)(bm + r0) * K + k0 + c0 * 8;
        const size_t ga1 = (size_t)(bm + r0 + 64) * K + k0 + c0 * 8;
        const size_t gb0 = (size_t)(bn + r0) * K + k0 + c0 * 8;
        const size_t gb1 = (size_t)(bn + r0 + 64) * K + k0 + c0 * 8;
        cpasync16(sb + so0,              Ah + ga0);
        cpasync16(sb + so1,              Ah + ga1);
        cpasync16(sb + TILE_B + so0,     Al + ga0);
        cpasync16(sb + TILE_B + so1,     Al + ga1);
        cpasync16(sb + 2 * TILE_B + so0, Bh + gb0);
        cpasync16(sb + 2 * TILE_B + so1, Bh + gb1);
        cpasync16(sb + 3 * TILE_B + so0, Bl + gb0);
        cpasync16(sb + 3 * TILE_B + so1, Bl + gb1);
        cp_commit();
    };

    float4 acc[2][8];
#pragma unroll
    for (int i = 0; i < 2; i++)
#pragma unroll
        for (int j = 0; j < 8; j++) acc[i][j] = make_float4(0.f, 0.f, 0.f, 0.f);

    const int a_row = (lane & 7) + ((lane >> 3) & 1) * 8;
    const int a_kc  = ((lane >> 4) & 1) * 8;
    const int b_row = lane & 7;
    const int b_kc  = ((lane >> 3) & 1) * 8;

    const int NT = K / GBK;
    issue_loads(0, 0);

    for (int kt = 0; kt < NT; kt++) {
        if (kt + 1 < NT) issue_loads((kt + 1) & 1, (kt + 1) * GBK);
        if (kt + 1 < NT) cp_wait<1>(); else cp_wait<0>();
        __syncthreads();

        const uint32_t st = sbase + (kt & 1) * STAGE_B;
        const uint32_t As_h = st;
        const uint32_t As_l = st + TILE_B;
        const uint32_t Bs_h = st + 2 * TILE_B;
        const uint32_t Bs_l = st + 3 * TILE_B;

#pragma unroll
        for (int k16 = 0; k16 < 2; k16++) {
            uint32_t ah[2][4], al[2][4];
#pragma unroll
            for (int i = 0; i < 2; i++) {
                const uint32_t ao =
                    (uint32_t)((wm * 32 + i * 16 + a_row) * 80 +
                               (k16 * 16 + a_kc) * 2);
                ldm_x4(ah[i][0], ah[i][1], ah[i][2], ah[i][3], As_h + ao);
                ldm_x4(al[i][0], al[i][1], al[i][2], al[i][3], As_l + ao);
            }
#pragma unroll
            for (int j = 0; j < 8; j++) {
                const uint32_t bo =
                    (uint32_t)((wn * 64 + j * 8 + b_row) * 80 +
                               (k16 * 16 + b_kc) * 2);
                uint32_t bh0, bh1, bl0, bl1;
                ldm_x2(bh0, bh1, Bs_h + bo);
                ldm_x2(bl0, bl1, Bs_l + bo);
#pragma unroll
                for (int i = 0; i < 2; i++) {
                    mma_bf16(acc[i][j], ah[i], bh0, bh1);
                    mma_bf16(acc[i][j], ah[i], bl0, bl1);
                    mma_bf16(acc[i][j], al[i], bh0, bh1);
                }
            }
        }
        __syncthreads();
    }

    const int qr = lane >> 2;
    const int qc = (lane & 3) * 2;
#pragma unroll
    for (int i = 0; i < 2; i++) {
#pragma unroll
        for (int j = 0; j < 8; j++) {
            const int gr0 = bm + wm * 32 + i * 16 + qr;
            const int gc  = bn + wn * 64 + j * 8 + qc;
            const float b0 = bias[gc];
            const float b1 = bias[gc + 1];
            float v00 = acc[i][j].x + b0, v01 = acc[i][j].y + b1;
            float v10 = acc[i][j].z + b0, v11 = acc[i][j].w + b1;
            if (ACT == 1) {
                v00 = v00 / (1.0f + expf(-v00));
                v01 = v01 / (1.0f + expf(-v01));
                v10 = v10 / (1.0f + expf(-v10));
                v11 = v11 / (1.0f + expf(-v11));
            }
            if (HAS_ADD) {
                v00 += add[(size_t)gr0 * N + gc];
                v01 += add[(size_t)gr0 * N + gc + 1];
                v10 += add[(size_t)(gr0 + 8) * N + gc];
                v11 += add[(size_t)(gr0 + 8) * N + gc + 1];
            }
            if (SPLIT_OUT) {
                __nv_bfloat16 h00 = __float2bfloat16(v00);
                __nv_bfloat16 h01 = __float2bfloat16(v01);
                __nv_bfloat16 h10 = __float2bfloat16(v10);
                __nv_bfloat16 h11 = __float2bfloat16(v11);
                *reinterpret_cast<__nv_bfloat162*>(Ch + (size_t)gr0 * N + gc) =
                    __nv_bfloat162(h00, h01);
                *reinterpret_cast<__nv_bfloat162*>(Ch + (size_t)(gr0 + 8) * N + gc) =
                    __nv_bfloat162(h10, h11);
                *reinterpret_cast<__nv_bfloat162*>(Cl + (size_t)gr0 * N + gc) =
                    __nv_bfloat162(__float2bfloat16(v00 - __bfloat162float(h00)),
                                   __float2bfloat16(v01 - __bfloat162float(h01)));
                *reinterpret_cast<__nv_bfloat162*>(Cl + (size_t)(gr0 + 8) * N + gc) =
                    __nv_bfloat162(__float2bfloat16(v10 - __bfloat162float(h10)),
                                   __float2bfloat16(v11 - __bfloat162float(h11)));
            } else {
                *reinterpret_cast<float2*>(Cf + (size_t)gr0 * N + gc) =
                    make_float2(v00, v01);
                *reinterpret_cast<float2*>(Cf + (size_t)(gr0 + 8) * N + gc) =
                    make_float2(v10, v11);
            }
        }
    }
}

// ---------------------------------------------------------------------------
// Prep kernels
// ---------------------------------------------------------------------------
__global__ void transpose_split(const float* __restrict__ W,
                                __nv_bfloat16* __restrict__ Th,
                                __nv_bfloat16* __restrict__ Tl, int K, int N) {
    __shared__ float t[32][33];
    const int n0 = blockIdx.x * 32, k0 = blockIdx.y * 32;
    const int tx = threadIdx.x, ty = threadIdx.y;
#pragma unroll
    for (int dy = 0; dy < 32; dy += 8)
        t[ty + dy][tx] = W[(size_t)(k0 + ty + dy) * N + n0 + tx];
    __syncthreads();
#pragma unroll
    for (int dy = 0; dy < 32; dy += 8) {
        const int n = n0 + ty + dy, k = k0 + tx;
        float v = t[tx][ty + dy];
        __nv_bfloat16 h = __float2bfloat16(v);
        Th[(size_t)n * K + k] = h;
        Tl[(size_t)n * K + k] = __float2bfloat16(v - __bfloat162float(h));
    }
}

__global__ void split_f32(const float* __restrict__ x, __nv_bfloat16* __restrict__ h,
                          __nv_bfloat16* __restrict__ l, int n) {
    int i = blockIdx.x * 256 + threadIdx.x;
    if (i < n) {
        float v = x[i];
        __nv_bfloat16 hh = __float2bfloat16(v);
        h[i] = hh;
        l[i] = __float2bfloat16(v - __bfloat162float(hh));
    }
}

__global__ void transpose32f(const float* __restrict__ in, float* __restrict__ out,
                             int R, int C) {
    __shared__ float t[32][33];
    const size_t boff = (size_t)blockIdx.z * R * C;
    const float* ip = in + boff;
    float* op = out + boff;
    const int r0 = blockIdx.y * 32, c0 = blockIdx.x * 32;
    const int tx = threadIdx.x, ty = threadIdx.y;
#pragma unroll
    for (int dy = 0; dy < 32; dy += 8)
        t[ty + dy][tx] = ip[(size_t)(r0 + ty + dy) * C + c0 + tx];
    __syncthreads();
#pragma unroll
    for (int dy = 0; dy < 32; dy += 8)
        op[(size_t)(c0 + ty + dy) * R + r0 + tx] = t[tx][ty + dy];
}

__global__ void init_twd(float2* __restrict__ twd) {
    int k = blockIdx.x * 256 + threadIdx.x;
    if (k < 1024) {
        double s, c;
        sincos(-6.283185307179586476925286766559 * (double)k / 4096.0, &s, &c);
        twd[k] = make_float2((float)c, (float)s);
    }
}

// ---------------------------------------------------------------------------
// Radix-4 FFT, 4096 points, 256 threads. DIF forward (natural -> digit-rev,
// zero-padded input [0,2048) only) and DIT inverse (digit-rev -> natural).
// ---------------------------------------------------------------------------
#define PIDX(i) ((i) + ((i) >> 4))

__device__ __forceinline__ float2 cmul(float2 a, float2 b) {
    return make_float2(a.x * b.x - a.y * b.y, a.x * b.y + a.y * b.x);
}
__device__ __forceinline__ int rev4(int p) {
    int b = __brev(p) >> 20;
    return ((b & 0x555) << 1) | ((b >> 1) & 0x555);
}

// Forward DIF. Input: natural order, positions [0,2048) valid, upper half
// implicitly zero (never read). Output: digit-reversed spectrum in sm[0..4096).
__device__ void fft4096_dif_pad(float2* sm, const float2* tw) {
    const int tid = threadIdx.x;
    __syncthreads();
    // stage len=4096 specialized: x2 = x3 = 0
#pragma unroll
    for (int u = 0; u < 4; u++) {
        const int j = tid + u * 256;                 // 0..1023
        float2 x0 = sm[PIDX(j)];
        float2 x1 = sm[PIDX(j + 1024)];
        float2 w1 = tw[j];
        float2 w2 = cmul(w1, w1);
        float2 w3 = cmul(w2, w1);
        float2 y0 = make_float2(x0.x + x1.x, x0.y + x1.y);
        float2 y1 = make_float2(x0.x + x1.y, x0.y - x1.x);   // x0 - i x1
        float2 y2 = make_float2(x0.x - x1.x, x0.y - x1.y);
        float2 y3 = make_float2(x0.x - x1.y, x0.y + x1.x);   // x0 + i x1
        sm[PIDX(j)]        = y0;
        sm[PIDX(j + 1024)] = cmul(y1, w1);
        sm[PIDX(j + 2048)] = cmul(y2, w2);
        sm[PIDX(j + 3072)] = cmul(y3, w3);
    }
    __syncthreads();
#pragma unroll
    for (int len = 1024; len >= 4; len >>= 2) {
        const int q = len >> 2;
        const int S = NFFT / len;
#pragma unroll
        for (int u = 0; u < 4; u++) {
            const int bf = tid + u * 256;
            const int g  = bf / q;
            const int j  = bf - g * q;
            const int base = g * len + j;
            float2 x0 = sm[PIDX(base)];
            float2 x1 = sm[PIDX(base + q)];
            float2 x2 = sm[PIDX(base + 2 * q)];
            float2 x3 = sm[PIDX(base + 3 * q)];
            float2 t0 = make_float2(x0.x + x2.x, x0.y + x2.y);
            float2 t1 = make_float2(x0.x - x2.x, x0.y - x2.y);
            float2 t2 = make_float2(x1.x + x3.x, x1.y + x3.y);
            float2 t3 = make_float2(x1.x - x3.x, x1.y - x3.y);
            float2 y0 = make_float2(t0.x + t2.x, t0.y + t2.y);
            float2 y2 = make_float2(t0.x - t2.x, t0.y - t2.y);
            float2 y1 = make_float2(t1.x + t3.y, t1.y - t3.x); // t1 - i t3
            float2 y3 = make_float2(t1.x - t3.y, t1.y + t3.x); // t1 + i t3
            float2 w1 = tw[j * S];
            float2 w2 = cmul(w1, w1);
            float2 w3 = cmul(w2, w1);
            sm[PIDX(base)]         = y0;
            sm[PIDX(base + q)]     = cmul(y1, w1);
            sm[PIDX(base + 2 * q)] = cmul(y2, w2);
            sm[PIDX(base + 3 * q)] = cmul(y3, w3);
        }
        __syncthreads();
    }
}

// Inverse DIT (unscaled). Input: digit-reversed spectrum. Output: natural.
__device__ void fft4096_dit_inv(float2* sm, const float2* tw) {
    const int tid = threadIdx.x;
    __syncthreads();
#pragma unroll
    for (int st = 0; st < 6; st++) {
        const int len = 4 << (2 * st);
        const int q   = len >> 2;
        const int S   = NFFT / len;
#pragma unroll
        for (int u = 0; u < 4; u++) {
            const int bf = tid + u * 256;
            const int g  = bf / q;
            const int j  = bf - g * q;
            const int base = g * len + j;
            float2 x0 = sm[PIDX(base)];
            float2 x1 = sm[PIDX(base + q)];
            float2 x2 = sm[PIDX(base + 2 * q)];
            float2 x3 = sm[PIDX(base + 3 * q)];
            float2 w1 = tw[j * S];
            w1.y = -w1.y;                                   // conj (inverse)
            float2 w2 = cmul(w1, w1);
            float2 w3 = cmul(w1, w2);
            x1 = cmul(x1, w1);
            x2 = cmul(x2, w2);
            x3 = cmul(x3, w3);
            float2 t0 = make_float2(x0.x + x2.x, x0.y + x2.y);
            float2 t1 = make_float2(x0.x - x2.x, x0.y - x2.y);
            float2 t2 = make_float2(x1.x + x3.x, x1.y + x3.y);
            float2 t3 = make_float2(x1.x - x3.x, x1.y - x3.y);
            sm[PIDX(base)]         = make_float2(t0.x + t2.x, t0.y + t2.y);
            sm[PIDX(base + 2 * q)] = make_float2(t0.x - t2.x, t0.y - t2.y);
            sm[PIDX(base + q)]     = make_float2(t1.x - t3.y, t1.y + t3.x);
            sm[PIDX(base + 3 * q)] = make_float2(t1.x + t3.y, t1.y - t3.x);
        }
        __syncthreads();
    }
}

// ---------------------------------------------------------------------------
// Filter spectra: 2 channels per block (Hermitian split), output FULL
// spectra in digit-reversed order for pointwise use in fftconv.
// ---------------------------------------------------------------------------
__global__ __launch_bounds__(256)
void filter_fft_packed(const float* __restrict__ hfiltT,
                       const float* __restrict__ a,
                       float2* __restrict__ wfh,
                       const float2* __restrict__ twd) {
    __shared__ float2 sd[PIDX(NFFT)];
    __shared__ float2 tw[1024];
    const int tid = threadIdx.x;
    const int d0 = blockIdx.x * 2;
    const int d1 = d0 + 1;
    for (int i = tid; i < 1024; i += 256) tw[i] = twd[i];
    const float ea = expf(a[0]);
    for (int t = tid; t < LEN; t += 256) {
        const float w = expf(-(float)t * ea);
        sd[PIDX(t)] = make_float2(hfiltT[(size_t)d0 * LEN + t] * w,
                                  hfiltT[(size_t)d1 * LEN + t] * w);
    }
    fft4096_dif_pad(sd, tw);
    // sd[p] = X[rev4(p)]. Emit Fa, Fb full spectra at digit-reversed position p.
    for (int p = tid; p < NFFT; p += 256) {
        const int k  = rev4(p);
        const int k2 = (NFFT - k) & (NFFT - 1);
        const int p2 = rev4(k2);
        float2 X1 = sd[PIDX(p)];
        float2 X2 = sd[PIDX(p2)];
        wfh[(size_t)d0 * NFFT + p] =
            make_float2(0.5f * (X1.x + X2.x), 0.5f * (X1.y - X2.y));
        wfh[(size_t)d1 * NFFT + p] =
            make_float2(0.5f * (X1.y + X2.y), -0.5f * (X1.x - X2.x));
    }
}

// ---------------------------------------------------------------------------
// FFT convolution: two BATCHES packed per block (real filter => pointwise
// multiply valid in digit-reversed order; real/imag parts stay separated).
// ---------------------------------------------------------------------------
__global__ __launch_bounds__(256)
void fftconv_packed(const float* __restrict__ lnzT,
                    const float2* __restrict__ wfh,
                    const float* __restrict__ hidT,
                    float* __restrict__ znewT,
                    const float2* __restrict__ twd) {
    __shared__ float2 sd[PIDX(NFFT)];
    __shared__ float2 tw[1024];
    const int tid = threadIdx.x;
    const int d  = blockIdx.x & (DIM - 1);
    const int bp = blockIdx.x >> 10;          // batch pair 0..3
    const int b0 = bp * 2;
    const int b1 = b0 + 1;
    for (int i = tid; i < 1024; i += 256) tw[i] = twd[i];
    const float* x0 = lnzT + ((size_t)b0 * DIM + d) * LEN;
    const float* x1 = lnzT + ((size_t)b1 * DIM + d) * LEN;
    for (int t = tid; t < LEN; t += 256)
        sd[PIDX(t)] = make_float2(x0[t], x1[t]);

    fft4096_dif_pad(sd, tw);

    const float2* F = wfh + (size_t)d * NFFT;
    for (int p = tid; p < NFFT; p += 256)
        sd[PIDX(p)] = cmul(sd[PIDX(p)], F[p]);

    fft4096_dit_inv(sd, tw);

    const float inv = 1.0f / (float)NFFT;
    float* o0 = znewT + ((size_t)b0 * DIM + d) * LEN;
    float* o1 = znewT + ((size_t)b1 * DIM + d) * LEN;
    const float* h = hidT + (size_t)d * LEN;
    for (int t = tid; t < LEN; t += 256) {
        float2 v = sd[PIDX(t)];
        const float hv = h[t];
        o0[t] = v.x * inv + hv;
        o1[t] = v.y * inv + hv;
    }
}

// ---------------------------------------------------------------------------
// LayerNorm kernels
// ---------------------------------------------------------------------------
__global__ void layernorm_rows(const float* __restrict__ x,
                               const float* __restrict__ gvec,
                               const float* __restrict__ bvec,
                               float* __restrict__ y) {
    const int row = blockIdx.x;
    const int tid = threadIdx.x;
    const float4 v = reinterpret_cast<const float4*>(x + (size_t)row * DIM)[tid];
    float s  = v.x + v.y + v.z + v.w;
    float s2 = v.x * v.x + v.y * v.y + v.z * v.z + v.w * v.w;
    __shared__ float rs[256], rs2[256];
    rs[tid] = s; rs2[tid] = s2;
    __syncthreads();
    for (int o = 128; o > 0; o >>= 1) {
        if (tid < o) { rs[tid] += rs[tid + o]; rs2[tid] += rs2[tid + o]; }
        __syncthreads();
    }
    const float mean = rs[0] * (1.0f / DIM);
    const float var  = rs2[0] * (1.0f / DIM) - mean * mean;
    const float rstd = rsqrtf(var + LN_EPS);
    const float4 gg = reinterpret_cast<const float4*>(gvec)[tid];
    const float4 bb = reinterpret_cast<const float4*>(bvec)[tid];
    float4 o;
    o.x = (v.x - mean) * rstd * gg.x + bb.x;
    o.y = (v.y - mean) * rstd * gg.y + bb.y;
    o.z = (v.z - mean) * rstd * gg.z + bb.z;
    o.w = (v.w - mean) * rstd * gg.w + bb.w;
    reinterpret_cast<float4*>(y + (size_t)row * DIM)[tid] = o;
}

__global__ void layernorm_rows_split(const float* __restrict__ x,
                                     const float* __restrict__ gvec,
                                     const float* __restrict__ bvec,
                                     __nv_bfloat16* __restrict__ yh,
                                     __nv_bfloat16* __restrict__ yl) {
    const int row = blockIdx.x;
    const int tid = threadIdx.x;
    const float4 v = reinterpret_cast<const float4*>(x + (size_t)row * DIM)[tid];
    float s  = v.x + v.y + v.z + v.w;
    float s2 = v.x * v.x + v.y * v.y + v.z * v.z + v.w * v.w;
    __shared__ float rs[256], rs2[256];
    rs[tid] = s; rs2[tid] = s2;
    __syncthreads();
    for (int o = 128; o > 0; o >>= 1) {
        if (tid < o) { rs[tid] += rs[tid + o]; rs2[tid] += rs2[tid + o]; }
        __syncthreads();
    }
    const float mean = rs[0] * (1.0f / DIM);
    const float var  = rs2[0] * (1.0f / DIM) - mean * mean;
    const float rstd = rsqrtf(var + LN_EPS);
    const float4 gg = reinterpret_cast<const float4*>(gvec)[tid];
    const float4 bb = reinterpret_cast<const float4*>(bvec)[tid];
    float o[4];
    o[0] = (v.x - mean) * rstd * gg.x + bb.x;
    o[1] = (v.y - mean) * rstd * gg.y + bb.y;
    o[2] = (v.z - mean) * rstd * gg.z + bb.z;
    o[3] = (v.w - mean) * rstd * gg.w + bb.w;
    __nv_bfloat16 hh[4], ll[4];
#pragma unroll
    for (int j = 0; j < 4; j++) {
        hh[j] = __float2bfloat16(o[j]);
        ll[j] = __float2bfloat16(o[j] - __bfloat162float(hh[j]));
    }
    const size_t base = (size_t)row * DIM + tid * 4;
    *reinterpret_cast<ushort4*>(yh + base) = *reinterpret_cast<ushort4*>(hh);
    *reinterpret_cast<ushort4*>(yl + base) = *reinterpret_cast<ushort4*>(ll);
}

// ---------------------------------------------------------------------------
// Launch
// ---------------------------------------------------------------------------
extern "C" void kernel_launch(void* const* d_in, const int* in_sizes, int n_in,
                              void* d_out, int out_size) {
    const float* z      = (const float*)d_in[0];
    const float* pos    = (const float*)d_in[1];
    const float* a      = (const float*)d_in[2];
    const float* hidden = (const float*)d_in[3];
    const float* ln_g   = (const float*)d_in[4];
    const float* ln_b   = (const float*)d_in[5];
    const float* wp1    = (const float*)d_in[6];
    const float* bp1    = (const float*)d_in[7];
    const float* wp2    = (const float*)d_in[8];
    const float* bp2    = (const float*)d_in[9];
    const float* w1     = (const float*)d_in[10];
    const float* b1     = (const float*)d_in[11];
    const float* w2     = (const float*)d_in[12];
    const float* b2     = (const float*)d_in[13];
    float* out = (float*)d_out;

    float *lnz, *lnzT, *hfilt, *hfiltT, *hidT, *znewT, *znew;
    float2 *wfh, *twd;
    __nv_bfloat16 *Xh, *Xl, *Hh, *Hl, *posh, *posl;
    __nv_bfloat16 *wp1t_h, *wp1t_l, *wp2t_h, *wp2t_l, *w1t_h, *w1t_l, *w2t_h, *w2t_l;
    cudaGetSymbolAddress((void**)&lnz,    g_lnz);
    cudaGetSymbolAddress((void**)&lnzT,   g_lnzT);
    cudaGetSymbolAddress((void**)&hfilt,  g_hfilt);
    cudaGetSymbolAddress((void**)&hfiltT, g_hfiltT);
    cudaGetSymbolAddress((void**)&hidT,   g_hidT);
    cudaGetSymbolAddress((void**)&wfh,    g_wfh);
    cudaGetSymbolAddress((void**)&twd,    g_twd);
    cudaGetSymbolAddress((void**)&znewT,  g_znewT);
    cudaGetSymbolAddress((void**)&znew,   g_znew);
    cudaGetSymbolAddress((void**)&Xh,     g_Xh);
    cudaGetSymbolAddress((void**)&Xl,     g_Xl);
    cudaGetSymbolAddress((void**)&Hh,     g_Hh);
    cudaGetSymbolAddress((void**)&Hl,     g_Hl);
    cudaGetSymbolAddress((void**)&posh,   g_posh);
    cudaGetSymbolAddress((void**)&posl,   g_posl);
    cudaGetSymbolAddress((void**)&wp1t_h, g_wp1t_h);
    cudaGetSymbolAddress((void**)&wp1t_l, g_wp1t_l);
    cudaGetSymbolAddress((void**)&wp2t_h, g_wp2t_h);
    cudaGetSymbolAddress((void**)&wp2t_l, g_wp2t_l);
    cudaGetSymbolAddress((void**)&w1t_h,  g_w1t_h);
    cudaGetSymbolAddress((void**)&w1t_l,  g_w1t_l);
    cudaGetSymbolAddress((void**)&w2t_h,  g_w2t_h);
    cudaGetSymbolAddress((void**)&w2t_l,  g_w2t_l);

    cudaFuncSetAttribute(gemm_mma<1, true,  false>,
                         cudaFuncAttributeMaxDynamicSharedMemorySize, GEMM_SMEM);
    cudaFuncSetAttribute(gemm_mma<0, false, false>,
                         cudaFuncAttributeMaxDynamicSharedMemorySize, GEMM_SMEM);
    cudaFuncSetAttribute(gemm_mma<0, false, true>,
                         cudaFuncAttributeMaxDynamicSharedMemorySize, GEMM_SMEM);

    // 0) prep
    transpose_split<<<dim3(DFF / 32, DIM / 32), dim3(32, 8)>>>(wp1, wp1t_h, wp1t_l, DIM, DFF);
    transpose_split<<<dim3(DIM / 32, DFF / 32), dim3(32, 8)>>>(wp2, wp2t_h, wp2t_l, DFF, DIM);
    transpose_split<<<dim3(DFF / 32, DIM / 32), dim3(32, 8)>>>(w1,  w1t_h,  w1t_l,  DIM, DFF);
    transpose_split<<<dim3(DIM / 32, DFF / 32), dim3(32, 8)>>>(w2,  w2t_h,  w2t_l,  DFF, DIM);
    split_f32<<<(LEN * DIM + 255) / 256, 256>>>(pos, posh, posl, LEN * DIM);
    init_twd<<<4, 256>>>(twd);
    transpose32f<<<dim3(DIM / 32, LEN / 32, 1), dim3(32, 8)>>>(hidden, hidT, LEN, DIM);

    // 1) filter FFN
    gemm_mma<1, true, false><<<dim3(DFF / GBN, LEN / GBM), 256, GEMM_SMEM>>>(
        posh, posl, wp1t_h, wp1t_l, bp1, nullptr, nullptr, Hh, Hl, LEN, DFF, DIM);
    gemm_mma<0, false, false><<<dim3(DIM / GBN, LEN / GBM), 256, GEMM_SMEM>>>(
        Hh, Hl, wp2t_h, wp2t_l, bp2, nullptr, hfilt, nullptr, nullptr, LEN, DIM, DFF);
    transpose32f<<<dim3(DIM / 32, LEN / 32, 1), dim3(32, 8)>>>(hfilt, hfiltT, LEN, DIM);

    // 2) filter spectra (full, digit-reversed order)
    filter_fft_packed<<<DIM / 2, 256>>>(hfiltT, a, wfh, twd);

    // 3) LN(z) + transpose
    layernorm_rows<<<BATCH * LEN, 256>>>(z, ln_g, ln_b, lnz);
    transpose32f<<<dim3(DIM / 32, LEN / 32, BATCH), dim3(32, 8)>>>(lnz, lnzT, LEN, DIM);

    // 4) FFT convolution (batch pairs, no permutation passes) + hidden residual
    fftconv_packed<<<(BATCH / 2) * DIM, 256>>>(lnzT, wfh, hidT, znewT, twd);
    transpose32f<<<dim3(LEN / 32, DIM / 32, BATCH), dim3(32, 8)>>>(znewT, znew, DIM, LEN);

    // 5) LN(znew) -> split bf16
    layernorm_rows_split<<<BATCH * LEN, 256>>>(znew, ln_g, ln_b, Xh, Xl);

    // 6) main FFN + residual
    gemm_mma<1, true, false><<<dim3(DFF / GBN, (BATCH * LEN) / GBM), 256, GEMM_SMEM>>>(
        Xh, Xl, w1t_h, w1t_l, b1, nullptr, nullptr, Hh, Hl, BATCH * LEN, DFF, DIM);
    gemm_mma<0, false, true><<<dim3(DIM / GBN, (BATCH * LEN) / GBM), 256, GEMM_SMEM>>>(
        Hh, Hl, w2t_h, w2t_l, b2, znew, out, nullptr, nullptr, BATCH * LEN, DIM, DFF);
}

// round 9
// speedup vs baseline: 1.2594x; 1.0541x over previous
#include <cuda_runtime.h>
#include <cuda_bf16.h>
#include <math.h>
#include <cstdint>

// Problem constants
#define BATCH 8
#define LEN   2048
#define DIM   1024
#define DFF   4096
#define NFFT  4096
#define LN_EPS 1e-5f

// ---------------------------------------------------------------------------
// Static device scratch (no allocation allowed)
// ---------------------------------------------------------------------------
__device__ float  g_lnz  [BATCH * LEN * DIM];
__device__ float  g_lnzT [BATCH * DIM * LEN];
__device__ float  g_hfilt[LEN * DIM];
__device__ float  g_hfiltT[DIM * LEN];
__device__ float  g_hidT [DIM * LEN];
__device__ float2 g_wfh  [DIM * NFFT];            // full spectra, digit-reversed order
__device__ float2 g_twd  [1024];
__device__ float  g_znewT[BATCH * DIM * LEN];
__device__ float  g_znew [BATCH * LEN * DIM];
__device__ __nv_bfloat16 g_Xh[BATCH * LEN * DIM];
__device__ __nv_bfloat16 g_Xl[BATCH * LEN * DIM];
__device__ __nv_bfloat16 g_Hh[BATCH * LEN * DFF];
__device__ __nv_bfloat16 g_Hl[BATCH * LEN * DFF];
__device__ __nv_bfloat16 g_posh[LEN * DIM];
__device__ __nv_bfloat16 g_posl[LEN * DIM];
__device__ __nv_bfloat16 g_wp1t_h[DFF * DIM];
__device__ __nv_bfloat16 g_wp1t_l[DFF * DIM];
__device__ __nv_bfloat16 g_wp2t_h[DIM * DFF];
__device__ __nv_bfloat16 g_wp2t_l[DIM * DFF];
__device__ __nv_bfloat16 g_w1t_h[DFF * DIM];
__device__ __nv_bfloat16 g_w1t_l[DFF * DIM];
__device__ __nv_bfloat16 g_w2t_h[DIM * DFF];
__device__ __nv_bfloat16 g_w2t_l[DIM * DFF];

// ---------------------------------------------------------------------------
// PTX wrappers (baseline sm_80+ only)
// ---------------------------------------------------------------------------
__device__ __forceinline__ uint32_t smem_u32(const void* p) {
    uint32_t a;
    asm("{ .reg .u64 t; cvta.to.shared.u64 t, %1; cvt.u32.u64 %0, t; }"
        : "=r"(a) : "l"(p));
    return a;
}
__device__ __forceinline__ void cpasync16(uint32_t s, const void* g) {
    asm volatile("cp.async.cg.shared.global [%0], [%1], 16;"
                 :: "r"(s), "l"(g) : "memory");
}
__device__ __forceinline__ void cp_commit() {
    asm volatile("cp.async.commit_group;" ::: "memory");
}
template <int N>
__device__ __forceinline__ void cp_wait() {
    asm volatile("cp.async.wait_group %0;" :: "n"(N) : "memory");
}
__device__ __forceinline__ void ldm_x4(uint32_t& r0, uint32_t& r1,
                                       uint32_t& r2, uint32_t& r3, uint32_t a) {
    asm volatile("ldmatrix.sync.aligned.m8n8.x4.shared.b16 {%0,%1,%2,%3}, [%4];"
                 : "=r"(r0), "=r"(r1), "=r"(r2), "=r"(r3) : "r"(a));
}
__device__ __forceinline__ void ldm_x2(uint32_t& r0, uint32_t& r1, uint32_t a) {
    asm volatile("ldmatrix.sync.aligned.m8n8.x2.shared.b16 {%0,%1}, [%2];"
                 : "=r"(r0), "=r"(r1) : "r"(a));
}
__device__ __forceinline__ void mma_bf16(float4& d, const uint32_t* a,
                                         uint32_t b0, uint32_t b1) {
    asm volatile(
        "mma.sync.aligned.m16n8k16.row.col.f32.bf16.bf16.f32 "
        "{%0,%1,%2,%3}, {%4,%5,%6,%7}, {%8,%9}, {%0,%1,%2,%3};"
        : "+f"(d.x), "+f"(d.y), "+f"(d.z), "+f"(d.w)
        : "r"(a[0]), "r"(a[1]), "r"(a[2]), "r"(a[3]), "r"(b0), "r"(b1));
}

// ---------------------------------------------------------------------------
// HMMA GEMM: block 128x128, BK=32, **4 warps** (2m x 2n), warp tile 64x64,
// 2-stage cp.async, 80B-padded rows, ldm_x2 for B (R4-validated pattern).
// Halves per-k-tile smem fragment reads vs the 8-warp 32x64 layout.
// ---------------------------------------------------------------------------
#define GBM 128
#define GBN 128
#define GBK 32
#define TPAD 40
#define TILE_B (128 * TPAD * 2)      // 10240 bytes per matrix tile
#define STAGE_B (4 * TILE_B)         // Ah, Al, Bh, Bl
#define GEMM_SMEM (2 * STAGE_B)      // 81920 bytes
#define GTHREADS 128

template <int ACT, bool SPLIT_OUT, bool HAS_ADD>
__global__ __launch_bounds__(GTHREADS)
void gemm_mma(const __nv_bfloat16* __restrict__ Ah, const __nv_bfloat16* __restrict__ Al,
              const __nv_bfloat16* __restrict__ Bh, const __nv_bfloat16* __restrict__ Bl,
              const float* __restrict__ bias, const float* __restrict__ add,
              float* __restrict__ Cf, __nv_bfloat16* __restrict__ Ch,
              __nv_bfloat16* __restrict__ Cl, int M, int N, int K) {
    extern __shared__ char smem[];
    const uint32_t sbase = smem_u32(smem);
    const int tid  = threadIdx.x;
    const int lane = tid & 31;
    const int wid  = tid >> 5;       // 0..3
    const int wm   = wid & 1;        // 2 warp rows (64 M each)
    const int wn   = wid >> 1;       // 2 warp cols (64 N each)
    const int bm = blockIdx.y * GBM;
    const int bn = blockIdx.x * GBN;

    auto issue_loads = [&](int stage, int k0) {
        const uint32_t sb = sbase + stage * STAGE_B;
#pragma unroll
        for (int p = 0; p < 4; p++) {
            const int idx = p * GTHREADS + tid;      // 0..511
            const int row = idx >> 2;                // 0..127
            const int c0  = idx & 3;                 // 16B chunk
            const uint32_t so = (uint32_t)(row * 80 + c0 * 16);
            const size_t kk = (size_t)k0 + c0 * 8;
            cpasync16(sb + so,              Ah + (size_t)(bm + row) * K + kk);
            cpasync16(sb + TILE_B + so,     Al + (size_t)(bm + row) * K + kk);
            cpasync16(sb + 2 * TILE_B + so, Bh + (size_t)(bn + row) * K + kk);
            cpasync16(sb + 3 * TILE_B + so, Bl + (size_t)(bn + row) * K + kk);
        }
        cp_commit();
    };

    float4 acc[4][8];
#pragma unroll
    for (int i = 0; i < 4; i++)
#pragma unroll
        for (int j = 0; j < 8; j++) acc[i][j] = make_float4(0.f, 0.f, 0.f, 0.f);

    const int a_row = (lane & 7) + ((lane >> 3) & 1) * 8;
    const int a_kc  = ((lane >> 4) & 1) * 8;
    const int b_row = lane & 7;
    const int b_kc  = ((lane >> 3) & 1) * 8;

    const int NT = K / GBK;
    issue_loads(0, 0);

    for (int kt = 0; kt < NT; kt++) {
        if (kt + 1 < NT) issue_loads((kt + 1) & 1, (kt + 1) * GBK);
        if (kt + 1 < NT) cp_wait<1>(); else cp_wait<0>();
        __syncthreads();

        const uint32_t st = sbase + (kt & 1) * STAGE_B;
        const uint32_t As_h = st;
        const uint32_t As_l = st + TILE_B;
        const uint32_t Bs_h = st + 2 * TILE_B;
        const uint32_t Bs_l = st + 3 * TILE_B;

#pragma unroll
        for (int k16 = 0; k16 < 2; k16++) {
            uint32_t ah[4][4], al[4][4];
#pragma unroll
            for (int i = 0; i < 4; i++) {
                const uint32_t ao =
                    (uint32_t)((wm * 64 + i * 16 + a_row) * 80 +
                               (k16 * 16 + a_kc) * 2);
                ldm_x4(ah[i][0], ah[i][1], ah[i][2], ah[i][3], As_h + ao);
                ldm_x4(al[i][0], al[i][1], al[i][2], al[i][3], As_l + ao);
            }
#pragma unroll
            for (int j = 0; j < 8; j++) {
                const uint32_t bo =
                    (uint32_t)((wn * 64 + j * 8 + b_row) * 80 +
                               (k16 * 16 + b_kc) * 2);
                uint32_t bh0, bh1, bl0, bl1;
                ldm_x2(bh0, bh1, Bs_h + bo);
                ldm_x2(bl0, bl1, Bs_l + bo);
#pragma unroll
                for (int i = 0; i < 4; i++) {
                    mma_bf16(acc[i][j], ah[i], bh0, bh1);
                    mma_bf16(acc[i][j], ah[i], bl0, bl1);
                    mma_bf16(acc[i][j], al[i], bh0, bh1);
                }
            }
        }
        __syncthreads();
    }

    // epilogue: warp tile 64x64 at (bm + wm*64, bn + wn*64)
    const int qr = lane >> 2;
    const int qc = (lane & 3) * 2;
#pragma unroll
    for (int i = 0; i < 4; i++) {
#pragma unroll
        for (int j = 0; j < 8; j++) {
            const int gr0 = bm + wm * 64 + i * 16 + qr;
            const int gc  = bn + wn * 64 + j * 8 + qc;
            const float b0 = bias[gc];
            const float b1 = bias[gc + 1];
            float v00 = acc[i][j].x + b0, v01 = acc[i][j].y + b1;
            float v10 = acc[i][j].z + b0, v11 = acc[i][j].w + b1;
            if (ACT == 1) {
                v00 = v00 / (1.0f + expf(-v00));
                v01 = v01 / (1.0f + expf(-v01));
                v10 = v10 / (1.0f + expf(-v10));
                v11 = v11 / (1.0f + expf(-v11));
            }
            if (HAS_ADD) {
                v00 += add[(size_t)gr0 * N + gc];
                v01 += add[(size_t)gr0 * N + gc + 1];
                v10 += add[(size_t)(gr0 + 8) * N + gc];
                v11 += add[(size_t)(gr0 + 8) * N + gc + 1];
            }
            if (SPLIT_OUT) {
                __nv_bfloat16 h00 = __float2bfloat16(v00);
                __nv_bfloat16 h01 = __float2bfloat16(v01);
                __nv_bfloat16 h10 = __float2bfloat16(v10);
                __nv_bfloat16 h11 = __float2bfloat16(v11);
                *reinterpret_cast<__nv_bfloat162*>(Ch + (size_t)gr0 * N + gc) =
                    __nv_bfloat162(h00, h01);
                *reinterpret_cast<__nv_bfloat162*>(Ch + (size_t)(gr0 + 8) * N + gc) =
                    __nv_bfloat162(h10, h11);
                *reinterpret_cast<__nv_bfloat162*>(Cl + (size_t)gr0 * N + gc) =
                    __nv_bfloat162(__float2bfloat16(v00 - __bfloat162float(h00)),
                                   __float2bfloat16(v01 - __bfloat162float(h01)));
                *reinterpret_cast<__nv_bfloat162*>(Cl + (size_t)(gr0 + 8) * N + gc) =
                    __nv_bfloat162(__float2bfloat16(v10 - __bfloat162float(h10)),
                                   __float2bfloat16(v11 - __bfloat162float(h11)));
            } else {
                *reinterpret_cast<float2*>(Cf + (size_t)gr0 * N + gc) =
                    make_float2(v00, v01);
                *reinterpret_cast<float2*>(Cf + (size_t)(gr0 + 8) * N + gc) =
                    make_float2(v10, v11);
            }
        }
    }
}

// ---------------------------------------------------------------------------
// Prep kernels
// ---------------------------------------------------------------------------
__global__ void transpose_split(const float* __restrict__ W,
                                __nv_bfloat16* __restrict__ Th,
                                __nv_bfloat16* __restrict__ Tl, int K, int N) {
    __shared__ float t[32][33];
    const int n0 = blockIdx.x * 32, k0 = blockIdx.y * 32;
    const int tx = threadIdx.x, ty = threadIdx.y;
#pragma unroll
    for (int dy = 0; dy < 32; dy += 8)
        t[ty + dy][tx] = W[(size_t)(k0 + ty + dy) * N + n0 + tx];
    __syncthreads();
#pragma unroll
    for (int dy = 0; dy < 32; dy += 8) {
        const int n = n0 + ty + dy, k = k0 + tx;
        float v = t[tx][ty + dy];
        __nv_bfloat16 h = __float2bfloat16(v);
        Th[(size_t)n * K + k] = h;
        Tl[(size_t)n * K + k] = __float2bfloat16(v - __bfloat162float(h));
    }
}

__global__ void split_f32(const float* __restrict__ x, __nv_bfloat16* __restrict__ h,
                          __nv_bfloat16* __restrict__ l, int n) {
    int i = blockIdx.x * 256 + threadIdx.x;
    if (i < n) {
        float v = x[i];
        __nv_bfloat16 hh = __float2bfloat16(v);
        h[i] = hh;
        l[i] = __float2bfloat16(v - __bfloat162float(hh));
    }
}

__global__ void transpose32f(const float* __restrict__ in, float* __restrict__ out,
                             int R, int C) {
    __shared__ float t[32][33];
    const size_t boff = (size_t)blockIdx.z * R * C;
    const float* ip = in + boff;
    float* op = out + boff;
    const int r0 = blockIdx.y * 32, c0 = blockIdx.x * 32;
    const int tx = threadIdx.x, ty = threadIdx.y;
#pragma unroll
    for (int dy = 0; dy < 32; dy += 8)
        t[ty + dy][tx] = ip[(size_t)(r0 + ty + dy) * C + c0 + tx];
    __syncthreads();
#pragma unroll
    for (int dy = 0; dy < 32; dy += 8)
        op[(size_t)(c0 + ty + dy) * R + r0 + tx] = t[tx][ty + dy];
}

__global__ void init_twd(float2* __restrict__ twd) {
    int k = blockIdx.x * 256 + threadIdx.x;
    if (k < 1024) {
        double s, c;
        sincos(-6.283185307179586476925286766559 * (double)k / 4096.0, &s, &c);
        twd[k] = make_float2((float)c, (float)s);
    }
}

// ---------------------------------------------------------------------------
// Radix-4 FFT, 4096 points, 256 threads. DIF forward (natural -> digit-rev,
// zero-padded input [0,2048) only) and DIT inverse (digit-rev -> natural).
// ---------------------------------------------------------------------------
#define PIDX(i) ((i) + ((i) >> 4))

__device__ __forceinline__ float2 cmul(float2 a, float2 b) {
    return make_float2(a.x * b.x - a.y * b.y, a.x * b.y + a.y * b.x);
}
__device__ __forceinline__ int rev4(int p) {
    int b = __brev(p) >> 20;
    return ((b & 0x555) << 1) | ((b >> 1) & 0x555);
}

// Forward DIF. Input: natural order, positions [0,2048) valid, upper half
// implicitly zero (never read). Output: digit-reversed spectrum.
__device__ void fft4096_dif_pad(float2* sm, const float2* tw) {
    const int tid = threadIdx.x;
    __syncthreads();
#pragma unroll
    for (int u = 0; u < 4; u++) {
        const int j = tid + u * 256;
        float2 x0 = sm[PIDX(j)];
        float2 x1 = sm[PIDX(j + 1024)];
        float2 w1 = tw[j];
        float2 w2 = cmul(w1, w1);
        float2 w3 = cmul(w2, w1);
        float2 y0 = make_float2(x0.x + x1.x, x0.y + x1.y);
        float2 y1 = make_float2(x0.x + x1.y, x0.y - x1.x);
        float2 y2 = make_float2(x0.x - x1.x, x0.y - x1.y);
        float2 y3 = make_float2(x0.x - x1.y, x0.y + x1.x);
        sm[PIDX(j)]        = y0;
        sm[PIDX(j + 1024)] = cmul(y1, w1);
        sm[PIDX(j + 2048)] = cmul(y2, w2);
        sm[PIDX(j + 3072)] = cmul(y3, w3);
    }
    __syncthreads();
#pragma unroll
    for (int len = 1024; len >= 4; len >>= 2) {
        const int q = len >> 2;
        const int S = NFFT / len;
#pragma unroll
        for (int u = 0; u < 4; u++) {
            const int bf = tid + u * 256;
            const int g  = bf / q;
            const int j  = bf - g * q;
            const int base = g * len + j;
            float2 x0 = sm[PIDX(base)];
            float2 x1 = sm[PIDX(base + q)];
            float2 x2 = sm[PIDX(base + 2 * q)];
            float2 x3 = sm[PIDX(base + 3 * q)];
            float2 t0 = make_float2(x0.x + x2.x, x0.y + x2.y);
            float2 t1 = make_float2(x0.x - x2.x, x0.y - x2.y);
            float2 t2 = make_float2(x1.x + x3.x, x1.y + x3.y);
            float2 t3 = make_float2(x1.x - x3.x, x1.y - x3.y);
            float2 y0 = make_float2(t0.x + t2.x, t0.y + t2.y);
            float2 y2 = make_float2(t0.x - t2.x, t0.y - t2.y);
            float2 y1 = make_float2(t1.x + t3.y, t1.y - t3.x);
            float2 y3 = make_float2(t1.x - t3.y, t1.y + t3.x);
            float2 w1 = tw[j * S];
            float2 w2 = cmul(w1, w1);
            float2 w3 = cmul(w2, w1);
            sm[PIDX(base)]         = y0;
            sm[PIDX(base + q)]     = cmul(y1, w1);
            sm[PIDX(base + 2 * q)] = cmul(y2, w2);
            sm[PIDX(base + 3 * q)] = cmul(y3, w3);
        }
        __syncthreads();
    }
}

// Inverse DIT (unscaled). Input: digit-reversed spectrum. Output: natural.
__device__ void fft4096_dit_inv(float2* sm, const float2* tw) {
    const int tid = threadIdx.x;
    __syncthreads();
#pragma unroll
    for (int st = 0; st < 6; st++) {
        const int len = 4 << (2 * st);
        const int q   = len >> 2;
        const int S   = NFFT / len;
#pragma unroll
        for (int u = 0; u < 4; u++) {
            const int bf = tid + u * 256;
            const int g  = bf / q;
            const int j  = bf - g * q;
            const int base = g * len + j;
            float2 x0 = sm[PIDX(base)];
            float2 x1 = sm[PIDX(base + q)];
            float2 x2 = sm[PIDX(base + 2 * q)];
            float2 x3 = sm[PIDX(base + 3 * q)];
            float2 w1 = tw[j * S];
            w1.y = -w1.y;
            float2 w2 = cmul(w1, w1);
            float2 w3 = cmul(w1, w2);
            x1 = cmul(x1, w1);
            x2 = cmul(x2, w2);
            x3 = cmul(x3, w3);
            float2 t0 = make_float2(x0.x + x2.x, x0.y + x2.y);
            float2 t1 = make_float2(x0.x - x2.x, x0.y - x2.y);
            float2 t2 = make_float2(x1.x + x3.x, x1.y + x3.y);
            float2 t3 = make_float2(x1.x - x3.x, x1.y - x3.y);
            sm[PIDX(base)]         = make_float2(t0.x + t2.x, t0.y + t2.y);
            sm[PIDX(base + 2 * q)] = make_float2(t0.x - t2.x, t0.y - t2.y);
            sm[PIDX(base + q)]     = make_float2(t1.x - t3.y, t1.y + t3.x);
            sm[PIDX(base + 3 * q)] = make_float2(t1.x + t3.y, t1.y - t3.x);
        }
        __syncthreads();
    }
}

// ---------------------------------------------------------------------------
// Filter spectra: 2 channels per block (Hermitian split), output FULL
// spectra in digit-reversed order for pointwise use in fftconv.
// ---------------------------------------------------------------------------
__global__ __launch_bounds__(256)
void filter_fft_packed(const float* __restrict__ hfiltT,
                       const float* __restrict__ a,
                       float2* __restrict__ wfh,
                       const float2* __restrict__ twd) {
    __shared__ float2 sd[PIDX(NFFT)];
    __shared__ float2 tw[1024];
    const int tid = threadIdx.x;
    const int d0 = blockIdx.x * 2;
    const int d1 = d0 + 1;
    for (int i = tid; i < 1024; i += 256) tw[i] = twd[i];
    const float ea = expf(a[0]);
    for (int t = tid; t < LEN; t += 256) {
        const float w = expf(-(float)t * ea);
        sd[PIDX(t)] = make_float2(hfiltT[(size_t)d0 * LEN + t] * w,
                                  hfiltT[(size_t)d1 * LEN + t] * w);
    }
    fft4096_dif_pad(sd, tw);
    for (int p = tid; p < NFFT; p += 256) {
        const int k  = rev4(p);
        const int k2 = (NFFT - k) & (NFFT - 1);
        const int p2 = rev4(k2);
        float2 X1 = sd[PIDX(p)];
        float2 X2 = sd[PIDX(p2)];
        wfh[(size_t)d0 * NFFT + p] =
            make_float2(0.5f * (X1.x + X2.x), 0.5f * (X1.y - X2.y));
        wfh[(size_t)d1 * NFFT + p] =
            make_float2(0.5f * (X1.y + X2.y), -0.5f * (X1.x - X2.x));
    }
}

// ---------------------------------------------------------------------------
// FFT convolution: two BATCHES packed per block (real filter => pointwise
// multiply valid in digit-reversed order).
// ---------------------------------------------------------------------------
__global__ __launch_bounds__(256)
void fftconv_packed(const float* __restrict__ lnzT,
                    const float2* __restrict__ wfh,
                    const float* __restrict__ hidT,
                    float* __restrict__ znewT,
                    const float2* __restrict__ twd) {
    __shared__ float2 sd[PIDX(NFFT)];
    __shared__ float2 tw[1024];
    const int tid = threadIdx.x;
    const int d  = blockIdx.x & (DIM - 1);
    const int bp = blockIdx.x >> 10;
    const int b0 = bp * 2;
    const int b1 = b0 + 1;
    for (int i = tid; i < 1024; i += 256) tw[i] = twd[i];
    const float* x0 = lnzT + ((size_t)b0 * DIM + d) * LEN;
    const float* x1 = lnzT + ((size_t)b1 * DIM + d) * LEN;
    for (int t = tid; t < LEN; t += 256)
        sd[PIDX(t)] = make_float2(x0[t], x1[t]);

    fft4096_dif_pad(sd, tw);

    const float2* F = wfh + (size_t)d * NFFT;
    for (int p = tid; p < NFFT; p += 256)
        sd[PIDX(p)] = cmul(sd[PIDX(p)], F[p]);

    fft4096_dit_inv(sd, tw);

    const float inv = 1.0f / (float)NFFT;
    float* o0 = znewT + ((size_t)b0 * DIM + d) * LEN;
    float* o1 = znewT + ((size_t)b1 * DIM + d) * LEN;
    const float* h = hidT + (size_t)d * LEN;
    for (int t = tid; t < LEN; t += 256) {
        float2 v = sd[PIDX(t)];
        const float hv = h[t];
        o0[t] = v.x * inv + hv;
        o1[t] = v.y * inv + hv;
    }
}

// ---------------------------------------------------------------------------
// LayerNorm kernels
// ---------------------------------------------------------------------------
__global__ void layernorm_rows(const float* __restrict__ x,
                               const float* __restrict__ gvec,
                               const float* __restrict__ bvec,
                               float* __restrict__ y) {
    const int row = blockIdx.x;
    const int tid = threadIdx.x;
    const float4 v = reinterpret_cast<const float4*>(x + (size_t)row * DIM)[tid];
    float s  = v.x + v.y + v.z + v.w;
    float s2 = v.x * v.x + v.y * v.y + v.z * v.z + v.w * v.w;
    __shared__ float rs[256], rs2[256];
    rs[tid] = s; rs2[tid] = s2;
    __syncthreads();
    for (int o = 128; o > 0; o >>= 1) {
        if (tid < o) { rs[tid] += rs[tid + o]; rs2[tid] += rs2[tid + o]; }
        __syncthreads();
    }
    const float mean = rs[0] * (1.0f / DIM);
    const float var  = rs2[0] * (1.0f / DIM) - mean * mean;
    const float rstd = rsqrtf(var + LN_EPS);
    const float4 gg = reinterpret_cast<const float4*>(gvec)[tid];
    const float4 bb = reinterpret_cast<const float4*>(bvec)[tid];
    float4 o;
    o.x = (v.x - mean) * rstd * gg.x + bb.x;
    o.y = (v.y - mean) * rstd * gg.y + bb.y;
    o.z = (v.z - mean) * rstd * gg.z + bb.z;
    o.w = (v.w - mean) * rstd * gg.w + bb.w;
    reinterpret_cast<float4*>(y + (size_t)row * DIM)[tid] = o;
}

__global__ void layernorm_rows_split(const float* __restrict__ x,
                                     const float* __restrict__ gvec,
                                     const float* __restrict__ bvec,
                                     __nv_bfloat16* __restrict__ yh,
                                     __nv_bfloat16* __restrict__ yl) {
    const int row = blockIdx.x;
    const int tid = threadIdx.x;
    const float4 v = reinterpret_cast<const float4*>(x + (size_t)row * DIM)[tid];
    float s  = v.x + v.y + v.z + v.w;
    float s2 = v.x * v.x + v.y * v.y + v.z * v.z + v.w * v.w;
    __shared__ float rs[256], rs2[256];
    rs[tid] = s; rs2[tid] = s2;
    __syncthreads();
    for (int o = 128; o > 0; o >>= 1) {
        if (tid < o) { rs[tid] += rs[tid + o]; rs2[tid] += rs2[tid + o]; }
        __syncthreads();
    }
    const float mean = rs[0] * (1.0f / DIM);
    const float var  = rs2[0] * (1.0f / DIM) - mean * mean;
    const float rstd = rsqrtf(var + LN_EPS);
    const float4 gg = reinterpret_cast<const float4*>(gvec)[tid];
    const float4 bb = reinterpret_cast<const float4*>(bvec)[tid];
    float o[4];
    o[0] = (v.x - mean) * rstd * gg.x + bb.x;
    o[1] = (v.y - mean) * rstd * gg.y + bb.y;
    o[2] = (v.z - mean) * rstd * gg.z + bb.z;
    o[3] = (v.w - mean) * rstd * gg.w + bb.w;
    __nv_bfloat16 hh[4], ll[4];
#pragma unroll
    for (int j = 0; j < 4; j++) {
        hh[j] = __float2bfloat16(o[j]);
        ll[j] = __float2bfloat16(o[j] - __bfloat162float(hh[j]));
    }
    const size_t base = (size_t)row * DIM + tid * 4;
    *reinterpret_cast<ushort4*>(yh + base) = *reinterpret_cast<ushort4*>(hh);
    *reinterpret_cast<ushort4*>(yl + base) = *reinterpret_cast<ushort4*>(ll);
}

// ---------------------------------------------------------------------------
// Launch
// ---------------------------------------------------------------------------
extern "C" void kernel_launch(void* const* d_in, const int* in_sizes, int n_in,
                              void* d_out, int out_size) {
    const float* z      = (const float*)d_in[0];
    const float* pos    = (const float*)d_in[1];
    const float* a      = (const float*)d_in[2];
    const float* hidden = (const float*)d_in[3];
    const float* ln_g   = (const float*)d_in[4];
    const float* ln_b   = (const float*)d_in[5];
    const float* wp1    = (const float*)d_in[6];
    const float* bp1    = (const float*)d_in[7];
    const float* wp2    = (const float*)d_in[8];
    const float* bp2    = (const float*)d_in[9];
    const float* w1     = (const float*)d_in[10];
    const float* b1     = (const float*)d_in[11];
    const float* w2     = (const float*)d_in[12];
    const float* b2     = (const float*)d_in[13];
    float* out = (float*)d_out;

    float *lnz, *lnzT, *hfilt, *hfiltT, *hidT, *znewT, *znew;
    float2 *wfh, *twd;
    __nv_bfloat16 *Xh, *Xl, *Hh, *Hl, *posh, *posl;
    __nv_bfloat16 *wp1t_h, *wp1t_l, *wp2t_h, *wp2t_l, *w1t_h, *w1t_l, *w2t_h, *w2t_l;
    cudaGetSymbolAddress((void**)&lnz,    g_lnz);
    cudaGetSymbolAddress((void**)&lnzT,   g_lnzT);
    cudaGetSymbolAddress((void**)&hfilt,  g_hfilt);
    cudaGetSymbolAddress((void**)&hfiltT, g_hfiltT);
    cudaGetSymbolAddress((void**)&hidT,   g_hidT);
    cudaGetSymbolAddress((void**)&wfh,    g_wfh);
    cudaGetSymbolAddress((void**)&twd,    g_twd);
    cudaGetSymbolAddress((void**)&znewT,  g_znewT);
    cudaGetSymbolAddress((void**)&znew,   g_znew);
    cudaGetSymbolAddress((void**)&Xh,     g_Xh);
    cudaGetSymbolAddress((void**)&Xl,     g_Xl);
    cudaGetSymbolAddress((void**)&Hh,     g_Hh);
    cudaGetSymbolAddress((void**)&Hl,     g_Hl);
    cudaGetSymbolAddress((void**)&posh,   g_posh);
    cudaGetSymbolAddress((void**)&posl,   g_posl);
    cudaGetSymbolAddress((void**)&wp1t_h, g_wp1t_h);
    cudaGetSymbolAddress((void**)&wp1t_l, g_wp1t_l);
    cudaGetSymbolAddress((void**)&wp2t_h, g_wp2t_h);
    cudaGetSymbolAddress((void**)&wp2t_l, g_wp2t_l);
    cudaGetSymbolAddress((void**)&w1t_h,  g_w1t_h);
    cudaGetSymbolAddress((void**)&w1t_l,  g_w1t_l);
    cudaGetSymbolAddress((void**)&w2t_h,  g_w2t_h);
    cudaGetSymbolAddress((void**)&w2t_l,  g_w2t_l);

    cudaFuncSetAttribute(gemm_mma<1, true,  false>,
                         cudaFuncAttributeMaxDynamicSharedMemorySize, GEMM_SMEM);
    cudaFuncSetAttribute(gemm_mma<0, false, false>,
                         cudaFuncAttributeMaxDynamicSharedMemorySize, GEMM_SMEM);
    cudaFuncSetAttribute(gemm_mma<0, false, true>,
                         cudaFuncAttributeMaxDynamicSharedMemorySize, GEMM_SMEM);

    // 0) prep
    transpose_split<<<dim3(DFF / 32, DIM / 32), dim3(32, 8)>>>(wp1, wp1t_h, wp1t_l, DIM, DFF);
    transpose_split<<<dim3(DIM / 32, DFF / 32), dim3(32, 8)>>>(wp2, wp2t_h, wp2t_l, DFF, DIM);
    transpose_split<<<dim3(DFF / 32, DIM / 32), dim3(32, 8)>>>(w1,  w1t_h,  w1t_l,  DIM, DFF);
    transpose_split<<<dim3(DIM / 32, DFF / 32), dim3(32, 8)>>>(w2,  w2t_h,  w2t_l,  DFF, DIM);
    split_f32<<<(LEN * DIM + 255) / 256, 256>>>(pos, posh, posl, LEN * DIM);
    init_twd<<<4, 256>>>(twd);
    transpose32f<<<dim3(DIM / 32, LEN / 32, 1), dim3(32, 8)>>>(hidden, hidT, LEN, DIM);

    // 1) filter FFN
    gemm_mma<1, true, false><<<dim3(DFF / GBN, LEN / GBM), GTHREADS, GEMM_SMEM>>>(
        posh, posl, wp1t_h, wp1t_l, bp1, nullptr, nullptr, Hh, Hl, LEN, DFF, DIM);
    gemm_mma<0, false, false><<<dim3(DIM / GBN, LEN / GBM), GTHREADS, GEMM_SMEM>>>(
        Hh, Hl, wp2t_h, wp2t_l, bp2, nullptr, hfilt, nullptr, nullptr, LEN, DIM, DFF);
    transpose32f<<<dim3(DIM / 32, LEN / 32, 1), dim3(32, 8)>>>(hfilt, hfiltT, LEN, DIM);

    // 2) filter spectra (full, digit-reversed order)
    filter_fft_packed<<<DIM / 2, 256>>>(hfiltT, a, wfh, twd);

    // 3) LN(z) + transpose
    layernorm_rows<<<BATCH * LEN, 256>>>(z, ln_g, ln_b, lnz);
    transpose32f<<<dim3(DIM / 32, LEN / 32, BATCH), dim3(32, 8)>>>(lnz, lnzT, LEN, DIM);

    // 4) FFT convolution (batch pairs) + hidden residual
    fftconv_packed<<<(BATCH / 2) * DIM, 256>>>(lnzT, wfh, hidT, znewT, twd);
    transpose32f<<<dim3(LEN / 32, DIM / 32, BATCH), dim3(32, 8)>>>(znewT, znew, DIM, LEN);

    // 5) LN(znew) -> split bf16
    layernorm_rows_split<<<BATCH * LEN, 256>>>(znew, ln_g, ln_b, Xh, Xl);

    // 6) main FFN + residual
    gemm_mma<1, true, false><<<dim3(DFF / GBN, (BATCH * LEN) / GBM), GTHREADS, GEMM_SMEM>>>(
        Xh, Xl, w1t_h, w1t_l, b1, nullptr, nullptr, Hh, Hl, BATCH * LEN, DFF, DIM);
    gemm_mma<0, false, true><<<dim3(DIM / GBN, (BATCH * LEN) / GBM), GTHREADS, GEMM_SMEM>>>(
        Hh, Hl, w2t_h, w2t_l, b2, znew, out, nullptr, nullptr, BATCH * LEN, DIM, DFF);
}

// round 10
// speedup vs baseline: 2.3224x; 1.8441x over previous
#include <cuda_runtime.h>
#include <cuda_fp16.h>
#include <cuda_bf16.h>
#include <math.h>
#include <cstdint>

// Problem constants
#define BATCH 8
#define LEN   2048
#define DIM   1024
#define DFF   4096
#define NFFT  4096
#define LN_EPS 1e-5f

// ---------------------------------------------------------------------------
// Static device scratch (no allocation allowed)
// ---------------------------------------------------------------------------
__device__ float  g_lnz  [BATCH * LEN * DIM];
__device__ float  g_lnzT [BATCH * DIM * LEN];
__device__ float  g_hfilt[LEN * DIM];
__device__ float  g_hfiltT[DIM * LEN];
__device__ float  g_hidT [DIM * LEN];
__device__ float2 g_wfh  [DIM * NFFT];            // full spectra, digit-reversed order
__device__ float2 g_twd  [1024];
__device__ float  g_znewT[BATCH * DIM * LEN];
__device__ float  g_znew [BATCH * LEN * DIM];
__device__ __half g_X16 [BATCH * LEN * DIM];      // LN(znew) fp16
__device__ __half g_H16 [BATCH * LEN * DFF];      // FFN hidden fp16
__device__ __half g_pos16[LEN * DIM];
// transposed fp16 weights: [N, K] layout
__device__ __half g_wp1t[DFF * DIM];
__device__ __half g_wp2t[DIM * DFF];
__device__ __half g_w1t [DFF * DIM];
__device__ __half g_w2t [DIM * DFF];

// ---------------------------------------------------------------------------
// PTX wrappers (baseline sm_80+ only)
// ---------------------------------------------------------------------------
__device__ __forceinline__ uint32_t smem_u32(const void* p) {
    uint32_t a;
    asm("{ .reg .u64 t; cvta.to.shared.u64 t, %1; cvt.u32.u64 %0, t; }"
        : "=r"(a) : "l"(p));
    return a;
}
__device__ __forceinline__ void cpasync16(uint32_t s, const void* g) {
    asm volatile("cp.async.cg.shared.global [%0], [%1], 16;"
                 :: "r"(s), "l"(g) : "memory");
}
__device__ __forceinline__ void cp_commit() {
    asm volatile("cp.async.commit_group;" ::: "memory");
}
template <int N>
__device__ __forceinline__ void cp_wait() {
    asm volatile("cp.async.wait_group %0;" :: "n"(N) : "memory");
}
__device__ __forceinline__ void ldm_x4(uint32_t& r0, uint32_t& r1,
                                       uint32_t& r2, uint32_t& r3, uint32_t a) {
    asm volatile("ldmatrix.sync.aligned.m8n8.x4.shared.b16 {%0,%1,%2,%3}, [%4];"
                 : "=r"(r0), "=r"(r1), "=r"(r2), "=r"(r3) : "r"(a));
}
__device__ __forceinline__ void ldm_x2(uint32_t& r0, uint32_t& r1, uint32_t a) {
    asm volatile("ldmatrix.sync.aligned.m8n8.x2.shared.b16 {%0,%1}, [%2];"
                 : "=r"(r0), "=r"(r1) : "r"(a));
}
__device__ __forceinline__ void mma_f16(float4& d, const uint32_t* a,
                                        uint32_t b0, uint32_t b1) {
    asm volatile(
        "mma.sync.aligned.m16n8k16.row.col.f32.f16.f16.f32 "
        "{%0,%1,%2,%3}, {%4,%5,%6,%7}, {%8,%9}, {%0,%1,%2,%3};"
        : "+f"(d.x), "+f"(d.y), "+f"(d.z), "+f"(d.w)
        : "r"(a[0]), "r"(a[1]), "r"(a[2]), "r"(a[3]), "r"(b0), "r"(b1));
}

// ---------------------------------------------------------------------------
// HMMA fp16 GEMM: C[M,N] = epi( A[M,K] @ B[N,K]^T + bias )
// Block 128x128, BK=32, 4 warps (2m x 2n), warp tile 64x64,
// 3-stage cp.async pipeline, 80B-padded rows, single-term fp16.
// ---------------------------------------------------------------------------
#define GBM 128
#define GBN 128
#define GBK 32
#define TPAD 40
#define TILE_B (128 * TPAD * 2)      // 10240 bytes per matrix tile
#define STAGE_B (2 * TILE_B)         // A, B
#define GEMM_SMEM (3 * STAGE_B)      // 61440 bytes
#define GTHREADS 128

template <int ACT, bool H_OUT, bool HAS_ADD>
__global__ __launch_bounds__(GTHREADS)
void gemm_mma(const __half* __restrict__ A, const __half* __restrict__ B,
              const float* __restrict__ bias, const float* __restrict__ add,
              float* __restrict__ Cf, __half* __restrict__ Ch,
              int M, int N, int K) {
    extern __shared__ char smem[];
    const uint32_t sbase = smem_u32(smem);
    const int tid  = threadIdx.x;
    const int lane = tid & 31;
    const int wid  = tid >> 5;       // 0..3
    const int wm   = wid & 1;        // 2 warp rows (64 M each)
    const int wn   = wid >> 1;       // 2 warp cols (64 N each)
    const int bm = blockIdx.y * GBM;
    const int bn = blockIdx.x * GBN;

    auto issue_loads = [&](int stage, int k0) {
        const uint32_t sb = sbase + stage * STAGE_B;
#pragma unroll
        for (int p = 0; p < 4; p++) {
            const int idx = p * GTHREADS + tid;      // 0..511
            const int row = idx >> 2;                // 0..127
            const int c0  = idx & 3;                 // 16B chunk
            const uint32_t so = (uint32_t)(row * 80 + c0 * 16);
            const size_t kk = (size_t)k0 + c0 * 8;
            cpasync16(sb + so,          A + (size_t)(bm + row) * K + kk);
            cpasync16(sb + TILE_B + so, B + (size_t)(bn + row) * K + kk);
        }
        cp_commit();
    };

    float4 acc[4][8];
#pragma unroll
    for (int i = 0; i < 4; i++)
#pragma unroll
        for (int j = 0; j < 8; j++) acc[i][j] = make_float4(0.f, 0.f, 0.f, 0.f);

    const int a_row = (lane & 7) + ((lane >> 3) & 1) * 8;
    const int a_kc  = ((lane >> 4) & 1) * 8;
    const int b_row = lane & 7;
    const int b_kc  = ((lane >> 3) & 1) * 8;

    const int NT = K / GBK;
    issue_loads(0, 0);
    issue_loads(1, GBK);

    for (int kt = 0; kt < NT; kt++) {
        if (kt + 2 < NT) { issue_loads((kt + 2) % 3, (kt + 2) * GBK); cp_wait<2>(); }
        else if (kt + 1 < NT) cp_wait<1>();
        else cp_wait<0>();
        __syncthreads();

        const uint32_t st = sbase + (kt % 3) * STAGE_B;
        const uint32_t As = st;
        const uint32_t Bs = st + TILE_B;

#pragma unroll
        for (int k16 = 0; k16 < 2; k16++) {
            uint32_t ah[4][4];
#pragma unroll
            for (int i = 0; i < 4; i++) {
                const uint32_t ao =
                    (uint32_t)((wm * 64 + i * 16 + a_row) * 80 +
                               (k16 * 16 + a_kc) * 2);
                ldm_x4(ah[i][0], ah[i][1], ah[i][2], ah[i][3], As + ao);
            }
#pragma unroll
            for (int j = 0; j < 8; j++) {
                const uint32_t bo =
                    (uint32_t)((wn * 64 + j * 8 + b_row) * 80 +
                               (k16 * 16 + b_kc) * 2);
                uint32_t b0, b1;
                ldm_x2(b0, b1, Bs + bo);
#pragma unroll
                for (int i = 0; i < 4; i++)
                    mma_f16(acc[i][j], ah[i], b0, b1);
            }
        }
        __syncthreads();
    }

    // epilogue: warp tile 64x64 at (bm + wm*64, bn + wn*64)
    const int qr = lane >> 2;
    const int qc = (lane & 3) * 2;
#pragma unroll
    for (int i = 0; i < 4; i++) {
#pragma unroll
        for (int j = 0; j < 8; j++) {
            const int gr0 = bm + wm * 64 + i * 16 + qr;
            const int gc  = bn + wn * 64 + j * 8 + qc;
            const float b0 = bias[gc];
            const float b1 = bias[gc + 1];
            float v00 = acc[i][j].x + b0, v01 = acc[i][j].y + b1;
            float v10 = acc[i][j].z + b0, v11 = acc[i][j].w + b1;
            if (ACT == 1) {
                v00 = v00 / (1.0f + expf(-v00));
                v01 = v01 / (1.0f + expf(-v01));
                v10 = v10 / (1.0f + expf(-v10));
                v11 = v11 / (1.0f + expf(-v11));
            }
            if (HAS_ADD) {
                v00 += add[(size_t)gr0 * N + gc];
                v01 += add[(size_t)gr0 * N + gc + 1];
                v10 += add[(size_t)(gr0 + 8) * N + gc];
                v11 += add[(size_t)(gr0 + 8) * N + gc + 1];
            }
            if (H_OUT) {
                *reinterpret_cast<__half2*>(Ch + (size_t)gr0 * N + gc) =
                    __halves2half2(__float2half_rn(v00), __float2half_rn(v01));
                *reinterpret_cast<__half2*>(Ch + (size_t)(gr0 + 8) * N + gc) =
                    __halves2half2(__float2half_rn(v10), __float2half_rn(v11));
            } else {
                *reinterpret_cast<float2*>(Cf + (size_t)gr0 * N + gc) =
                    make_float2(v00, v01);
                *reinterpret_cast<float2*>(Cf + (size_t)(gr0 + 8) * N + gc) =
                    make_float2(v10, v11);
            }
        }
    }
}

// ---------------------------------------------------------------------------
// Prep kernels
// ---------------------------------------------------------------------------
__global__ void transpose_h(const float* __restrict__ W,
                            __half* __restrict__ T, int K, int N) {
    __shared__ float t[32][33];
    const int n0 = blockIdx.x * 32, k0 = blockIdx.y * 32;
    const int tx = threadIdx.x, ty = threadIdx.y;
#pragma unroll
    for (int dy = 0; dy < 32; dy += 8)
        t[ty + dy][tx] = W[(size_t)(k0 + ty + dy) * N + n0 + tx];
    __syncthreads();
#pragma unroll
    for (int dy = 0; dy < 32; dy += 8) {
        const int n = n0 + ty + dy, k = k0 + tx;
        T[(size_t)n * K + k] = __float2half_rn(t[tx][ty + dy]);
    }
}

__global__ void cvt_f32_h(const float* __restrict__ x, __half* __restrict__ h, int n) {
    int i = blockIdx.x * 256 + threadIdx.x;
    if (i < n) h[i] = __float2half_rn(x[i]);
}

__global__ void transpose32f(const float* __restrict__ in, float* __restrict__ out,
                             int R, int C) {
    __shared__ float t[32][33];
    const size_t boff = (size_t)blockIdx.z * R * C;
    const float* ip = in + boff;
    float* op = out + boff;
    const int r0 = blockIdx.y * 32, c0 = blockIdx.x * 32;
    const int tx = threadIdx.x, ty = threadIdx.y;
#pragma unroll
    for (int dy = 0; dy < 32; dy += 8)
        t[ty + dy][tx] = ip[(size_t)(r0 + ty + dy) * C + c0 + tx];
    __syncthreads();
#pragma unroll
    for (int dy = 0; dy < 32; dy += 8)
        op[(size_t)(c0 + ty + dy) * R + r0 + tx] = t[tx][ty + dy];
}

__global__ void init_twd(float2* __restrict__ twd) {
    int k = blockIdx.x * 256 + threadIdx.x;
    if (k < 1024) {
        double s, c;
        sincos(-6.283185307179586476925286766559 * (double)k / 4096.0, &s, &c);
        twd[k] = make_float2((float)c, (float)s);
    }
}

// ---------------------------------------------------------------------------
// Radix-4 FFT, 4096 points, 256 threads. DIF forward (natural -> digit-rev,
// zero-padded input [0,2048) only) and DIT inverse (digit-rev -> natural).
// ---------------------------------------------------------------------------
#define PIDX(i) ((i) + ((i) >> 4))

__device__ __forceinline__ float2 cmul(float2 a, float2 b) {
    return make_float2(a.x * b.x - a.y * b.y, a.x * b.y + a.y * b.x);
}
__device__ __forceinline__ int rev4(int p) {
    int b = __brev(p) >> 20;
    return ((b & 0x555) << 1) | ((b >> 1) & 0x555);
}

__device__ void fft4096_dif_pad(float2* sm, const float2* tw) {
    const int tid = threadIdx.x;
    __syncthreads();
#pragma unroll
    for (int u = 0; u < 4; u++) {
        const int j = tid + u * 256;
        float2 x0 = sm[PIDX(j)];
        float2 x1 = sm[PIDX(j + 1024)];
        float2 w1 = tw[j];
        float2 w2 = cmul(w1, w1);
        float2 w3 = cmul(w2, w1);
        float2 y0 = make_float2(x0.x + x1.x, x0.y + x1.y);
        float2 y1 = make_float2(x0.x + x1.y, x0.y - x1.x);
        float2 y2 = make_float2(x0.x - x1.x, x0.y - x1.y);
        float2 y3 = make_float2(x0.x - x1.y, x0.y + x1.x);
        sm[PIDX(j)]        = y0;
        sm[PIDX(j + 1024)] = cmul(y1, w1);
        sm[PIDX(j + 2048)] = cmul(y2, w2);
        sm[PIDX(j + 3072)] = cmul(y3, w3);
    }
    __syncthreads();
#pragma unroll
    for (int len = 1024; len >= 4; len >>= 2) {
        const int q = len >> 2;
        const int S = NFFT / len;
#pragma unroll
        for (int u = 0; u < 4; u++) {
            const int bf = tid + u * 256;
            const int g  = bf / q;
            const int j  = bf - g * q;
            const int base = g * len + j;
            float2 x0 = sm[PIDX(base)];
            float2 x1 = sm[PIDX(base + q)];
            float2 x2 = sm[PIDX(base + 2 * q)];
            float2 x3 = sm[PIDX(base + 3 * q)];
            float2 t0 = make_float2(x0.x + x2.x, x0.y + x2.y);
            float2 t1 = make_float2(x0.x - x2.x, x0.y - x2.y);
            float2 t2 = make_float2(x1.x + x3.x, x1.y + x3.y);
            float2 t3 = make_float2(x1.x - x3.x, x1.y - x3.y);
            float2 y0 = make_float2(t0.x + t2.x, t0.y + t2.y);
            float2 y2 = make_float2(t0.x - t2.x, t0.y - t2.y);
            float2 y1 = make_float2(t1.x + t3.y, t1.y - t3.x);
            float2 y3 = make_float2(t1.x - t3.y, t1.y + t3.x);
            float2 w1 = tw[j * S];
            float2 w2 = cmul(w1, w1);
            float2 w3 = cmul(w2, w1);
            sm[PIDX(base)]         = y0;
            sm[PIDX(base + q)]     = cmul(y1, w1);
            sm[PIDX(base + 2 * q)] = cmul(y2, w2);
            sm[PIDX(base + 3 * q)] = cmul(y3, w3);
        }
        __syncthreads();
    }
}

__device__ void fft4096_dit_inv(float2* sm, const float2* tw) {
    const int tid = threadIdx.x;
    __syncthreads();
#pragma unroll
    for (int st = 0; st < 6; st++) {
        const int len = 4 << (2 * st);
        const int q   = len >> 2;
        const int S   = NFFT / len;
#pragma unroll
        for (int u = 0; u < 4; u++) {
            const int bf = tid + u * 256;
            const int g  = bf / q;
            const int j  = bf - g * q;
            const int base = g * len + j;
            float2 x0 = sm[PIDX(base)];
            float2 x1 = sm[PIDX(base + q)];
            float2 x2 = sm[PIDX(base + 2 * q)];
            float2 x3 = sm[PIDX(base + 3 * q)];
            float2 w1 = tw[j * S];
            w1.y = -w1.y;
            float2 w2 = cmul(w1, w1);
            float2 w3 = cmul(w1, w2);
            x1 = cmul(x1, w1);
            x2 = cmul(x2, w2);
            x3 = cmul(x3, w3);
            float2 t0 = make_float2(x0.x + x2.x, x0.y + x2.y);
            float2 t1 = make_float2(x0.x - x2.x, x0.y - x2.y);
            float2 t2 = make_float2(x1.x + x3.x, x1.y + x3.y);
            float2 t3 = make_float2(x1.x - x3.x, x1.y - x3.y);
            sm[PIDX(base)]         = make_float2(t0.x + t2.x, t0.y + t2.y);
            sm[PIDX(base + 2 * q)] = make_float2(t0.x - t2.x, t0.y - t2.y);
            sm[PIDX(base + q)]     = make_float2(t1.x - t3.y, t1.y + t3.x);
            sm[PIDX(base + 3 * q)] = make_float2(t1.x + t3.y, t1.y - t3.x);
        }
        __syncthreads();
    }
}

// ---------------------------------------------------------------------------
// Filter spectra: 2 channels per block (Hermitian split), output FULL
// spectra in digit-reversed order for pointwise use in fftconv.
// ---------------------------------------------------------------------------
__global__ __launch_bounds__(256)
void filter_fft_packed(const float* __restrict__ hfiltT,
                       const float* __restrict__ a,
                       float2* __restrict__ wfh,
                       const float2* __restrict__ twd) {
    __shared__ float2 sd[PIDX(NFFT)];
    __shared__ float2 tw[1024];
    const int tid = threadIdx.x;
    const int d0 = blockIdx.x * 2;
    const int d1 = d0 + 1;
    for (int i = tid; i < 1024; i += 256) tw[i] = twd[i];
    const float ea = expf(a[0]);
    for (int t = tid; t < LEN; t += 256) {
        const float w = expf(-(float)t * ea);
        sd[PIDX(t)] = make_float2(hfiltT[(size_t)d0 * LEN + t] * w,
                                  hfiltT[(size_t)d1 * LEN + t] * w);
    }
    fft4096_dif_pad(sd, tw);
    for (int p = tid; p < NFFT; p += 256) {
        const int k  = rev4(p);
        const int k2 = (NFFT - k) & (NFFT - 1);
        const int p2 = rev4(k2);
        float2 X1 = sd[PIDX(p)];
        float2 X2 = sd[PIDX(p2)];
        wfh[(size_t)d0 * NFFT + p] =
            make_float2(0.5f * (X1.x + X2.x), 0.5f * (X1.y - X2.y));
        wfh[(size_t)d1 * NFFT + p] =
            make_float2(0.5f * (X1.y + X2.y), -0.5f * (X1.x - X2.x));
    }
}

// ---------------------------------------------------------------------------
// FFT convolution: two BATCHES packed per block (real filter => pointwise
// multiply valid in digit-reversed order).
// ---------------------------------------------------------------------------
__global__ __launch_bounds__(256)
void fftconv_packed(const float* __restrict__ lnzT,
                    const float2* __restrict__ wfh,
                    const float* __restrict__ hidT,
                    float* __restrict__ znewT,
                    const float2* __restrict__ twd) {
    __shared__ float2 sd[PIDX(NFFT)];
    __shared__ float2 tw[1024];
    const int tid = threadIdx.x;
    const int d  = blockIdx.x & (DIM - 1);
    const int bp = blockIdx.x >> 10;
    const int b0 = bp * 2;
    const int b1 = b0 + 1;
    for (int i = tid; i < 1024; i += 256) tw[i] = twd[i];
    const float* x0 = lnzT + ((size_t)b0 * DIM + d) * LEN;
    const float* x1 = lnzT + ((size_t)b1 * DIM + d) * LEN;
    for (int t = tid; t < LEN; t += 256)
        sd[PIDX(t)] = make_float2(x0[t], x1[t]);

    fft4096_dif_pad(sd, tw);

    const float2* F = wfh + (size_t)d * NFFT;
    for (int p = tid; p < NFFT; p += 256)
        sd[PIDX(p)] = cmul(sd[PIDX(p)], F[p]);

    fft4096_dit_inv(sd, tw);

    const float inv = 1.0f / (float)NFFT;
    float* o0 = znewT + ((size_t)b0 * DIM + d) * LEN;
    float* o1 = znewT + ((size_t)b1 * DIM + d) * LEN;
    const float* h = hidT + (size_t)d * LEN;
    for (int t = tid; t < LEN; t += 256) {
        float2 v = sd[PIDX(t)];
        const float hv = h[t];
        o0[t] = v.x * inv + hv;
        o1[t] = v.y * inv + hv;
    }
}

// ---------------------------------------------------------------------------
// LayerNorm kernels
// ---------------------------------------------------------------------------
__global__ void layernorm_rows(const float* __restrict__ x,
                               const float* __restrict__ gvec,
                               const float* __restrict__ bvec,
                               float* __restrict__ y) {
    const int row = blockIdx.x;
    const int tid = threadIdx.x;
    const float4 v = reinterpret_cast<const float4*>(x + (size_t)row * DIM)[tid];
    float s  = v.x + v.y + v.z + v.w;
    float s2 = v.x * v.x + v.y * v.y + v.z * v.z + v.w * v.w;
    __shared__ float rs[256], rs2[256];
    rs[tid] = s; rs2[tid] = s2;
    __syncthreads();
    for (int o = 128; o > 0; o >>= 1) {
        if (tid < o) { rs[tid] += rs[tid + o]; rs2[tid] += rs2[tid + o]; }
        __syncthreads();
    }
    const float mean = rs[0] * (1.0f / DIM);
    const float var  = rs2[0] * (1.0f / DIM) - mean * mean;
    const float rstd = rsqrtf(var + LN_EPS);
    const float4 gg = reinterpret_cast<const float4*>(gvec)[tid];
    const float4 bb = reinterpret_cast<const float4*>(bvec)[tid];
    float4 o;
    o.x = (v.x - mean) * rstd * gg.x + bb.x;
    o.y = (v.y - mean) * rstd * gg.y + bb.y;
    o.z = (v.z - mean) * rstd * gg.z + bb.z;
    o.w = (v.w - mean) * rstd * gg.w + bb.w;
    reinterpret_cast<float4*>(y + (size_t)row * DIM)[tid] = o;
}

__global__ void layernorm_rows_h(const float* __restrict__ x,
                                 const float* __restrict__ gvec,
                                 const float* __restrict__ bvec,
                                 __half* __restrict__ yh) {
    const int row = blockIdx.x;
    const int tid = threadIdx.x;
    const float4 v = reinterpret_cast<const float4*>(x + (size_t)row * DIM)[tid];
    float s  = v.x + v.y + v.z + v.w;
    float s2 = v.x * v.x + v.y * v.y + v.z * v.z + v.w * v.w;
    __shared__ float rs[256], rs2[256];
    rs[tid] = s; rs2[tid] = s2;
    __syncthreads();
    for (int o = 128; o > 0; o >>= 1) {
        if (tid < o) { rs[tid] += rs[tid + o]; rs2[tid] += rs2[tid + o]; }
        __syncthreads();
    }
    const float mean = rs[0] * (1.0f / DIM);
    const float var  = rs2[0] * (1.0f / DIM) - mean * mean;
    const float rstd = rsqrtf(var + LN_EPS);
    const float4 gg = reinterpret_cast<const float4*>(gvec)[tid];
    const float4 bb = reinterpret_cast<const float4*>(bvec)[tid];
    __half h[4];
    h[0] = __float2half_rn((v.x - mean) * rstd * gg.x + bb.x);
    h[1] = __float2half_rn((v.y - mean) * rstd * gg.y + bb.y);
    h[2] = __float2half_rn((v.z - mean) * rstd * gg.z + bb.z);
    h[3] = __float2half_rn((v.w - mean) * rstd * gg.w + bb.w);
    *reinterpret_cast<ushort4*>(yh + (size_t)row * DIM + tid * 4) =
        *reinterpret_cast<ushort4*>(h);
}

// ---------------------------------------------------------------------------
// Launch
// ---------------------------------------------------------------------------
extern "C" void kernel_launch(void* const* d_in, const int* in_sizes, int n_in,
                              void* d_out, int out_size) {
    const float* z      = (const float*)d_in[0];
    const float* pos    = (const float*)d_in[1];
    const float* a      = (const float*)d_in[2];
    const float* hidden = (const float*)d_in[3];
    const float* ln_g   = (const float*)d_in[4];
    const float* ln_b   = (const float*)d_in[5];
    const float* wp1    = (const float*)d_in[6];
    const float* bp1    = (const float*)d_in[7];
    const float* wp2    = (const float*)d_in[8];
    const float* bp2    = (const float*)d_in[9];
    const float* w1     = (const float*)d_in[10];
    const float* b1     = (const float*)d_in[11];
    const float* w2     = (const float*)d_in[12];
    const float* b2     = (const float*)d_in[13];
    float* out = (float*)d_out;

    float *lnz, *lnzT, *hfilt, *hfiltT, *hidT, *znewT, *znew;
    float2 *wfh, *twd;
    __half *X16, *H16, *pos16, *wp1t, *wp2t, *w1t, *w2t;
    cudaGetSymbolAddress((void**)&lnz,    g_lnz);
    cudaGetSymbolAddress((void**)&lnzT,   g_lnzT);
    cudaGetSymbolAddress((void**)&hfilt,  g_hfilt);
    cudaGetSymbolAddress((void**)&hfiltT, g_hfiltT);
    cudaGetSymbolAddress((void**)&hidT,   g_hidT);
    cudaGetSymbolAddress((void**)&wfh,    g_wfh);
    cudaGetSymbolAddress((void**)&twd,    g_twd);
    cudaGetSymbolAddress((void**)&znewT,  g_znewT);
    cudaGetSymbolAddress((void**)&znew,   g_znew);
    cudaGetSymbolAddress((void**)&X16,    g_X16);
    cudaGetSymbolAddress((void**)&H16,    g_H16);
    cudaGetSymbolAddress((void**)&pos16,  g_pos16);
    cudaGetSymbolAddress((void**)&wp1t,   g_wp1t);
    cudaGetSymbolAddress((void**)&wp2t,   g_wp2t);
    cudaGetSymbolAddress((void**)&w1t,    g_w1t);
    cudaGetSymbolAddress((void**)&w2t,    g_w2t);

    cudaFuncSetAttribute(gemm_mma<1, true,  false>,
                         cudaFuncAttributeMaxDynamicSharedMemorySize, GEMM_SMEM);
    cudaFuncSetAttribute(gemm_mma<0, false, false>,
                         cudaFuncAttributeMaxDynamicSharedMemorySize, GEMM_SMEM);
    cudaFuncSetAttribute(gemm_mma<0, false, true>,
                         cudaFuncAttributeMaxDynamicSharedMemorySize, GEMM_SMEM);

    // 0) prep
    transpose_h<<<dim3(DFF / 32, DIM / 32), dim3(32, 8)>>>(wp1, wp1t, DIM, DFF);
    transpose_h<<<dim3(DIM / 32, DFF / 32), dim3(32, 8)>>>(wp2, wp2t, DFF, DIM);
    transpose_h<<<dim3(DFF / 32, DIM / 32), dim3(32, 8)>>>(w1,  w1t,  DIM, DFF);
    transpose_h<<<dim3(DIM / 32, DFF / 32), dim3(32, 8)>>>(w2,  w2t,  DFF, DIM);
    cvt_f32_h<<<(LEN * DIM + 255) / 256, 256>>>(pos, pos16, LEN * DIM);
    init_twd<<<4, 256>>>(twd);
    transpose32f<<<dim3(DIM / 32, LEN / 32, 1), dim3(32, 8)>>>(hidden, hidT, LEN, DIM);

    // 1) filter FFN
    gemm_mma<1, true, false><<<dim3(DFF / GBN, LEN / GBM), GTHREADS, GEMM_SMEM>>>(
        pos16, wp1t, bp1, nullptr, nullptr, H16, LEN, DFF, DIM);
    gemm_mma<0, false, false><<<dim3(DIM / GBN, LEN / GBM), GTHREADS, GEMM_SMEM>>>(
        H16, wp2t, bp2, nullptr, hfilt, nullptr, LEN, DIM, DFF);
    transpose32f<<<dim3(DIM / 32, LEN / 32, 1), dim3(32, 8)>>>(hfilt, hfiltT, LEN, DIM);

    // 2) filter spectra (full, digit-reversed order)
    filter_fft_packed<<<DIM / 2, 256>>>(hfiltT, a, wfh, twd);

    // 3) LN(z) + transpose
    layernorm_rows<<<BATCH * LEN, 256>>>(z, ln_g, ln_b, lnz);
    transpose32f<<<dim3(DIM / 32, LEN / 32, BATCH), dim3(32, 8)>>>(lnz, lnzT, LEN, DIM);

    // 4) FFT convolution (batch pairs) + hidden residual
    fftconv_packed<<<(BATCH / 2) * DIM, 256>>>(lnzT, wfh, hidT, znewT, twd);
    transpose32f<<<dim3(LEN / 32, DIM / 32, BATCH), dim3(32, 8)>>>(znewT, znew, DIM, LEN);

    // 5) LN(znew) -> fp16
    layernorm_rows_h<<<BATCH * LEN, 256>>>(znew, ln_g, ln_b, X16);

    // 6) main FFN + residual
    gemm_mma<1, true, false><<<dim3(DFF / GBN, (BATCH * LEN) / GBM), GTHREADS, GEMM_SMEM>>>(
        X16, w1t, b1, nullptr, nullptr, H16, BATCH * LEN, DFF, DIM);
    gemm_mma<0, false, true><<<dim3(DIM / GBN, (BATCH * LEN) / GBM), GTHREADS, GEMM_SMEM>>>(
        H16, w2t, b2, znew, out, nullptr, BATCH * LEN, DIM, DFF);
}

// round 11
// speedup vs baseline: 2.3301x; 1.0033x over previous
#include <cuda_runtime.h>
#include <cuda_fp16.h>
#include <cuda_bf16.h>
#include <math.h>
#include <cstdint>

// Problem constants
#define BATCH 8
#define LEN   2048
#define DIM   1024
#define DFF   4096
#define NFFT  4096
#define LN_EPS 1e-5f

// ---------------------------------------------------------------------------
// Static device scratch (no allocation allowed)
// ---------------------------------------------------------------------------
__device__ float  g_lnz  [BATCH * LEN * DIM];
__device__ float  g_lnzT [BATCH * DIM * LEN];
__device__ float  g_hfilt[LEN * DIM];
__device__ float  g_hfiltT[DIM * LEN];
__device__ float  g_hidT [DIM * LEN];
__device__ float2 g_wfh  [DIM * NFFT];            // full spectra, digit-reversed order
__device__ float2 g_twd  [1024];
__device__ float  g_znewT[BATCH * DIM * LEN];
__device__ float  g_znew [BATCH * LEN * DIM];
__device__ __half g_X16 [BATCH * LEN * DIM];      // LN(znew) fp16
__device__ __half g_H16 [BATCH * LEN * DFF];      // FFN hidden fp16
__device__ __half g_pos16[LEN * DIM];
// transposed fp16 weights: [N, K] layout
__device__ __half g_wp1t[DFF * DIM];
__device__ __half g_wp2t[DIM * DFF];
__device__ __half g_w1t [DFF * DIM];
__device__ __half g_w2t [DIM * DFF];

// ---------------------------------------------------------------------------
// PTX wrappers (baseline sm_80+ only)
// ---------------------------------------------------------------------------
__device__ __forceinline__ uint32_t smem_u32(const void* p) {
    uint32_t a;
    asm("{ .reg .u64 t; cvta.to.shared.u64 t, %1; cvt.u32.u64 %0, t; }"
        : "=r"(a) : "l"(p));
    return a;
}
__device__ __forceinline__ void cpasync16(uint32_t s, const void* g) {
    asm volatile("cp.async.cg.shared.global [%0], [%1], 16;"
                 :: "r"(s), "l"(g) : "memory");
}
__device__ __forceinline__ void cp_commit() {
    asm volatile("cp.async.commit_group;" ::: "memory");
}
template <int N>
__device__ __forceinline__ void cp_wait() {
    asm volatile("cp.async.wait_group %0;" :: "n"(N) : "memory");
}
__device__ __forceinline__ void ldm_x4(uint32_t& r0, uint32_t& r1,
                                       uint32_t& r2, uint32_t& r3, uint32_t a) {
    asm volatile("ldmatrix.sync.aligned.m8n8.x4.shared.b16 {%0,%1,%2,%3}, [%4];"
                 : "=r"(r0), "=r"(r1), "=r"(r2), "=r"(r3) : "r"(a));
}
__device__ __forceinline__ void ldm_x2(uint32_t& r0, uint32_t& r1, uint32_t a) {
    asm volatile("ldmatrix.sync.aligned.m8n8.x2.shared.b16 {%0,%1}, [%2];"
                 : "=r"(r0), "=r"(r1) : "r"(a));
}
__device__ __forceinline__ void mma_f16(float4& d, const uint32_t* a,
                                        uint32_t b0, uint32_t b1) {
    asm volatile(
        "mma.sync.aligned.m16n8k16.row.col.f32.f16.f16.f32 "
        "{%0,%1,%2,%3}, {%4,%5,%6,%7}, {%8,%9}, {%0,%1,%2,%3};"
        : "+f"(d.x), "+f"(d.y), "+f"(d.z), "+f"(d.w)
        : "r"(a[0]), "r"(a[1]), "r"(a[2]), "r"(a[3]), "r"(b0), "r"(b1));
}

// ---------------------------------------------------------------------------
// HMMA fp16 GEMM: C[M,N] = epi( A[M,K] @ B[N,K]^T + bias )
// Block 128x128, BK=32, 4 warps (2m x 2n), warp tile 64x64,
// 4-stage cp.async pipeline, ONE __syncthreads per k-tile.
// ---------------------------------------------------------------------------
#define GBM 128
#define GBN 128
#define GBK 32
#define TPAD 40
#define TILE_B (128 * TPAD * 2)      // 10240 bytes per matrix tile
#define STAGE_B (2 * TILE_B)         // A, B
#define NSTAGE 4
#define GEMM_SMEM (NSTAGE * STAGE_B) // 81920 bytes
#define GTHREADS 128

template <int ACT, bool H_OUT, bool HAS_ADD>
__global__ __launch_bounds__(GTHREADS)
void gemm_mma(const __half* __restrict__ A, const __half* __restrict__ B,
              const float* __restrict__ bias, const float* __restrict__ add,
              float* __restrict__ Cf, __half* __restrict__ Ch,
              int M, int N, int K) {
    extern __shared__ char smem[];
    const uint32_t sbase = smem_u32(smem);
    const int tid  = threadIdx.x;
    const int lane = tid & 31;
    const int wid  = tid >> 5;       // 0..3
    const int wm   = wid & 1;        // 2 warp rows (64 M each)
    const int wn   = wid >> 1;       // 2 warp cols (64 N each)
    const int bm = blockIdx.y * GBM;
    const int bn = blockIdx.x * GBN;

    auto issue_loads = [&](int stage, int k0) {
        const uint32_t sb = sbase + stage * STAGE_B;
#pragma unroll
        for (int p = 0; p < 4; p++) {
            const int idx = p * GTHREADS + tid;      // 0..511
            const int row = idx >> 2;                // 0..127
            const int c0  = idx & 3;                 // 16B chunk
            const uint32_t so = (uint32_t)(row * 80 + c0 * 16);
            const size_t kk = (size_t)k0 + c0 * 8;
            cpasync16(sb + so,          A + (size_t)(bm + row) * K + kk);
            cpasync16(sb + TILE_B + so, B + (size_t)(bn + row) * K + kk);
        }
        cp_commit();
    };

    float4 acc[4][8];
#pragma unroll
    for (int i = 0; i < 4; i++)
#pragma unroll
        for (int j = 0; j < 8; j++) acc[i][j] = make_float4(0.f, 0.f, 0.f, 0.f);

    const int a_row = (lane & 7) + ((lane >> 3) & 1) * 8;
    const int a_kc  = ((lane >> 4) & 1) * 8;
    const int b_row = lane & 7;
    const int b_kc  = ((lane >> 3) & 1) * 8;

    const int NT = K / GBK;
    issue_loads(0, 0);
    issue_loads(1, GBK);

    for (int kt = 0; kt < NT; kt++) {
        cp_wait<1>();                    // stage kt resident
        __syncthreads();                 // all warps done with compute(kt-1)
        if (kt + 2 < NT)                 // safe: stage (kt+2)%4 idle since kt-2
            issue_loads((kt + 2) % NSTAGE, (kt + 2) * GBK);

        const uint32_t st = sbase + (kt % NSTAGE) * STAGE_B;
        const uint32_t As = st;
        const uint32_t Bs = st + TILE_B;

#pragma unroll
        for (int k16 = 0; k16 < 2; k16++) {
            uint32_t ah[4][4];
#pragma unroll
            for (int i = 0; i < 4; i++) {
                const uint32_t ao =
                    (uint32_t)((wm * 64 + i * 16 + a_row) * 80 +
                               (k16 * 16 + a_kc) * 2);
                ldm_x4(ah[i][0], ah[i][1], ah[i][2], ah[i][3], As + ao);
            }
#pragma unroll
            for (int j = 0; j < 8; j++) {
                const uint32_t bo =
                    (uint32_t)((wn * 64 + j * 8 + b_row) * 80 +
                               (k16 * 16 + b_kc) * 2);
                uint32_t b0, b1;
                ldm_x2(b0, b1, Bs + bo);
#pragma unroll
                for (int i = 0; i < 4; i++)
                    mma_f16(acc[i][j], ah[i], b0, b1);
            }
        }
    }

    // epilogue: warp tile 64x64 at (bm + wm*64, bn + wn*64)
    const int qr = lane >> 2;
    const int qc = (lane & 3) * 2;
#pragma unroll
    for (int i = 0; i < 4; i++) {
#pragma unroll
        for (int j = 0; j < 8; j++) {
            const int gr0 = bm + wm * 64 + i * 16 + qr;
            const int gc  = bn + wn * 64 + j * 8 + qc;
            const float b0 = bias[gc];
            const float b1 = bias[gc + 1];
            float v00 = acc[i][j].x + b0, v01 = acc[i][j].y + b1;
            float v10 = acc[i][j].z + b0, v11 = acc[i][j].w + b1;
            if (ACT == 1) {
                v00 = v00 / (1.0f + expf(-v00));
                v01 = v01 / (1.0f + expf(-v01));
                v10 = v10 / (1.0f + expf(-v10));
                v11 = v11 / (1.0f + expf(-v11));
            }
            if (HAS_ADD) {
                v00 += add[(size_t)gr0 * N + gc];
                v01 += add[(size_t)gr0 * N + gc + 1];
                v10 += add[(size_t)(gr0 + 8) * N + gc];
                v11 += add[(size_t)(gr0 + 8) * N + gc + 1];
            }
            if (H_OUT) {
                *reinterpret_cast<__half2*>(Ch + (size_t)gr0 * N + gc) =
                    __halves2half2(__float2half_rn(v00), __float2half_rn(v01));
                *reinterpret_cast<__half2*>(Ch + (size_t)(gr0 + 8) * N + gc) =
                    __halves2half2(__float2half_rn(v10), __float2half_rn(v11));
            } else {
                *reinterpret_cast<float2*>(Cf + (size_t)gr0 * N + gc) =
                    make_float2(v00, v01);
                *reinterpret_cast<float2*>(Cf + (size_t)(gr0 + 8) * N + gc) =
                    make_float2(v10, v11);
            }
        }
    }
}

// ---------------------------------------------------------------------------
// Prep kernels
// ---------------------------------------------------------------------------
__global__ void transpose_h(const float* __restrict__ W,
                            __half* __restrict__ T, int K, int N) {
    __shared__ float t[32][33];
    const int n0 = blockIdx.x * 32, k0 = blockIdx.y * 32;
    const int tx = threadIdx.x, ty = threadIdx.y;
#pragma unroll
    for (int dy = 0; dy < 32; dy += 8)
        t[ty + dy][tx] = W[(size_t)(k0 + ty + dy) * N + n0 + tx];
    __syncthreads();
#pragma unroll
    for (int dy = 0; dy < 32; dy += 8) {
        const int n = n0 + ty + dy, k = k0 + tx;
        T[(size_t)n * K + k] = __float2half_rn(t[tx][ty + dy]);
    }
}

__global__ void cvt_f32_h(const float* __restrict__ x, __half* __restrict__ h, int n) {
    int i = blockIdx.x * 256 + threadIdx.x;
    if (i < n) h[i] = __float2half_rn(x[i]);
}

__global__ void transpose32f(const float* __restrict__ in, float* __restrict__ out,
                             int R, int C) {
    __shared__ float t[32][33];
    const size_t boff = (size_t)blockIdx.z * R * C;
    const float* ip = in + boff;
    float* op = out + boff;
    const int r0 = blockIdx.y * 32, c0 = blockIdx.x * 32;
    const int tx = threadIdx.x, ty = threadIdx.y;
#pragma unroll
    for (int dy = 0; dy < 32; dy += 8)
        t[ty + dy][tx] = ip[(size_t)(r0 + ty + dy) * C + c0 + tx];
    __syncthreads();
#pragma unroll
    for (int dy = 0; dy < 32; dy += 8)
        op[(size_t)(c0 + ty + dy) * R + r0 + tx] = t[tx][ty + dy];
}

__global__ void init_twd(float2* __restrict__ twd) {
    int k = blockIdx.x * 256 + threadIdx.x;
    if (k < 1024) {
        double s, c;
        sincos(-6.283185307179586476925286766559 * (double)k / 4096.0, &s, &c);
        twd[k] = make_float2((float)c, (float)s);
    }
}

// ---------------------------------------------------------------------------
// Radix-4 FFT, 4096 points, 256 threads. DIF forward (natural -> digit-rev,
// zero-padded input [0,2048) only) and DIT inverse (digit-rev -> natural).
// ---------------------------------------------------------------------------
#define PIDX(i) ((i) + ((i) >> 4))

__device__ __forceinline__ float2 cmul(float2 a, float2 b) {
    return make_float2(a.x * b.x - a.y * b.y, a.x * b.y + a.y * b.x);
}
__device__ __forceinline__ int rev4(int p) {
    int b = __brev(p) >> 20;
    return ((b & 0x555) << 1) | ((b >> 1) & 0x555);
}

__device__ void fft4096_dif_pad(float2* sm, const float2* tw) {
    const int tid = threadIdx.x;
    __syncthreads();
#pragma unroll
    for (int u = 0; u < 4; u++) {
        const int j = tid + u * 256;
        float2 x0 = sm[PIDX(j)];
        float2 x1 = sm[PIDX(j + 1024)];
        float2 w1 = tw[j];
        float2 w2 = cmul(w1, w1);
        float2 w3 = cmul(w2, w1);
        float2 y0 = make_float2(x0.x + x1.x, x0.y + x1.y);
        float2 y1 = make_float2(x0.x + x1.y, x0.y - x1.x);
        float2 y2 = make_float2(x0.x - x1.x, x0.y - x1.y);
        float2 y3 = make_float2(x0.x - x1.y, x0.y + x1.x);
        sm[PIDX(j)]        = y0;
        sm[PIDX(j + 1024)] = cmul(y1, w1);
        sm[PIDX(j + 2048)] = cmul(y2, w2);
        sm[PIDX(j + 3072)] = cmul(y3, w3);
    }
    __syncthreads();
#pragma unroll
    for (int len = 1024; len >= 4; len >>= 2) {
        const int q = len >> 2;
        const int S = NFFT / len;
#pragma unroll
        for (int u = 0; u < 4; u++) {
            const int bf = tid + u * 256;
            const int g  = bf / q;
            const int j  = bf - g * q;
            const int base = g * len + j;
            float2 x0 = sm[PIDX(base)];
            float2 x1 = sm[PIDX(base + q)];
            float2 x2 = sm[PIDX(base + 2 * q)];
            float2 x3 = sm[PIDX(base + 3 * q)];
            float2 t0 = make_float2(x0.x + x2.x, x0.y + x2.y);
            float2 t1 = make_float2(x0.x - x2.x, x0.y - x2.y);
            float2 t2 = make_float2(x1.x + x3.x, x1.y + x3.y);
            float2 t3 = make_float2(x1.x - x3.x, x1.y - x3.y);
            float2 y0 = make_float2(t0.x + t2.x, t0.y + t2.y);
            float2 y2 = make_float2(t0.x - t2.x, t0.y - t2.y);
            float2 y1 = make_float2(t1.x + t3.y, t1.y - t3.x);
            float2 y3 = make_float2(t1.x - t3.y, t1.y + t3.x);
            float2 w1 = tw[j * S];
            float2 w2 = cmul(w1, w1);
            float2 w3 = cmul(w2, w1);
            sm[PIDX(base)]         = y0;
            sm[PIDX(base + q)]     = cmul(y1, w1);
            sm[PIDX(base + 2 * q)] = cmul(y2, w2);
            sm[PIDX(base + 3 * q)] = cmul(y3, w3);
        }
        __syncthreads();
    }
}

__device__ void fft4096_dit_inv(float2* sm, const float2* tw) {
    const int tid = threadIdx.x;
    __syncthreads();
#pragma unroll
    for (int st = 0; st < 6; st++) {
        const int len = 4 << (2 * st);
        const int q   = len >> 2;
        const int S   = NFFT / len;
#pragma unroll
        for (int u = 0; u < 4; u++) {
            const int bf = tid + u * 256;
            const int g  = bf / q;
            const int j  = bf - g * q;
            const int base = g * len + j;
            float2 x0 = sm[PIDX(base)];
            float2 x1 = sm[PIDX(base + q)];
            float2 x2 = sm[PIDX(base + 2 * q)];
            float2 x3 = sm[PIDX(base + 3 * q)];
            float2 w1 = tw[j * S];
            w1.y = -w1.y;
            float2 w2 = cmul(w1, w1);
            float2 w3 = cmul(w1, w2);
            x1 = cmul(x1, w1);
            x2 = cmul(x2, w2);
            x3 = cmul(x3, w3);
            float2 t0 = make_float2(x0.x + x2.x, x0.y + x2.y);
            float2 t1 = make_float2(x0.x - x2.x, x0.y - x2.y);
            float2 t2 = make_float2(x1.x + x3.x, x1.y + x3.y);
            float2 t3 = make_float2(x1.x - x3.x, x1.y - x3.y);
            sm[PIDX(base)]         = make_float2(t0.x + t2.x, t0.y + t2.y);
            sm[PIDX(base + 2 * q)] = make_float2(t0.x - t2.x, t0.y - t2.y);
            sm[PIDX(base + q)]     = make_float2(t1.x - t3.y, t1.y + t3.x);
            sm[PIDX(base + 3 * q)] = make_float2(t1.x + t3.y, t1.y - t3.x);
        }
        __syncthreads();
    }
}

// ---------------------------------------------------------------------------
// Filter spectra: 2 channels per block (Hermitian split), output FULL
// spectra in digit-reversed order for pointwise use in fftconv.
// ---------------------------------------------------------------------------
__global__ __launch_bounds__(256)
void filter_fft_packed(const float* __restrict__ hfiltT,
                       const float* __restrict__ a,
                       float2* __restrict__ wfh,
                       const float2* __restrict__ twd) {
    __shared__ float2 sd[PIDX(NFFT)];
    __shared__ float2 tw[1024];
    const int tid = threadIdx.x;
    const int d0 = blockIdx.x * 2;
    const int d1 = d0 + 1;
    for (int i = tid; i < 1024; i += 256) tw[i] = twd[i];
    const float ea = expf(a[0]);
    for (int t = tid; t < LEN; t += 256) {
        const float w = expf(-(float)t * ea);
        sd[PIDX(t)] = make_float2(hfiltT[(size_t)d0 * LEN + t] * w,
                                  hfiltT[(size_t)d1 * LEN + t] * w);
    }
    fft4096_dif_pad(sd, tw);
    for (int p = tid; p < NFFT; p += 256) {
        const int k  = rev4(p);
        const int k2 = (NFFT - k) & (NFFT - 1);
        const int p2 = rev4(k2);
        float2 X1 = sd[PIDX(p)];
        float2 X2 = sd[PIDX(p2)];
        wfh[(size_t)d0 * NFFT + p] =
            make_float2(0.5f * (X1.x + X2.x), 0.5f * (X1.y - X2.y));
        wfh[(size_t)d1 * NFFT + p] =
            make_float2(0.5f * (X1.y + X2.y), -0.5f * (X1.x - X2.x));
    }
}

// ---------------------------------------------------------------------------
// FFT convolution: two BATCHES packed per block (real filter => pointwise
// multiply valid in digit-reversed order).
// ---------------------------------------------------------------------------
__global__ __launch_bounds__(256)
void fftconv_packed(const float* __restrict__ lnzT,
                    const float2* __restrict__ wfh,
                    const float* __restrict__ hidT,
                    float* __restrict__ znewT,
                    const float2* __restrict__ twd) {
    __shared__ float2 sd[PIDX(NFFT)];
    __shared__ float2 tw[1024];
    const int tid = threadIdx.x;
    const int d  = blockIdx.x & (DIM - 1);
    const int bp = blockIdx.x >> 10;
    const int b0 = bp * 2;
    const int b1 = b0 + 1;
    for (int i = tid; i < 1024; i += 256) tw[i] = twd[i];
    const float* x0 = lnzT + ((size_t)b0 * DIM + d) * LEN;
    const float* x1 = lnzT + ((size_t)b1 * DIM + d) * LEN;
    for (int t = tid; t < LEN; t += 256)
        sd[PIDX(t)] = make_float2(x0[t], x1[t]);

    fft4096_dif_pad(sd, tw);

    const float2* F = wfh + (size_t)d * NFFT;
    for (int p = tid; p < NFFT; p += 256)
        sd[PIDX(p)] = cmul(sd[PIDX(p)], F[p]);

    fft4096_dit_inv(sd, tw);

    const float inv = 1.0f / (float)NFFT;
    float* o0 = znewT + ((size_t)b0 * DIM + d) * LEN;
    float* o1 = znewT + ((size_t)b1 * DIM + d) * LEN;
    const float* h = hidT + (size_t)d * LEN;
    for (int t = tid; t < LEN; t += 256) {
        float2 v = sd[PIDX(t)];
        const float hv = h[t];
        o0[t] = v.x * inv + hv;
        o1[t] = v.y * inv + hv;
    }
}

// ---------------------------------------------------------------------------
// LayerNorm kernels
// ---------------------------------------------------------------------------
__global__ void layernorm_rows(const float* __restrict__ x,
                               const float* __restrict__ gvec,
                               const float* __restrict__ bvec,
                               float* __restrict__ y) {
    const int row = blockIdx.x;
    const int tid = threadIdx.x;
    const float4 v = reinterpret_cast<const float4*>(x + (size_t)row * DIM)[tid];
    float s  = v.x + v.y + v.z + v.w;
    float s2 = v.x * v.x + v.y * v.y + v.z * v.z + v.w * v.w;
    __shared__ float rs[256], rs2[256];
    rs[tid] = s; rs2[tid] = s2;
    __syncthreads();
    for (int o = 128; o > 0; o >>= 1) {
        if (tid < o) { rs[tid] += rs[tid + o]; rs2[tid] += rs2[tid + o]; }
        __syncthreads();
    }
    const float mean = rs[0] * (1.0f / DIM);
    const float var  = rs2[0] * (1.0f / DIM) - mean * mean;
    const float rstd = rsqrtf(var + LN_EPS);
    const float4 gg = reinterpret_cast<const float4*>(gvec)[tid];
    const float4 bb = reinterpret_cast<const float4*>(bvec)[tid];
    float4 o;
    o.x = (v.x - mean) * rstd * gg.x + bb.x;
    o.y = (v.y - mean) * rstd * gg.y + bb.y;
    o.z = (v.z - mean) * rstd * gg.z + bb.z;
    o.w = (v.w - mean) * rstd * gg.w + bb.w;
    reinterpret_cast<float4*>(y + (size_t)row * DIM)[tid] = o;
}

__global__ void layernorm_rows_h(const float* __restrict__ x,
                                 const float* __restrict__ gvec,
                                 const float* __restrict__ bvec,
                                 __half* __restrict__ yh) {
    const int row = blockIdx.x;
    const int tid = threadIdx.x;
    const float4 v = reinterpret_cast<const float4*>(x + (size_t)row * DIM)[tid];
    float s  = v.x + v.y + v.z + v.w;
    float s2 = v.x * v.x + v.y * v.y + v.z * v.z + v.w * v.w;
    __shared__ float rs[256], rs2[256];
    rs[tid] = s; rs2[tid] = s2;
    __syncthreads();
    for (int o = 128; o > 0; o >>= 1) {
        if (tid < o) { rs[tid] += rs[tid + o]; rs2[tid] += rs2[tid + o]; }
        __syncthreads();
    }
    const float mean = rs[0] * (1.0f / DIM);
    const float var  = rs2[0] * (1.0f / DIM) - mean * mean;
    const float rstd = rsqrtf(var + LN_EPS);
    const float4 gg = reinterpret_cast<const float4*>(gvec)[tid];
    const float4 bb = reinterpret_cast<const float4*>(bvec)[tid];
    __half h[4];
    h[0] = __float2half_rn((v.x - mean) * rstd * gg.x + bb.x);
    h[1] = __float2half_rn((v.y - mean) * rstd * gg.y + bb.y);
    h[2] = __float2half_rn((v.z - mean) * rstd * gg.z + bb.z);
    h[3] = __float2half_rn((v.w - mean) * rstd * gg.w + bb.w);
    *reinterpret_cast<ushort4*>(yh + (size_t)row * DIM + tid * 4) =
        *reinterpret_cast<ushort4*>(h);
}

// ---------------------------------------------------------------------------
// Launch
// ---------------------------------------------------------------------------
extern "C" void kernel_launch(void* const* d_in, const int* in_sizes, int n_in,
                              void* d_out, int out_size) {
    const float* z      = (const float*)d_in[0];
    const float* pos    = (const float*)d_in[1];
    const float* a      = (const float*)d_in[2];
    const float* hidden = (const float*)d_in[3];
    const float* ln_g   = (const float*)d_in[4];
    const float* ln_b   = (const float*)d_in[5];
    const float* wp1    = (const float*)d_in[6];
    const float* bp1    = (const float*)d_in[7];
    const float* wp2    = (const float*)d_in[8];
    const float* bp2    = (const float*)d_in[9];
    const float* w1     = (const float*)d_in[10];
    const float* b1     = (const float*)d_in[11];
    const float* w2     = (const float*)d_in[12];
    const float* b2     = (const float*)d_in[13];
    float* out = (float*)d_out;

    float *lnz, *lnzT, *hfilt, *hfiltT, *hidT, *znewT, *znew;
    float2 *wfh, *twd;
    __half *X16, *H16, *pos16, *wp1t, *wp2t, *w1t, *w2t;
    cudaGetSymbolAddress((void**)&lnz,    g_lnz);
    cudaGetSymbolAddress((void**)&lnzT,   g_lnzT);
    cudaGetSymbolAddress((void**)&hfilt,  g_hfilt);
    cudaGetSymbolAddress((void**)&hfiltT, g_hfiltT);
    cudaGetSymbolAddress((void**)&hidT,   g_hidT);
    cudaGetSymbolAddress((void**)&wfh,    g_wfh);
    cudaGetSymbolAddress((void**)&twd,    g_twd);
    cudaGetSymbolAddress((void**)&znewT,  g_znewT);
    cudaGetSymbolAddress((void**)&znew,   g_znew);
    cudaGetSymbolAddress((void**)&X16,    g_X16);
    cudaGetSymbolAddress((void**)&H16,    g_H16);
    cudaGetSymbolAddress((void**)&pos16,  g_pos16);
    cudaGetSymbolAddress((void**)&wp1t,   g_wp1t);
    cudaGetSymbolAddress((void**)&wp2t,   g_wp2t);
    cudaGetSymbolAddress((void**)&w1t,    g_w1t);
    cudaGetSymbolAddress((void**)&w2t,    g_w2t);

    cudaFuncSetAttribute(gemm_mma<1, true,  false>,
                         cudaFuncAttributeMaxDynamicSharedMemorySize, GEMM_SMEM);
    cudaFuncSetAttribute(gemm_mma<0, false, false>,
                         cudaFuncAttributeMaxDynamicSharedMemorySize, GEMM_SMEM);
    cudaFuncSetAttribute(gemm_mma<0, false, true>,
                         cudaFuncAttributeMaxDynamicSharedMemorySize, GEMM_SMEM);

    // 0) prep
    transpose_h<<<dim3(DFF / 32, DIM / 32), dim3(32, 8)>>>(wp1, wp1t, DIM, DFF);
    transpose_h<<<dim3(DIM / 32, DFF / 32), dim3(32, 8)>>>(wp2, wp2t, DFF, DIM);
    transpose_h<<<dim3(DFF / 32, DIM / 32), dim3(32, 8)>>>(w1,  w1t,  DIM, DFF);
    transpose_h<<<dim3(DIM / 32, DFF / 32), dim3(32, 8)>>>(w2,  w2t,  DFF, DIM);
    cvt_f32_h<<<(LEN * DIM + 255) / 256, 256>>>(pos, pos16, LEN * DIM);
    init_twd<<<4, 256>>>(twd);
    transpose32f<<<dim3(DIM / 32, LEN / 32, 1), dim3(32, 8)>>>(hidden, hidT, LEN, DIM);

    // 1) filter FFN
    gemm_mma<1, true, false><<<dim3(DFF / GBN, LEN / GBM), GTHREADS, GEMM_SMEM>>>(
        pos16, wp1t, bp1, nullptr, nullptr, H16, LEN, DFF, DIM);
    gemm_mma<0, false, false><<<dim3(DIM / GBN, LEN / GBM), GTHREADS, GEMM_SMEM>>>(
        H16, wp2t, bp2, nullptr, hfilt, nullptr, LEN, DIM, DFF);
    transpose32f<<<dim3(DIM / 32, LEN / 32, 1), dim3(32, 8)>>>(hfilt, hfiltT, LEN, DIM);

    // 2) filter spectra (full, digit-reversed order)
    filter_fft_packed<<<DIM / 2, 256>>>(hfiltT, a, wfh, twd);

    // 3) LN(z) + transpose
    layernorm_rows<<<BATCH * LEN, 256>>>(z, ln_g, ln_b, lnz);
    transpose32f<<<dim3(DIM / 32, LEN / 32, BATCH), dim3(32, 8)>>>(lnz, lnzT, LEN, DIM);

    // 4) FFT convolution (batch pairs) + hidden residual
    fftconv_packed<<<(BATCH / 2) * DIM, 256>>>(lnzT, wfh, hidT, znewT, twd);
    transpose32f<<<dim3(LEN / 32, DIM / 32, BATCH), dim3(32, 8)>>>(znewT, znew, DIM, LEN);

    // 5) LN(znew) -> fp16
    layernorm_rows_h<<<BATCH * LEN, 256>>>(znew, ln_g, ln_b, X16);

    // 6) main FFN + residual
    gemm_mma<1, true, false><<<dim3(DFF / GBN, (BATCH * LEN) / GBM), GTHREADS, GEMM_SMEM>>>(
        X16, w1t, b1, nullptr, nullptr, H16, BATCH * LEN, DFF, DIM);
    gemm_mma<0, false, true><<<dim3(DIM / GBN, (BATCH * LEN) / GBM), GTHREADS, GEMM_SMEM>>>(
        H16, w2t, b2, znew, out, nullptr, BATCH * LEN, DIM, DFF);
}

// round 12
// speedup vs baseline: 2.3705x; 1.0173x over previous
#include <cuda_runtime.h>
#include <cuda_fp16.h>
#include <cuda_bf16.h>
#include <math.h>
#include <cstdint>

// Problem constants
#define BATCH 8
#define LEN   2048
#define DIM   1024
#define DFF   4096
#define NFFT  4096
#define LN_EPS 1e-5f

// ---------------------------------------------------------------------------
// Static device scratch (no allocation allowed)
// ---------------------------------------------------------------------------
__device__ float  g_lnz  [BATCH * LEN * DIM];
__device__ float  g_lnzT [BATCH * DIM * LEN];
__device__ float  g_hfilt[LEN * DIM];
__device__ float  g_hfiltT[DIM * LEN];
__device__ float  g_hidT [DIM * LEN];
__device__ float2 g_wfh  [DIM * NFFT];            // full spectra, digit-reversed order
__device__ float2 g_twd  [1024];
__device__ float  g_znewT[BATCH * DIM * LEN];
__device__ float  g_znew [BATCH * LEN * DIM];
__device__ __half g_X16 [BATCH * LEN * DIM];      // LN(znew) fp16
__device__ __half g_H16 [BATCH * LEN * DFF];      // FFN hidden fp16
__device__ __half g_pos16[LEN * DIM];
// transposed fp16 weights: [N, K] layout
__device__ __half g_wp1t[DFF * DIM];
__device__ __half g_wp2t[DIM * DFF];
__device__ __half g_w1t [DFF * DIM];
__device__ __half g_w2t [DIM * DFF];

// ---------------------------------------------------------------------------
// PTX wrappers (baseline sm_80+ only)
// ---------------------------------------------------------------------------
__device__ __forceinline__ uint32_t smem_u32(const void* p) {
    uint32_t a;
    asm("{ .reg .u64 t; cvta.to.shared.u64 t, %1; cvt.u32.u64 %0, t; }"
        : "=r"(a) : "l"(p));
    return a;
}
__device__ __forceinline__ void cpasync16(uint32_t s, const void* g) {
    asm volatile("cp.async.cg.shared.global [%0], [%1], 16;"
                 :: "r"(s), "l"(g) : "memory");
}
__device__ __forceinline__ void cp_commit() {
    asm volatile("cp.async.commit_group;" ::: "memory");
}
template <int N>
__device__ __forceinline__ void cp_wait() {
    asm volatile("cp.async.wait_group %0;" :: "n"(N) : "memory");
}
__device__ __forceinline__ void ldm_x4(uint32_t& r0, uint32_t& r1,
                                       uint32_t& r2, uint32_t& r3, uint32_t a) {
    asm volatile("ldmatrix.sync.aligned.m8n8.x4.shared.b16 {%0,%1,%2,%3}, [%4];"
                 : "=r"(r0), "=r"(r1), "=r"(r2), "=r"(r3) : "r"(a));
}
__device__ __forceinline__ void ldm_x2(uint32_t& r0, uint32_t& r1, uint32_t a) {
    asm volatile("ldmatrix.sync.aligned.m8n8.x2.shared.b16 {%0,%1}, [%2];"
                 : "=r"(r0), "=r"(r1) : "r"(a));
}
__device__ __forceinline__ void mma_f16(float4& d, const uint32_t* a,
                                        uint32_t b0, uint32_t b1) {
    asm volatile(
        "mma.sync.aligned.m16n8k16.row.col.f32.f16.f16.f32 "
        "{%0,%1,%2,%3}, {%4,%5,%6,%7}, {%8,%9}, {%0,%1,%2,%3};"
        : "+f"(d.x), "+f"(d.y), "+f"(d.z), "+f"(d.w)
        : "r"(a[0]), "r"(a[1]), "r"(a[2]), "r"(a[3]), "r"(b0), "r"(b1));
}

// ---------------------------------------------------------------------------
// HMMA fp16 GEMM: C[M,N] = epi( A[M,K] @ B[N,K]^T + bias )
// Block 128x128, BK=32, 4 warps (2m x 2n), warp tile 64x64,
// 4-stage cp.async pipeline, ONE __syncthreads per k-tile.
// ---------------------------------------------------------------------------
#define GBM 128
#define GBN 128
#define GBK 32
#define TPAD 40
#define TILE_B (128 * TPAD * 2)      // 10240 bytes per matrix tile
#define STAGE_B (2 * TILE_B)         // A, B
#define NSTAGE 4
#define GEMM_SMEM (NSTAGE * STAGE_B) // 81920 bytes
#define GTHREADS 128

template <int ACT, bool H_OUT, bool HAS_ADD>
__global__ __launch_bounds__(GTHREADS)
void gemm_mma(const __half* __restrict__ A, const __half* __restrict__ B,
              const float* __restrict__ bias, const float* __restrict__ add,
              float* __restrict__ Cf, __half* __restrict__ Ch,
              int M, int N, int K) {
    extern __shared__ char smem[];
    const uint32_t sbase = smem_u32(smem);
    const int tid  = threadIdx.x;
    const int lane = tid & 31;
    const int wid  = tid >> 5;       // 0..3
    const int wm   = wid & 1;        // 2 warp rows (64 M each)
    const int wn   = wid >> 1;       // 2 warp cols (64 N each)
    const int bm = blockIdx.y * GBM;
    const int bn = blockIdx.x * GBN;

    auto issue_loads = [&](int stage, int k0) {
        const uint32_t sb = sbase + stage * STAGE_B;
#pragma unroll
        for (int p = 0; p < 4; p++) {
            const int idx = p * GTHREADS + tid;      // 0..511
            const int row = idx >> 2;                // 0..127
            const int c0  = idx & 3;                 // 16B chunk
            const uint32_t so = (uint32_t)(row * 80 + c0 * 16);
            const size_t kk = (size_t)k0 + c0 * 8;
            cpasync16(sb + so,          A + (size_t)(bm + row) * K + kk);
            cpasync16(sb + TILE_B + so, B + (size_t)(bn + row) * K + kk);
        }
        cp_commit();
    };

    float4 acc[4][8];
#pragma unroll
    for (int i = 0; i < 4; i++)
#pragma unroll
        for (int j = 0; j < 8; j++) acc[i][j] = make_float4(0.f, 0.f, 0.f, 0.f);

    const int a_row = (lane & 7) + ((lane >> 3) & 1) * 8;
    const int a_kc  = ((lane >> 4) & 1) * 8;
    const int b_row = lane & 7;
    const int b_kc  = ((lane >> 3) & 1) * 8;

    const int NT = K / GBK;
    issue_loads(0, 0);
    issue_loads(1, GBK);

    for (int kt = 0; kt < NT; kt++) {
        cp_wait<1>();                    // stage kt resident
        __syncthreads();                 // all warps done with compute(kt-1)
        if (kt + 2 < NT)                 // safe: stage (kt+2)%4 idle since kt-2
            issue_loads((kt + 2) % NSTAGE, (kt + 2) * GBK);

        const uint32_t st = sbase + (kt % NSTAGE) * STAGE_B;
        const uint32_t As = st;
        const uint32_t Bs = st + TILE_B;

#pragma unroll
        for (int k16 = 0; k16 < 2; k16++) {
            uint32_t ah[4][4];
#pragma unroll
            for (int i = 0; i < 4; i++) {
                const uint32_t ao =
                    (uint32_t)((wm * 64 + i * 16 + a_row) * 80 +
                               (k16 * 16 + a_kc) * 2);
                ldm_x4(ah[i][0], ah[i][1], ah[i][2], ah[i][3], As + ao);
            }
#pragma unroll
            for (int j = 0; j < 8; j++) {
                const uint32_t bo =
                    (uint32_t)((wn * 64 + j * 8 + b_row) * 80 +
                               (k16 * 16 + b_kc) * 2);
                uint32_t b0, b1;
                ldm_x2(b0, b1, Bs + bo);
#pragma unroll
                for (int i = 0; i < 4; i++)
                    mma_f16(acc[i][j], ah[i], b0, b1);
            }
        }
    }

    // epilogue: warp tile 64x64 at (bm + wm*64, bn + wn*64)
    const int qr = lane >> 2;
    const int qc = (lane & 3) * 2;
#pragma unroll
    for (int i = 0; i < 4; i++) {
#pragma unroll
        for (int j = 0; j < 8; j++) {
            const int gr0 = bm + wm * 64 + i * 16 + qr;
            const int gc  = bn + wn * 64 + j * 8 + qc;
            const float b0 = bias[gc];
            const float b1 = bias[gc + 1];
            float v00 = acc[i][j].x + b0, v01 = acc[i][j].y + b1;
            float v10 = acc[i][j].z + b0, v11 = acc[i][j].w + b1;
            if (ACT == 1) {
                v00 = v00 / (1.0f + expf(-v00));
                v01 = v01 / (1.0f + expf(-v01));
                v10 = v10 / (1.0f + expf(-v10));
                v11 = v11 / (1.0f + expf(-v11));
            }
            if (HAS_ADD) {
                v00 += add[(size_t)gr0 * N + gc];
                v01 += add[(size_t)gr0 * N + gc + 1];
                v10 += add[(size_t)(gr0 + 8) * N + gc];
                v11 += add[(size_t)(gr0 + 8) * N + gc + 1];
            }
            if (H_OUT) {
                *reinterpret_cast<__half2*>(Ch + (size_t)gr0 * N + gc) =
                    __halves2half2(__float2half_rn(v00), __float2half_rn(v01));
                *reinterpret_cast<__half2*>(Ch + (size_t)(gr0 + 8) * N + gc) =
                    __halves2half2(__float2half_rn(v10), __float2half_rn(v11));
            } else {
                *reinterpret_cast<float2*>(Cf + (size_t)gr0 * N + gc) =
                    make_float2(v00, v01);
                *reinterpret_cast<float2*>(Cf + (size_t)(gr0 + 8) * N + gc) =
                    make_float2(v10, v11);
            }
        }
    }
}

// ---------------------------------------------------------------------------
// Prep kernels
// ---------------------------------------------------------------------------
__global__ void transpose_h(const float* __restrict__ W,
                            __half* __restrict__ T, int K, int N) {
    __shared__ float t[32][33];
    const int n0 = blockIdx.x * 32, k0 = blockIdx.y * 32;
    const int tx = threadIdx.x, ty = threadIdx.y;
#pragma unroll
    for (int dy = 0; dy < 32; dy += 8)
        t[ty + dy][tx] = W[(size_t)(k0 + ty + dy) * N + n0 + tx];
    __syncthreads();
#pragma unroll
    for (int dy = 0; dy < 32; dy += 8) {
        const int n = n0 + ty + dy, k = k0 + tx;
        T[(size_t)n * K + k] = __float2half_rn(t[tx][ty + dy]);
    }
}

__global__ void cvt_f32_h(const float* __restrict__ x, __half* __restrict__ h, int n) {
    int i = blockIdx.x * 256 + threadIdx.x;
    if (i < n) h[i] = __float2half_rn(x[i]);
}

__global__ void transpose32f(const float* __restrict__ in, float* __restrict__ out,
                             int R, int C) {
    __shared__ float t[32][33];
    const size_t boff = (size_t)blockIdx.z * R * C;
    const float* ip = in + boff;
    float* op = out + boff;
    const int r0 = blockIdx.y * 32, c0 = blockIdx.x * 32;
    const int tx = threadIdx.x, ty = threadIdx.y;
#pragma unroll
    for (int dy = 0; dy < 32; dy += 8)
        t[ty + dy][tx] = ip[(size_t)(r0 + ty + dy) * C + c0 + tx];
    __syncthreads();
#pragma unroll
    for (int dy = 0; dy < 32; dy += 8)
        op[(size_t)(c0 + ty + dy) * R + r0 + tx] = t[tx][ty + dy];
}

__global__ void init_twd(float2* __restrict__ twd) {
    int k = blockIdx.x * 256 + threadIdx.x;
    if (k < 1024) {
        double s, c;
        sincos(-6.283185307179586476925286766559 * (double)k / 4096.0, &s, &c);
        twd[k] = make_float2((float)c, (float)s);
    }
}

// ---------------------------------------------------------------------------
// Radix-4 FFT, 4096 points, 256 threads. DIF forward (natural -> digit-rev,
// zero-padded input [0,2048) only) and DIT inverse (digit-rev -> natural).
// ---------------------------------------------------------------------------
#define PIDX(i) ((i) + ((i) >> 4))

__device__ __forceinline__ float2 cmul(float2 a, float2 b) {
    return make_float2(a.x * b.x - a.y * b.y, a.x * b.y + a.y * b.x);
}
__device__ __forceinline__ int rev4(int p) {
    int b = __brev(p) >> 20;
    return ((b & 0x555) << 1) | ((b >> 1) & 0x555);
}

__device__ void fft4096_dif_pad(float2* sm, const float2* tw) {
    const int tid = threadIdx.x;
    __syncthreads();
#pragma unroll
    for (int u = 0; u < 4; u++) {
        const int j = tid + u * 256;
        float2 x0 = sm[PIDX(j)];
        float2 x1 = sm[PIDX(j + 1024)];
        float2 w1 = tw[j];
        float2 w2 = cmul(w1, w1);
        float2 w3 = cmul(w2, w1);
        float2 y0 = make_float2(x0.x + x1.x, x0.y + x1.y);
        float2 y1 = make_float2(x0.x + x1.y, x0.y - x1.x);
        float2 y2 = make_float2(x0.x - x1.x, x0.y - x1.y);
        float2 y3 = make_float2(x0.x - x1.y, x0.y + x1.x);
        sm[PIDX(j)]        = y0;
        sm[PIDX(j + 1024)] = cmul(y1, w1);
        sm[PIDX(j + 2048)] = cmul(y2, w2);
        sm[PIDX(j + 3072)] = cmul(y3, w3);
    }
    __syncthreads();
#pragma unroll
    for (int len = 1024; len >= 4; len >>= 2) {
        const int q = len >> 2;
        const int S = NFFT / len;
#pragma unroll
        for (int u = 0; u < 4; u++) {
            const int bf = tid + u * 256;
            const int g  = bf / q;
            const int j  = bf - g * q;
            const int base = g * len + j;
            float2 x0 = sm[PIDX(base)];
            float2 x1 = sm[PIDX(base + q)];
            float2 x2 = sm[PIDX(base + 2 * q)];
            float2 x3 = sm[PIDX(base + 3 * q)];
            float2 t0 = make_float2(x0.x + x2.x, x0.y + x2.y);
            float2 t1 = make_float2(x0.x - x2.x, x0.y - x2.y);
            float2 t2 = make_float2(x1.x + x3.x, x1.y + x3.y);
            float2 t3 = make_float2(x1.x - x3.x, x1.y - x3.y);
            float2 y0 = make_float2(t0.x + t2.x, t0.y + t2.y);
            float2 y2 = make_float2(t0.x - t2.x, t0.y - t2.y);
            float2 y1 = make_float2(t1.x + t3.y, t1.y - t3.x);
            float2 y3 = make_float2(t1.x - t3.y, t1.y + t3.x);
            float2 w1 = tw[j * S];
            float2 w2 = cmul(w1, w1);
            float2 w3 = cmul(w2, w1);
            sm[PIDX(base)]         = y0;
            sm[PIDX(base + q)]     = cmul(y1, w1);
            sm[PIDX(base + 2 * q)] = cmul(y2, w2);
            sm[PIDX(base + 3 * q)] = cmul(y3, w3);
        }
        __syncthreads();
    }
}

__device__ void fft4096_dit_inv(float2* sm, const float2* tw) {
    const int tid = threadIdx.x;
    __syncthreads();
#pragma unroll
    for (int st = 0; st < 6; st++) {
        const int len = 4 << (2 * st);
        const int q   = len >> 2;
        const int S   = NFFT / len;
#pragma unroll
        for (int u = 0; u < 4; u++) {
            const int bf = tid + u * 256;
            const int g  = bf / q;
            const int j  = bf - g * q;
            const int base = g * len + j;
            float2 x0 = sm[PIDX(base)];
            float2 x1 = sm[PIDX(base + q)];
            float2 x2 = sm[PIDX(base + 2 * q)];
            float2 x3 = sm[PIDX(base + 3 * q)];
            float2 w1 = tw[j * S];
            w1.y = -w1.y;
            float2 w2 = cmul(w1, w1);
            float2 w3 = cmul(w1, w2);
            x1 = cmul(x1, w1);
            x2 = cmul(x2, w2);
            x3 = cmul(x3, w3);
            float2 t0 = make_float2(x0.x + x2.x, x0.y + x2.y);
            float2 t1 = make_float2(x0.x - x2.x, x0.y - x2.y);
            float2 t2 = make_float2(x1.x + x3.x, x1.y + x3.y);
            float2 t3 = make_float2(x1.x - x3.x, x1.y - x3.y);
            sm[PIDX(base)]         = make_float2(t0.x + t2.x, t0.y + t2.y);
            sm[PIDX(base + 2 * q)] = make_float2(t0.x - t2.x, t0.y - t2.y);
            sm[PIDX(base + q)]     = make_float2(t1.x - t3.y, t1.y + t3.x);
            sm[PIDX(base + 3 * q)] = make_float2(t1.x + t3.y, t1.y - t3.x);
        }
        __syncthreads();
    }
}

// ---------------------------------------------------------------------------
// Filter spectra: 2 channels per block (Hermitian split), output FULL
// spectra in digit-reversed order for pointwise use in fftconv.
// ---------------------------------------------------------------------------
__global__ __launch_bounds__(256)
void filter_fft_packed(const float* __restrict__ hfiltT,
                       const float* __restrict__ a,
                       float2* __restrict__ wfh,
                       const float2* __restrict__ twd) {
    __shared__ float2 sd[PIDX(NFFT)];
    __shared__ float2 tw[1024];
    const int tid = threadIdx.x;
    const int d0 = blockIdx.x * 2;
    const int d1 = d0 + 1;
    for (int i = tid; i < 1024; i += 256) tw[i] = twd[i];
    const float ea = expf(a[0]);
    for (int t = tid; t < LEN; t += 256) {
        const float w = expf(-(float)t * ea);
        sd[PIDX(t)] = make_float2(hfiltT[(size_t)d0 * LEN + t] * w,
                                  hfiltT[(size_t)d1 * LEN + t] * w);
    }
    fft4096_dif_pad(sd, tw);
    for (int p = tid; p < NFFT; p += 256) {
        const int k  = rev4(p);
        const int k2 = (NFFT - k) & (NFFT - 1);
        const int p2 = rev4(k2);
        float2 X1 = sd[PIDX(p)];
        float2 X2 = sd[PIDX(p2)];
        wfh[(size_t)d0 * NFFT + p] =
            make_float2(0.5f * (X1.x + X2.x), 0.5f * (X1.y - X2.y));
        wfh[(size_t)d1 * NFFT + p] =
            make_float2(0.5f * (X1.y + X2.y), -0.5f * (X1.x - X2.x));
    }
}

// ---------------------------------------------------------------------------
// FFT convolution: two BATCHES packed per block (real filter => pointwise
// multiply valid in digit-reversed order).
// ---------------------------------------------------------------------------
__global__ __launch_bounds__(256)
void fftconv_packed(const float* __restrict__ lnzT,
                    const float2* __restrict__ wfh,
                    const float* __restrict__ hidT,
                    float* __restrict__ znewT,
                    const float2* __restrict__ twd) {
    __shared__ float2 sd[PIDX(NFFT)];
    __shared__ float2 tw[1024];
    const int tid = threadIdx.x;
    const int d  = blockIdx.x & (DIM - 1);
    const int bp = blockIdx.x >> 10;
    const int b0 = bp * 2;
    const int b1 = b0 + 1;
    for (int i = tid; i < 1024; i += 256) tw[i] = twd[i];
    const float* x0 = lnzT + ((size_t)b0 * DIM + d) * LEN;
    const float* x1 = lnzT + ((size_t)b1 * DIM + d) * LEN;
    for (int t = tid; t < LEN; t += 256)
        sd[PIDX(t)] = make_float2(x0[t], x1[t]);

    fft4096_dif_pad(sd, tw);

    const float2* F = wfh + (size_t)d * NFFT;
    for (int p = tid; p < NFFT; p += 256)
        sd[PIDX(p)] = cmul(sd[PIDX(p)], F[p]);

    fft4096_dit_inv(sd, tw);

    const float inv = 1.0f / (float)NFFT;
    float* o0 = znewT + ((size_t)b0 * DIM + d) * LEN;
    float* o1 = znewT + ((size_t)b1 * DIM + d) * LEN;
    const float* h = hidT + (size_t)d * LEN;
    for (int t = tid; t < LEN; t += 256) {
        float2 v = sd[PIDX(t)];
        const float hv = h[t];
        o0[t] = v.x * inv + hv;
        o1[t] = v.y * inv + hv;
    }
}

// ---------------------------------------------------------------------------
// LayerNorm kernels
// ---------------------------------------------------------------------------
__global__ void layernorm_rows(const float* __restrict__ x,
                               const float* __restrict__ gvec,
                               const float* __restrict__ bvec,
                               float* __restrict__ y) {
    const int row = blockIdx.x;
    const int tid = threadIdx.x;
    const float4 v = reinterpret_cast<const float4*>(x + (size_t)row * DIM)[tid];
    float s  = v.x + v.y + v.z + v.w;
    float s2 = v.x * v.x + v.y * v.y + v.z * v.z + v.w * v.w;
    __shared__ float rs[256], rs2[256];
    rs[tid] = s; rs2[tid] = s2;
    __syncthreads();
    for (int o = 128; o > 0; o >>= 1) {
        if (tid < o) { rs[tid] += rs[tid + o]; rs2[tid] += rs2[tid + o]; }
        __syncthreads();
    }
    const float mean = rs[0] * (1.0f / DIM);
    const float var  = rs2[0] * (1.0f / DIM) - mean * mean;
    const float rstd = rsqrtf(var + LN_EPS);
    const float4 gg = reinterpret_cast<const float4*>(gvec)[tid];
    const float4 bb = reinterpret_cast<const float4*>(bvec)[tid];
    float4 o;
    o.x = (v.x - mean) * rstd * gg.x + bb.x;
    o.y = (v.y - mean) * rstd * gg.y + bb.y;
    o.z = (v.z - mean) * rstd * gg.z + bb.z;
    o.w = (v.w - mean) * rstd * gg.w + bb.w;
    reinterpret_cast<float4*>(y + (size_t)row * DIM)[tid] = o;
}

__global__ void layernorm_rows_h(const float* __restrict__ x,
                                 const float* __restrict__ gvec,
                                 const float* __restrict__ bvec,
                                 __half* __restrict__ yh) {
    const int row = blockIdx.x;
    const int tid = threadIdx.x;
    const float4 v = reinterpret_cast<const float4*>(x + (size_t)row * DIM)[tid];
    float s  = v.x + v.y + v.z + v.w;
    float s2 = v.x * v.x + v.y * v.y + v.z * v.z + v.w * v.w;
    __shared__ float rs[256], rs2[256];
    rs[tid] = s; rs2[tid] = s2;
    __syncthreads();
    for (int o = 128; o > 0; o >>= 1) {
        if (tid < o) { rs[tid] += rs[tid + o]; rs2[tid] += rs2[tid + o]; }
        __syncthreads();
    }
    const float mean = rs[0] * (1.0f / DIM);
    const float var  = rs2[0] * (1.0f / DIM) - mean * mean;
    const float rstd = rsqrtf(var + LN_EPS);
    const float4 gg = reinterpret_cast<const float4*>(gvec)[tid];
    const float4 bb = reinterpret_cast<const float4*>(bvec)[tid];
    __half h[4];
    h[0] = __float2half_rn((v.x - mean) * rstd * gg.x + bb.x);
    h[1] = __float2half_rn((v.y - mean) * rstd * gg.y + bb.y);
    h[2] = __float2half_rn((v.z - mean) * rstd * gg.z + bb.z);
    h[3] = __float2half_rn((v.w - mean) * rstd * gg.w + bb.w);
    *reinterpret_cast<ushort4*>(yh + (size_t)row * DIM + tid * 4) =
        *reinterpret_cast<ushort4*>(h);
}

// ---------------------------------------------------------------------------
// Launch: fork two independent front-half chains onto captured side streams.
// ---------------------------------------------------------------------------
extern "C" void kernel_launch(void* const* d_in, const int* in_sizes, int n_in,
                              void* d_out, int out_size) {
    const float* z      = (const float*)d_in[0];
    const float* pos    = (const float*)d_in[1];
    const float* a      = (const float*)d_in[2];
    const float* hidden = (const float*)d_in[3];
    const float* ln_g   = (const float*)d_in[4];
    const float* ln_b   = (const float*)d_in[5];
    const float* wp1    = (const float*)d_in[6];
    const float* bp1    = (const float*)d_in[7];
    const float* wp2    = (const float*)d_in[8];
    const float* bp2    = (const float*)d_in[9];
    const float* w1     = (const float*)d_in[10];
    const float* b1     = (const float*)d_in[11];
    const float* w2     = (const float*)d_in[12];
    const float* b2     = (const float*)d_in[13];
    float* out = (float*)d_out;

    float *lnz, *lnzT, *hfilt, *hfiltT, *hidT, *znewT, *znew;
    float2 *wfh, *twd;
    __half *X16, *H16, *pos16, *wp1t, *wp2t, *w1t, *w2t;
    cudaGetSymbolAddress((void**)&lnz,    g_lnz);
    cudaGetSymbolAddress((void**)&lnzT,   g_lnzT);
    cudaGetSymbolAddress((void**)&hfilt,  g_hfilt);
    cudaGetSymbolAddress((void**)&hfiltT, g_hfiltT);
    cudaGetSymbolAddress((void**)&hidT,   g_hidT);
    cudaGetSymbolAddress((void**)&wfh,    g_wfh);
    cudaGetSymbolAddress((void**)&twd,    g_twd);
    cudaGetSymbolAddress((void**)&znewT,  g_znewT);
    cudaGetSymbolAddress((void**)&znew,   g_znew);
    cudaGetSymbolAddress((void**)&X16,    g_X16);
    cudaGetSymbolAddress((void**)&H16,    g_H16);
    cudaGetSymbolAddress((void**)&pos16,  g_pos16);
    cudaGetSymbolAddress((void**)&wp1t,   g_wp1t);
    cudaGetSymbolAddress((void**)&wp2t,   g_wp2t);
    cudaGetSymbolAddress((void**)&w1t,    g_w1t);
    cudaGetSymbolAddress((void**)&w2t,    g_w2t);

    cudaFuncSetAttribute(gemm_mma<1, true,  false>,
                         cudaFuncAttributeMaxDynamicSharedMemorySize, GEMM_SMEM);
    cudaFuncSetAttribute(gemm_mma<0, false, false>,
                         cudaFuncAttributeMaxDynamicSharedMemorySize, GEMM_SMEM);
    cudaFuncSetAttribute(gemm_mma<0, false, true>,
                         cudaFuncAttributeMaxDynamicSharedMemorySize, GEMM_SMEM);

    cudaStream_t s1, s2;
    cudaStreamCreateWithFlags(&s1, cudaStreamNonBlocking);
    cudaStreamCreateWithFlags(&s2, cudaStreamNonBlocking);
    cudaEvent_t e0, e1, e2;
    cudaEventCreateWithFlags(&e0, cudaEventDisableTiming);
    cudaEventCreateWithFlags(&e1, cudaEventDisableTiming);
    cudaEventCreateWithFlags(&e2, cudaEventDisableTiming);

    // root work on the (captured) default stream, then fork
    init_twd<<<4, 256>>>(twd);
    cudaEventRecord(e0, 0);
    cudaStreamWaitEvent(s1, e0, 0);
    cudaStreamWaitEvent(s2, e0, 0);

    // ── chain A (s1): filter FFN -> filter spectra ──
    transpose_h<<<dim3(DFF / 32, DIM / 32), dim3(32, 8), 0, s1>>>(wp1, wp1t, DIM, DFF);
    transpose_h<<<dim3(DIM / 32, DFF / 32), dim3(32, 8), 0, s1>>>(wp2, wp2t, DFF, DIM);
    cvt_f32_h<<<(LEN * DIM + 255) / 256, 256, 0, s1>>>(pos, pos16, LEN * DIM);
    gemm_mma<1, true, false><<<dim3(DFF / GBN, LEN / GBM), GTHREADS, GEMM_SMEM, s1>>>(
        pos16, wp1t, bp1, nullptr, nullptr, H16, LEN, DFF, DIM);
    gemm_mma<0, false, false><<<dim3(DIM / GBN, LEN / GBM), GTHREADS, GEMM_SMEM, s1>>>(
        H16, wp2t, bp2, nullptr, hfilt, nullptr, LEN, DIM, DFF);
    transpose32f<<<dim3(DIM / 32, LEN / 32, 1), dim3(32, 8), 0, s1>>>(hfilt, hfiltT, LEN, DIM);
    filter_fft_packed<<<DIM / 2, 256, 0, s1>>>(hfiltT, a, wfh, twd);

    // ── chain B (s2): LN(z) + transposes + main-weight prep ──
    layernorm_rows<<<BATCH * LEN, 256, 0, s2>>>(z, ln_g, ln_b, lnz);
    transpose32f<<<dim3(DIM / 32, LEN / 32, BATCH), dim3(32, 8), 0, s2>>>(lnz, lnzT, LEN, DIM);
    transpose32f<<<dim3(DIM / 32, LEN / 32, 1), dim3(32, 8), 0, s2>>>(hidden, hidT, LEN, DIM);
    transpose_h<<<dim3(DFF / 32, DIM / 32), dim3(32, 8), 0, s2>>>(w1, w1t, DIM, DFF);
    transpose_h<<<dim3(DIM / 32, DFF / 32), dim3(32, 8), 0, s2>>>(w2, w2t, DFF, DIM);

    // join
    cudaEventRecord(e1, s1);
    cudaEventRecord(e2, s2);
    cudaStreamWaitEvent(0, e1, 0);
    cudaStreamWaitEvent(0, e2, 0);

    // ── tail (default stream, serial) ──
    fftconv_packed<<<(BATCH / 2) * DIM, 256>>>(lnzT, wfh, hidT, znewT, twd);
    transpose32f<<<dim3(LEN / 32, DIM / 32, BATCH), dim3(32, 8)>>>(znewT, znew, DIM, LEN);
    layernorm_rows_h<<<BATCH * LEN, 256>>>(znew, ln_g, ln_b, X16);
    gemm_mma<1, true, false><<<dim3(DFF / GBN, (BATCH * LEN) / GBM), GTHREADS, GEMM_SMEM>>>(
        X16, w1t, b1, nullptr, nullptr, H16, BATCH * LEN, DFF, DIM);
    gemm_mma<0, false, true><<<dim3(DIM / GBN, (BATCH * LEN) / GBM), GTHREADS, GEMM_SMEM>>>(
        H16, w2t, b2, znew, out, nullptr, BATCH * LEN, DIM, DFF);

    // cleanup — only when NOT capturing (destroying capture-participating
    // streams/events mid-capture invalidates the capture)
    cudaStreamCaptureStatus cs = cudaStreamCaptureStatusNone;
    cudaStreamIsCapturing(0, &cs);
    if (cs == cudaStreamCaptureStatusNone) {
        cudaStreamDestroy(s1);
        cudaStreamDestroy(s2);
        cudaEventDestroy(e0);
        cudaEventDestroy(e1);
        cudaEventDestroy(e2);
    }
}

// round 13
// speedup vs baseline: 2.4187x; 1.0203x over previous
#include <cuda_runtime.h>
#include <cuda_fp16.h>
#include <cuda_bf16.h>
#include <math.h>
#include <cstdint>

// Problem constants
#define BATCH 8
#define LEN   2048
#define DIM   1024
#define DFF   4096
#define NFFT  4096
#define LN_EPS 1e-5f

// ---------------------------------------------------------------------------
// Static device scratch (no allocation allowed)
// ---------------------------------------------------------------------------
__device__ float  g_lnz  [BATCH * LEN * DIM];
__device__ float  g_lnzT [BATCH * DIM * LEN];
__device__ float  g_hfilt[LEN * DIM];
__device__ float  g_hfiltT[DIM * LEN];
__device__ float  g_hidT [DIM * LEN];
__device__ float2 g_wfh  [DIM * NFFT];            // full spectra, digit-reversed, pre-scaled by 1/N
__device__ float2 g_twd  [1024];
__device__ float  g_znewT[BATCH * DIM * LEN];
__device__ __half g_znew16[BATCH * LEN * DIM];    // conv+hidden residual, fp16 row-major
__device__ __half g_X16 [BATCH * LEN * DIM];      // LN(znew) fp16
__device__ __half g_H16 [BATCH * LEN * DFF];      // FFN hidden fp16
__device__ __half g_pos16[LEN * DIM];
// transposed fp16 weights: [N, K] layout
__device__ __half g_wp1t[DFF * DIM];
__device__ __half g_wp2t[DIM * DFF];
__device__ __half g_w1t [DFF * DIM];
__device__ __half g_w2t [DIM * DFF];

// ---------------------------------------------------------------------------
// PTX wrappers (baseline sm_80+ only)
// ---------------------------------------------------------------------------
__device__ __forceinline__ uint32_t smem_u32(const void* p) {
    uint32_t a;
    asm("{ .reg .u64 t; cvta.to.shared.u64 t, %1; cvt.u32.u64 %0, t; }"
        : "=r"(a) : "l"(p));
    return a;
}
__device__ __forceinline__ void cpasync16(uint32_t s, const void* g) {
    asm volatile("cp.async.cg.shared.global [%0], [%1], 16;"
                 :: "r"(s), "l"(g) : "memory");
}
__device__ __forceinline__ void cp_commit() {
    asm volatile("cp.async.commit_group;" ::: "memory");
}
template <int N>
__device__ __forceinline__ void cp_wait() {
    asm volatile("cp.async.wait_group %0;" :: "n"(N) : "memory");
}
__device__ __forceinline__ void ldm_x4(uint32_t& r0, uint32_t& r1,
                                       uint32_t& r2, uint32_t& r3, uint32_t a) {
    asm volatile("ldmatrix.sync.aligned.m8n8.x4.shared.b16 {%0,%1,%2,%3}, [%4];"
                 : "=r"(r0), "=r"(r1), "=r"(r2), "=r"(r3) : "r"(a));
}
__device__ __forceinline__ void ldm_x2(uint32_t& r0, uint32_t& r1, uint32_t a) {
    asm volatile("ldmatrix.sync.aligned.m8n8.x2.shared.b16 {%0,%1}, [%2];"
                 : "=r"(r0), "=r"(r1) : "r"(a));
}
__device__ __forceinline__ void mma_f16(float4& d, const uint32_t* a,
                                        uint32_t b0, uint32_t b1) {
    asm volatile(
        "mma.sync.aligned.m16n8k16.row.col.f32.f16.f16.f32 "
        "{%0,%1,%2,%3}, {%4,%5,%6,%7}, {%8,%9}, {%0,%1,%2,%3};"
        : "+f"(d.x), "+f"(d.y), "+f"(d.z), "+f"(d.w)
        : "r"(a[0]), "r"(a[1]), "r"(a[2]), "r"(a[3]), "r"(b0), "r"(b1));
}

// ---------------------------------------------------------------------------
// HMMA fp16 GEMM (unchanged from R10/R11): block 128x128, BK=32, 4 warps,
// warp tile 64x64, 4-stage cp.async, one __syncthreads per k-tile.
// HAS_ADD residual is fp16.
// ---------------------------------------------------------------------------
#define GBM 128
#define GBN 128
#define GBK 32
#define TPAD 40
#define TILE_B (128 * TPAD * 2)
#define STAGE_B (2 * TILE_B)
#define NSTAGE 4
#define GEMM_SMEM (NSTAGE * STAGE_B)
#define GTHREADS 128

template <int ACT, bool H_OUT, bool HAS_ADD>
__global__ __launch_bounds__(GTHREADS)
void gemm_mma(const __half* __restrict__ A, const __half* __restrict__ B,
              const float* __restrict__ bias, const __half* __restrict__ add,
              float* __restrict__ Cf, __half* __restrict__ Ch,
              int M, int N, int K) {
    extern __shared__ char smem[];
    const uint32_t sbase = smem_u32(smem);
    const int tid  = threadIdx.x;
    const int lane = tid & 31;
    const int wid  = tid >> 5;
    const int wm   = wid & 1;
    const int wn   = wid >> 1;
    const int bm = blockIdx.y * GBM;
    const int bn = blockIdx.x * GBN;

    auto issue_loads = [&](int stage, int k0) {
        const uint32_t sb = sbase + stage * STAGE_B;
#pragma unroll
        for (int p = 0; p < 4; p++) {
            const int idx = p * GTHREADS + tid;
            const int row = idx >> 2;
            const int c0  = idx & 3;
            const uint32_t so = (uint32_t)(row * 80 + c0 * 16);
            const size_t kk = (size_t)k0 + c0 * 8;
            cpasync16(sb + so,          A + (size_t)(bm + row) * K + kk);
            cpasync16(sb + TILE_B + so, B + (size_t)(bn + row) * K + kk);
        }
        cp_commit();
    };

    float4 acc[4][8];
#pragma unroll
    for (int i = 0; i < 4; i++)
#pragma unroll
        for (int j = 0; j < 8; j++) acc[i][j] = make_float4(0.f, 0.f, 0.f, 0.f);

    const int a_row = (lane & 7) + ((lane >> 3) & 1) * 8;
    const int a_kc  = ((lane >> 4) & 1) * 8;
    const int b_row = lane & 7;
    const int b_kc  = ((lane >> 3) & 1) * 8;

    const int NT = K / GBK;
    issue_loads(0, 0);
    issue_loads(1, GBK);

    for (int kt = 0; kt < NT; kt++) {
        cp_wait<1>();
        __syncthreads();
        if (kt + 2 < NT)
            issue_loads((kt + 2) % NSTAGE, (kt + 2) * GBK);

        const uint32_t st = sbase + (kt % NSTAGE) * STAGE_B;
        const uint32_t As = st;
        const uint32_t Bs = st + TILE_B;

#pragma unroll
        for (int k16 = 0; k16 < 2; k16++) {
            uint32_t ah[4][4];
#pragma unroll
            for (int i = 0; i < 4; i++) {
                const uint32_t ao =
                    (uint32_t)((wm * 64 + i * 16 + a_row) * 80 +
                               (k16 * 16 + a_kc) * 2);
                ldm_x4(ah[i][0], ah[i][1], ah[i][2], ah[i][3], As + ao);
            }
#pragma unroll
            for (int j = 0; j < 8; j++) {
                const uint32_t bo =
                    (uint32_t)((wn * 64 + j * 8 + b_row) * 80 +
                               (k16 * 16 + b_kc) * 2);
                uint32_t b0, b1;
                ldm_x2(b0, b1, Bs + bo);
#pragma unroll
                for (int i = 0; i < 4; i++)
                    mma_f16(acc[i][j], ah[i], b0, b1);
            }
        }
    }

    const int qr = lane >> 2;
    const int qc = (lane & 3) * 2;
#pragma unroll
    for (int i = 0; i < 4; i++) {
#pragma unroll
        for (int j = 0; j < 8; j++) {
            const int gr0 = bm + wm * 64 + i * 16 + qr;
            const int gc  = bn + wn * 64 + j * 8 + qc;
            const float b0 = bias[gc];
            const float b1 = bias[gc + 1];
            float v00 = acc[i][j].x + b0, v01 = acc[i][j].y + b1;
            float v10 = acc[i][j].z + b0, v11 = acc[i][j].w + b1;
            if (ACT == 1) {
                v00 = v00 / (1.0f + expf(-v00));
                v01 = v01 / (1.0f + expf(-v01));
                v10 = v10 / (1.0f + expf(-v10));
                v11 = v11 / (1.0f + expf(-v11));
            }
            if (HAS_ADD) {
                __half2 a0 = *reinterpret_cast<const __half2*>(add + (size_t)gr0 * N + gc);
                __half2 a1 = *reinterpret_cast<const __half2*>(add + (size_t)(gr0 + 8) * N + gc);
                v00 += __half2float(a0.x);
                v01 += __half2float(a0.y);
                v10 += __half2float(a1.x);
                v11 += __half2float(a1.y);
            }
            if (H_OUT) {
                *reinterpret_cast<__half2*>(Ch + (size_t)gr0 * N + gc) =
                    __halves2half2(__float2half_rn(v00), __float2half_rn(v01));
                *reinterpret_cast<__half2*>(Ch + (size_t)(gr0 + 8) * N + gc) =
                    __halves2half2(__float2half_rn(v10), __float2half_rn(v11));
            } else {
                *reinterpret_cast<float2*>(Cf + (size_t)gr0 * N + gc) =
                    make_float2(v00, v01);
                *reinterpret_cast<float2*>(Cf + (size_t)(gr0 + 8) * N + gc) =
                    make_float2(v10, v11);
            }
        }
    }
}

// ---------------------------------------------------------------------------
// Prep kernels
// ---------------------------------------------------------------------------
__global__ void transpose_h(const float* __restrict__ W,
                            __half* __restrict__ T, int K, int N) {
    __shared__ float t[32][33];
    const int n0 = blockIdx.x * 32, k0 = blockIdx.y * 32;
    const int tx = threadIdx.x, ty = threadIdx.y;
#pragma unroll
    for (int dy = 0; dy < 32; dy += 8)
        t[ty + dy][tx] = W[(size_t)(k0 + ty + dy) * N + n0 + tx];
    __syncthreads();
#pragma unroll
    for (int dy = 0; dy < 32; dy += 8) {
        const int n = n0 + ty + dy, k = k0 + tx;
        T[(size_t)n * K + k] = __float2half_rn(t[tx][ty + dy]);
    }
}

__global__ void cvt_f32_h(const float* __restrict__ x, __half* __restrict__ h, int n) {
    int i = blockIdx.x * 256 + threadIdx.x;
    if (i < n) h[i] = __float2half_rn(x[i]);
}

__global__ void transpose32f(const float* __restrict__ in, float* __restrict__ out,
                             int R, int C) {
    __shared__ float t[32][33];
    const size_t boff = (size_t)blockIdx.z * R * C;
    const float* ip = in + boff;
    float* op = out + boff;
    const int r0 = blockIdx.y * 32, c0 = blockIdx.x * 32;
    const int tx = threadIdx.x, ty = threadIdx.y;
#pragma unroll
    for (int dy = 0; dy < 32; dy += 8)
        t[ty + dy][tx] = ip[(size_t)(r0 + ty + dy) * C + c0 + tx];
    __syncthreads();
#pragma unroll
    for (int dy = 0; dy < 32; dy += 8)
        op[(size_t)(c0 + ty + dy) * R + r0 + tx] = t[tx][ty + dy];
}

// float in -> fp16 out transpose (for znewT -> znew16)
__global__ void transpose32f_h(const float* __restrict__ in, __half* __restrict__ out,
                               int R, int C) {
    __shared__ float t[32][33];
    const float* ip = in + (size_t)blockIdx.z * R * C;
    __half* op = out + (size_t)blockIdx.z * R * C;
    const int r0 = blockIdx.y * 32, c0 = blockIdx.x * 32;
    const int tx = threadIdx.x, ty = threadIdx.y;
#pragma unroll
    for (int dy = 0; dy < 32; dy += 8)
        t[ty + dy][tx] = ip[(size_t)(r0 + ty + dy) * C + c0 + tx];
    __syncthreads();
#pragma unroll
    for (int dy = 0; dy < 32; dy += 8)
        op[(size_t)(c0 + ty + dy) * R + r0 + tx] = __float2half_rn(t[tx][ty + dy]);
}

__global__ void init_twd(float2* __restrict__ twd) {
    int k = blockIdx.x * 256 + threadIdx.x;
    if (k < 1024) {
        double s, c;
        sincos(-6.283185307179586476925286766559 * (double)k / 4096.0, &s, &c);
        twd[k] = make_float2((float)c, (float)s);
    }
}

// ---------------------------------------------------------------------------
// Radix-4 FFT, 4096 points, 256 threads, twiddles from gmem (L1/L2 hot).
// DIF forward (natural -> digit-rev, zero-padded upper half never read).
// DIT inverse with the pointwise filter multiply fused into stage 0.
// ---------------------------------------------------------------------------
#define PIDX(i) ((i) + ((i) >> 4))

__device__ __forceinline__ float2 cmul(float2 a, float2 b) {
    return make_float2(a.x * b.x - a.y * b.y, a.x * b.y + a.y * b.x);
}
__device__ __forceinline__ int rev4(int p) {
    int b = __brev(p) >> 20;
    return ((b & 0x555) << 1) | ((b >> 1) & 0x555);
}

__device__ void fft4096_dif_pad(float2* sm, const float2* __restrict__ tw) {
    const int tid = threadIdx.x;
    __syncthreads();
#pragma unroll
    for (int u = 0; u < 4; u++) {
        const int j = tid + u * 256;
        float2 x0 = sm[PIDX(j)];
        float2 x1 = sm[PIDX(j + 1024)];
        float2 w1 = __ldg(&tw[j]);
        float2 w2 = cmul(w1, w1);
        float2 w3 = cmul(w2, w1);
        float2 y0 = make_float2(x0.x + x1.x, x0.y + x1.y);
        float2 y1 = make_float2(x0.x + x1.y, x0.y - x1.x);
        float2 y2 = make_float2(x0.x - x1.x, x0.y - x1.y);
        float2 y3 = make_float2(x0.x - x1.y, x0.y + x1.x);
        sm[PIDX(j)]        = y0;
        sm[PIDX(j + 1024)] = cmul(y1, w1);
        sm[PIDX(j + 2048)] = cmul(y2, w2);
        sm[PIDX(j + 3072)] = cmul(y3, w3);
    }
    __syncthreads();
#pragma unroll
    for (int len = 1024; len >= 4; len >>= 2) {
        const int q = len >> 2;
        const int S = NFFT / len;
#pragma unroll
        for (int u = 0; u < 4; u++) {
            const int bf = tid + u * 256;
            const int g  = bf / q;
            const int j  = bf - g * q;
            const int base = g * len + j;
            float2 x0 = sm[PIDX(base)];
            float2 x1 = sm[PIDX(base + q)];
            float2 x2 = sm[PIDX(base + 2 * q)];
            float2 x3 = sm[PIDX(base + 3 * q)];
            float2 t0 = make_float2(x0.x + x2.x, x0.y + x2.y);
            float2 t1 = make_float2(x0.x - x2.x, x0.y - x2.y);
            float2 t2 = make_float2(x1.x + x3.x, x1.y + x3.y);
            float2 t3 = make_float2(x1.x - x3.x, x1.y - x3.y);
            float2 y0 = make_float2(t0.x + t2.x, t0.y + t2.y);
            float2 y2 = make_float2(t0.x - t2.x, t0.y - t2.y);
            float2 y1 = make_float2(t1.x + t3.y, t1.y - t3.x);
            float2 y3 = make_float2(t1.x - t3.y, t1.y + t3.x);
            float2 w1 = __ldg(&tw[j * S]);
            float2 w2 = cmul(w1, w1);
            float2 w3 = cmul(w2, w1);
            sm[PIDX(base)]         = y0;
            sm[PIDX(base + q)]     = cmul(y1, w1);
            sm[PIDX(base + 2 * q)] = cmul(y2, w2);
            sm[PIDX(base + 3 * q)] = cmul(y3, w3);
        }
        __syncthreads();
    }
}

// Inverse DIT; stage 0 fused with pointwise multiply by F (digit-rev indexed).
// If F == nullptr, plain inverse.
__device__ void fft4096_dit_inv_mul(float2* sm, const float2* __restrict__ tw,
                                    const float2* __restrict__ F) {
    const int tid = threadIdx.x;
    __syncthreads();
    // stage 0: len=4, q=1, j=0, twiddles = 1. Multiply-on-load by F.
#pragma unroll
    for (int u = 0; u < 4; u++) {
        const int g = tid + u * 256;        // 0..1023
        const int base = g * 4;
        float2 x0 = sm[PIDX(base)];
        float2 x1 = sm[PIDX(base + 1)];
        float2 x2 = sm[PIDX(base + 2)];
        float2 x3 = sm[PIDX(base + 3)];
        if (F) {
            x0 = cmul(x0, __ldg(&F[base]));
            x1 = cmul(x1, __ldg(&F[base + 1]));
            x2 = cmul(x2, __ldg(&F[base + 2]));
            x3 = cmul(x3, __ldg(&F[base + 3]));
        }
        float2 t0 = make_float2(x0.x + x2.x, x0.y + x2.y);
        float2 t1 = make_float2(x0.x - x2.x, x0.y - x2.y);
        float2 t2 = make_float2(x1.x + x3.x, x1.y + x3.y);
        float2 t3 = make_float2(x1.x - x3.x, x1.y - x3.y);
        sm[PIDX(base)]     = make_float2(t0.x + t2.x, t0.y + t2.y);
        sm[PIDX(base + 2)] = make_float2(t0.x - t2.x, t0.y - t2.y);
        sm[PIDX(base + 1)] = make_float2(t1.x - t3.y, t1.y + t3.x);
        sm[PIDX(base + 3)] = make_float2(t1.x + t3.y, t1.y - t3.x);
    }
    __syncthreads();
#pragma unroll
    for (int st = 1; st < 6; st++) {
        const int len = 4 << (2 * st);
        const int q   = len >> 2;
        const int S   = NFFT / len;
#pragma unroll
        for (int u = 0; u < 4; u++) {
            const int bf = tid + u * 256;
            const int g  = bf / q;
            const int j  = bf - g * q;
            const int base = g * len + j;
            float2 x0 = sm[PIDX(base)];
            float2 x1 = sm[PIDX(base + q)];
            float2 x2 = sm[PIDX(base + 2 * q)];
            float2 x3 = sm[PIDX(base + 3 * q)];
            float2 w1 = __ldg(&tw[j * S]);
            w1.y = -w1.y;
            float2 w2 = cmul(w1, w1);
            float2 w3 = cmul(w1, w2);
            x1 = cmul(x1, w1);
            x2 = cmul(x2, w2);
            x3 = cmul(x3, w3);
            float2 t0 = make_float2(x0.x + x2.x, x0.y + x2.y);
            float2 t1 = make_float2(x0.x - x2.x, x0.y - x2.y);
            float2 t2 = make_float2(x1.x + x3.x, x1.y + x3.y);
            float2 t3 = make_float2(x1.x - x3.x, x1.y - x3.y);
            sm[PIDX(base)]         = make_float2(t0.x + t2.x, t0.y + t2.y);
            sm[PIDX(base + 2 * q)] = make_float2(t0.x - t2.x, t0.y - t2.y);
            sm[PIDX(base + q)]     = make_float2(t1.x - t3.y, t1.y + t3.x);
            sm[PIDX(base + 3 * q)] = make_float2(t1.x + t3.y, t1.y - t3.x);
        }
        __syncthreads();
    }
}

// ---------------------------------------------------------------------------
// Filter spectra: 2 channels per block (Hermitian split), full digit-reversed
// spectra pre-scaled by 1/NFFT.
// ---------------------------------------------------------------------------
__global__ __launch_bounds__(256)
void filter_fft_packed(const float* __restrict__ hfiltT,
                       const float* __restrict__ a,
                       float2* __restrict__ wfh,
                       const float2* __restrict__ twd) {
    __shared__ float2 sd[PIDX(NFFT)];
    const int tid = threadIdx.x;
    const int d0 = blockIdx.x * 2;
    const int d1 = d0 + 1;
    const float ea = expf(a[0]);
    for (int t = tid; t < LEN; t += 256) {
        const float w = expf(-(float)t * ea);
        sd[PIDX(t)] = make_float2(hfiltT[(size_t)d0 * LEN + t] * w,
                                  hfiltT[(size_t)d1 * LEN + t] * w);
    }
    fft4096_dif_pad(sd, twd);
    const float inv = 1.0f / (float)NFFT;
    for (int p = tid; p < NFFT; p += 256) {
        const int k  = rev4(p);
        const int k2 = (NFFT - k) & (NFFT - 1);
        const int p2 = rev4(k2);
        float2 X1 = sd[PIDX(p)];
        float2 X2 = sd[PIDX(p2)];
        wfh[(size_t)d0 * NFFT + p] =
            make_float2(0.5f * inv * (X1.x + X2.x), 0.5f * inv * (X1.y - X2.y));
        wfh[(size_t)d1 * NFFT + p] =
            make_float2(0.5f * inv * (X1.y + X2.y), -0.5f * inv * (X1.x - X2.x));
    }
}

// ---------------------------------------------------------------------------
// FFT convolution: two BATCHES packed per block; multiply fused into DIT.
// ---------------------------------------------------------------------------
__global__ __launch_bounds__(256)
void fftconv_packed(const float* __restrict__ lnzT,
                    const float2* __restrict__ wfh,
                    const float* __restrict__ hidT,
                    float* __restrict__ znewT,
                    const float2* __restrict__ twd) {
    __shared__ float2 sd[PIDX(NFFT)];
    const int tid = threadIdx.x;
    const int d  = blockIdx.x & (DIM - 1);
    const int bp = blockIdx.x >> 10;
    const int b0 = bp * 2;
    const int b1 = b0 + 1;
    const float* x0 = lnzT + ((size_t)b0 * DIM + d) * LEN;
    const float* x1 = lnzT + ((size_t)b1 * DIM + d) * LEN;
    for (int t = tid; t < LEN; t += 256)
        sd[PIDX(t)] = make_float2(x0[t], x1[t]);

    fft4096_dif_pad(sd, twd);
    fft4096_dit_inv_mul(sd, twd, wfh + (size_t)d * NFFT);

    float* o0 = znewT + ((size_t)b0 * DIM + d) * LEN;
    float* o1 = znewT + ((size_t)b1 * DIM + d) * LEN;
    const float* h = hidT + (size_t)d * LEN;
    for (int t = tid; t < LEN; t += 256) {
        float2 v = sd[PIDX(t)];
        const float hv = h[t];
        o0[t] = v.x + hv;
        o1[t] = v.y + hv;
    }
}

// ---------------------------------------------------------------------------
// LayerNorm kernels
// ---------------------------------------------------------------------------
__global__ void layernorm_rows(const float* __restrict__ x,
                               const float* __restrict__ gvec,
                               const float* __restrict__ bvec,
                               float* __restrict__ y) {
    const int row = blockIdx.x;
    const int tid = threadIdx.x;
    const float4 v = reinterpret_cast<const float4*>(x + (size_t)row * DIM)[tid];
    float s  = v.x + v.y + v.z + v.w;
    float s2 = v.x * v.x + v.y * v.y + v.z * v.z + v.w * v.w;
    __shared__ float rs[256], rs2[256];
    rs[tid] = s; rs2[tid] = s2;
    __syncthreads();
    for (int o = 128; o > 0; o >>= 1) {
        if (tid < o) { rs[tid] += rs[tid + o]; rs2[tid] += rs2[tid + o]; }
        __syncthreads();
    }
    const float mean = rs[0] * (1.0f / DIM);
    const float var  = rs2[0] * (1.0f / DIM) - mean * mean;
    const float rstd = rsqrtf(var + LN_EPS);
    const float4 gg = reinterpret_cast<const float4*>(gvec)[tid];
    const float4 bb = reinterpret_cast<const float4*>(bvec)[tid];
    float4 o;
    o.x = (v.x - mean) * rstd * gg.x + bb.x;
    o.y = (v.y - mean) * rstd * gg.y + bb.y;
    o.z = (v.z - mean) * rstd * gg.z + bb.z;
    o.w = (v.w - mean) * rstd * gg.w + bb.w;
    reinterpret_cast<float4*>(y + (size_t)row * DIM)[tid] = o;
}

// fp16 input -> fp16 output LN
__global__ void layernorm_rows_hh(const __half* __restrict__ x,
                                  const float* __restrict__ gvec,
                                  const float* __restrict__ bvec,
                                  __half* __restrict__ yh) {
    const int row = blockIdx.x;
    const int tid = threadIdx.x;
    const ushort4 raw = reinterpret_cast<const ushort4*>(x + (size_t)row * DIM)[tid];
    const __half* hv = reinterpret_cast<const __half*>(&raw);
    float v[4];
#pragma unroll
    for (int j = 0; j < 4; j++) v[j] = __half2float(hv[j]);
    float s  = v[0] + v[1] + v[2] + v[3];
    float s2 = v[0] * v[0] + v[1] * v[1] + v[2] * v[2] + v[3] * v[3];
    __shared__ float rs[256], rs2[256];
    rs[tid] = s; rs2[tid] = s2;
    __syncthreads();
    for (int o = 128; o > 0; o >>= 1) {
        if (tid < o) { rs[tid] += rs[tid + o]; rs2[tid] += rs2[tid + o]; }
        __syncthreads();
    }
    const float mean = rs[0] * (1.0f / DIM);
    const float var  = rs2[0] * (1.0f / DIM) - mean * mean;
    const float rstd = rsqrtf(var + LN_EPS);
    const float4 gg = reinterpret_cast<const float4*>(gvec)[tid];
    const float4 bb = reinterpret_cast<const float4*>(bvec)[tid];
    __half h[4];
    h[0] = __float2half_rn((v[0] - mean) * rstd * gg.x + bb.x);
    h[1] = __float2half_rn((v[1] - mean) * rstd * gg.y + bb.y);
    h[2] = __float2half_rn((v[2] - mean) * rstd * gg.z + bb.z);
    h[3] = __float2half_rn((v[3] - mean) * rstd * gg.w + bb.w);
    *reinterpret_cast<ushort4*>(yh + (size_t)row * DIM + tid * 4) =
        *reinterpret_cast<ushort4*>(h);
}

// ---------------------------------------------------------------------------
// Launch: fork two independent front-half chains onto captured side streams.
// ---------------------------------------------------------------------------
extern "C" void kernel_launch(void* const* d_in, const int* in_sizes, int n_in,
                              void* d_out, int out_size) {
    const float* z      = (const float*)d_in[0];
    const float* pos    = (const float*)d_in[1];
    const float* a      = (const float*)d_in[2];
    const float* hidden = (const float*)d_in[3];
    const float* ln_g   = (const float*)d_in[4];
    const float* ln_b   = (const float*)d_in[5];
    const float* wp1    = (const float*)d_in[6];
    const float* bp1    = (const float*)d_in[7];
    const float* wp2    = (const float*)d_in[8];
    const float* bp2    = (const float*)d_in[9];
    const float* w1     = (const float*)d_in[10];
    const float* b1     = (const float*)d_in[11];
    const float* w2     = (const float*)d_in[12];
    const float* b2     = (const float*)d_in[13];
    float* out = (float*)d_out;

    float *lnz, *lnzT, *hfilt, *hfiltT, *hidT, *znewT;
    float2 *wfh, *twd;
    __half *znew16, *X16, *H16, *pos16, *wp1t, *wp2t, *w1t, *w2t;
    cudaGetSymbolAddress((void**)&lnz,    g_lnz);
    cudaGetSymbolAddress((void**)&lnzT,   g_lnzT);
    cudaGetSymbolAddress((void**)&hfilt,  g_hfilt);
    cudaGetSymbolAddress((void**)&hfiltT, g_hfiltT);
    cudaGetSymbolAddress((void**)&hidT,   g_hidT);
    cudaGetSymbolAddress((void**)&wfh,    g_wfh);
    cudaGetSymbolAddress((void**)&twd,    g_twd);
    cudaGetSymbolAddress((void**)&znewT,  g_znewT);
    cudaGetSymbolAddress((void**)&znew16, g_znew16);
    cudaGetSymbolAddress((void**)&X16,    g_X16);
    cudaGetSymbolAddress((void**)&H16,    g_H16);
    cudaGetSymbolAddress((void**)&pos16,  g_pos16);
    cudaGetSymbolAddress((void**)&wp1t,   g_wp1t);
    cudaGetSymbolAddress((void**)&wp2t,   g_wp2t);
    cudaGetSymbolAddress((void**)&w1t,    g_w1t);
    cudaGetSymbolAddress((void**)&w2t,    g_w2t);

    cudaFuncSetAttribute(gemm_mma<1, true,  false>,
                         cudaFuncAttributeMaxDynamicSharedMemorySize, GEMM_SMEM);
    cudaFuncSetAttribute(gemm_mma<0, false, false>,
                         cudaFuncAttributeMaxDynamicSharedMemorySize, GEMM_SMEM);
    cudaFuncSetAttribute(gemm_mma<0, false, true>,
                         cudaFuncAttributeMaxDynamicSharedMemorySize, GEMM_SMEM);

    cudaStream_t s1, s2;
    cudaStreamCreateWithFlags(&s1, cudaStreamNonBlocking);
    cudaStreamCreateWithFlags(&s2, cudaStreamNonBlocking);
    cudaEvent_t e0, e1, e2;
    cudaEventCreateWithFlags(&e0, cudaEventDisableTiming);
    cudaEventCreateWithFlags(&e1, cudaEventDisableTiming);
    cudaEventCreateWithFlags(&e2, cudaEventDisableTiming);

    // root work on the (captured) default stream, then fork
    init_twd<<<4, 256>>>(twd);
    cudaEventRecord(e0, 0);
    cudaStreamWaitEvent(s1, e0, 0);
    cudaStreamWaitEvent(s2, e0, 0);

    // ── chain A (s1): filter FFN -> filter spectra ──
    transpose_h<<<dim3(DFF / 32, DIM / 32), dim3(32, 8), 0, s1>>>(wp1, wp1t, DIM, DFF);
    transpose_h<<<dim3(DIM / 32, DFF / 32), dim3(32, 8), 0, s1>>>(wp2, wp2t, DFF, DIM);
    cvt_f32_h<<<(LEN * DIM + 255) / 256, 256, 0, s1>>>(pos, pos16, LEN * DIM);
    gemm_mma<1, true, false><<<dim3(DFF / GBN, LEN / GBM), GTHREADS, GEMM_SMEM, s1>>>(
        pos16, wp1t, bp1, nullptr, nullptr, H16, LEN, DFF, DIM);
    gemm_mma<0, false, false><<<dim3(DIM / GBN, LEN / GBM), GTHREADS, GEMM_SMEM, s1>>>(
        H16, wp2t, bp2, nullptr, hfilt, nullptr, LEN, DIM, DFF);
    transpose32f<<<dim3(DIM / 32, LEN / 32, 1), dim3(32, 8), 0, s1>>>(hfilt, hfiltT, LEN, DIM);
    filter_fft_packed<<<DIM / 2, 256, 0, s1>>>(hfiltT, a, wfh, twd);

    // ── chain B (s2): LN(z) + transposes + main-weight prep ──
    layernorm_rows<<<BATCH * LEN, 256, 0, s2>>>(z, ln_g, ln_b, lnz);
    transpose32f<<<dim3(DIM / 32, LEN / 32, BATCH), dim3(32, 8), 0, s2>>>(lnz, lnzT, LEN, DIM);
    transpose32f<<<dim3(DIM / 32, LEN / 32, 1), dim3(32, 8), 0, s2>>>(hidden, hidT, LEN, DIM);
    transpose_h<<<dim3(DFF / 32, DIM / 32), dim3(32, 8), 0, s2>>>(w1, w1t, DIM, DFF);
    transpose_h<<<dim3(DIM / 32, DFF / 32), dim3(32, 8), 0, s2>>>(w2, w2t, DFF, DIM);

    // join
    cudaEventRecord(e1, s1);
    cudaEventRecord(e2, s2);
    cudaStreamWaitEvent(0, e1, 0);
    cudaStreamWaitEvent(0, e2, 0);

    // ── tail (default stream, serial) ──
    fftconv_packed<<<(BATCH / 2) * DIM, 256>>>(lnzT, wfh, hidT, znewT, twd);
    transpose32f_h<<<dim3(LEN / 32, DIM / 32, BATCH), dim3(32, 8)>>>(znewT, znew16, DIM, LEN);
    layernorm_rows_hh<<<BATCH * LEN, 256>>>(znew16, ln_g, ln_b, X16);
    gemm_mma<1, true, false><<<dim3(DFF / GBN, (BATCH * LEN) / GBM), GTHREADS, GEMM_SMEM>>>(
        X16, w1t, b1, nullptr, nullptr, H16, BATCH * LEN, DFF, DIM);
    gemm_mma<0, false, true><<<dim3(DIM / GBN, (BATCH * LEN) / GBM), GTHREADS, GEMM_SMEM>>>(
        H16, w2t, b2, znew16, out, nullptr, BATCH * LEN, DIM, DFF);

    // cleanup — only when NOT capturing
    cudaStreamCaptureStatus cs = cudaStreamCaptureStatusNone;
    cudaStreamIsCapturing(0, &cs);
    if (cs == cudaStreamCaptureStatusNone) {
        cudaStreamDestroy(s1);
        cudaStreamDestroy(s2);
        cudaEventDestroy(e0);
        cudaEventDestroy(e1);
        cudaEventDestroy(e2);
    }
}

// round 14
// speedup vs baseline: 2.4247x; 1.0025x over previous
#include <cuda_runtime.h>
#include <cuda_fp16.h>
#include <cuda_bf16.h>
#include <math.h>
#include <cstdint>

// Problem constants
#define BATCH 8
#define LEN   2048
#define DIM   1024
#define DFF   4096
#define NFFT  4096
#define LN_EPS 1e-5f

// ---------------------------------------------------------------------------
// Static device scratch (no allocation allowed)
// ---------------------------------------------------------------------------
__device__ float  g_lnz  [BATCH * LEN * DIM];
__device__ float  g_lnzT [BATCH * DIM * LEN];
__device__ float  g_hfilt[LEN * DIM];
__device__ float  g_hfiltT[DIM * LEN];
__device__ float  g_hidT [DIM * LEN];
__device__ float2 g_wfh  [DIM * NFFT];            // full spectra, digit-reversed, pre-scaled by 1/N
__device__ float2 g_twd  [1024];
__device__ __half g_znewT16[BATCH * DIM * LEN];   // conv+hidden residual, fp16 [b][d][t]
__device__ __half g_znew16[BATCH * LEN * DIM];    // fp16 row-major
__device__ __half g_X16 [BATCH * LEN * DIM];      // LN(znew) fp16
__device__ __half g_H16 [BATCH * LEN * DFF];      // FFN hidden fp16
__device__ __half g_pos16[LEN * DIM];
// transposed fp16 weights: [N, K] layout
__device__ __half g_wp1t[DFF * DIM];
__device__ __half g_wp2t[DIM * DFF];
__device__ __half g_w1t [DFF * DIM];
__device__ __half g_w2t [DIM * DFF];

// ---------------------------------------------------------------------------
// PTX wrappers (baseline sm_80+ only)
// ---------------------------------------------------------------------------
__device__ __forceinline__ uint32_t smem_u32(const void* p) {
    uint32_t a;
    asm("{ .reg .u64 t; cvta.to.shared.u64 t, %1; cvt.u32.u64 %0, t; }"
        : "=r"(a) : "l"(p));
    return a;
}
__device__ __forceinline__ void cpasync16(uint32_t s, const void* g) {
    asm volatile("cp.async.cg.shared.global [%0], [%1], 16;"
                 :: "r"(s), "l"(g) : "memory");
}
__device__ __forceinline__ void cp_commit() {
    asm volatile("cp.async.commit_group;" ::: "memory");
}
template <int N>
__device__ __forceinline__ void cp_wait() {
    asm volatile("cp.async.wait_group %0;" :: "n"(N) : "memory");
}
__device__ __forceinline__ void ldm_x4(uint32_t& r0, uint32_t& r1,
                                       uint32_t& r2, uint32_t& r3, uint32_t a) {
    asm volatile("ldmatrix.sync.aligned.m8n8.x4.shared.b16 {%0,%1,%2,%3}, [%4];"
                 : "=r"(r0), "=r"(r1), "=r"(r2), "=r"(r3) : "r"(a));
}
__device__ __forceinline__ void ldm_x2(uint32_t& r0, uint32_t& r1, uint32_t a) {
    asm volatile("ldmatrix.sync.aligned.m8n8.x2.shared.b16 {%0,%1}, [%2];"
                 : "=r"(r0), "=r"(r1) : "r"(a));
}
__device__ __forceinline__ void mma_f16(float4& d, const uint32_t* a,
                                        uint32_t b0, uint32_t b1) {
    asm volatile(
        "mma.sync.aligned.m16n8k16.row.col.f32.f16.f16.f32 "
        "{%0,%1,%2,%3}, {%4,%5,%6,%7}, {%8,%9}, {%0,%1,%2,%3};"
        : "+f"(d.x), "+f"(d.y), "+f"(d.z), "+f"(d.w)
        : "r"(a[0]), "r"(a[1]), "r"(a[2]), "r"(a[3]), "r"(b0), "r"(b1));
}

// ---------------------------------------------------------------------------
// HMMA fp16 GEMM (unchanged): block 128x128, BK=32, 4 warps, warp tile 64x64,
// 4-stage cp.async, one __syncthreads per k-tile. HAS_ADD residual is fp16.
// ---------------------------------------------------------------------------
#define GBM 128
#define GBN 128
#define GBK 32
#define TPAD 40
#define TILE_B (128 * TPAD * 2)
#define STAGE_B (2 * TILE_B)
#define NSTAGE 4
#define GEMM_SMEM (NSTAGE * STAGE_B)
#define GTHREADS 128

template <int ACT, bool H_OUT, bool HAS_ADD>
__global__ __launch_bounds__(GTHREADS)
void gemm_mma(const __half* __restrict__ A, const __half* __restrict__ B,
              const float* __restrict__ bias, const __half* __restrict__ add,
              float* __restrict__ Cf, __half* __restrict__ Ch,
              int M, int N, int K) {
    extern __shared__ char smem[];
    const uint32_t sbase = smem_u32(smem);
    const int tid  = threadIdx.x;
    const int lane = tid & 31;
    const int wid  = tid >> 5;
    const int wm   = wid & 1;
    const int wn   = wid >> 1;
    const int bm = blockIdx.y * GBM;
    const int bn = blockIdx.x * GBN;

    auto issue_loads = [&](int stage, int k0) {
        const uint32_t sb = sbase + stage * STAGE_B;
#pragma unroll
        for (int p = 0; p < 4; p++) {
            const int idx = p * GTHREADS + tid;
            const int row = idx >> 2;
            const int c0  = idx & 3;
            const uint32_t so = (uint32_t)(row * 80 + c0 * 16);
            const size_t kk = (size_t)k0 + c0 * 8;
            cpasync16(sb + so,          A + (size_t)(bm + row) * K + kk);
            cpasync16(sb + TILE_B + so, B + (size_t)(bn + row) * K + kk);
        }
        cp_commit();
    };

    float4 acc[4][8];
#pragma unroll
    for (int i = 0; i < 4; i++)
#pragma unroll
        for (int j = 0; j < 8; j++) acc[i][j] = make_float4(0.f, 0.f, 0.f, 0.f);

    const int a_row = (lane & 7) + ((lane >> 3) & 1) * 8;
    const int a_kc  = ((lane >> 4) & 1) * 8;
    const int b_row = lane & 7;
    const int b_kc  = ((lane >> 3) & 1) * 8;

    const int NT = K / GBK;
    issue_loads(0, 0);
    issue_loads(1, GBK);

    for (int kt = 0; kt < NT; kt++) {
        cp_wait<1>();
        __syncthreads();
        if (kt + 2 < NT)
            issue_loads((kt + 2) % NSTAGE, (kt + 2) * GBK);

        const uint32_t st = sbase + (kt % NSTAGE) * STAGE_B;
        const uint32_t As = st;
        const uint32_t Bs = st + TILE_B;

#pragma unroll
        for (int k16 = 0; k16 < 2; k16++) {
            uint32_t ah[4][4];
#pragma unroll
            for (int i = 0; i < 4; i++) {
                const uint32_t ao =
                    (uint32_t)((wm * 64 + i * 16 + a_row) * 80 +
                               (k16 * 16 + a_kc) * 2);
                ldm_x4(ah[i][0], ah[i][1], ah[i][2], ah[i][3], As + ao);
            }
#pragma unroll
            for (int j = 0; j < 8; j++) {
                const uint32_t bo =
                    (uint32_t)((wn * 64 + j * 8 + b_row) * 80 +
                               (k16 * 16 + b_kc) * 2);
                uint32_t b0, b1;
                ldm_x2(b0, b1, Bs + bo);
#pragma unroll
                for (int i = 0; i < 4; i++)
                    mma_f16(acc[i][j], ah[i], b0, b1);
            }
        }
    }

    const int qr = lane >> 2;
    const int qc = (lane & 3) * 2;
#pragma unroll
    for (int i = 0; i < 4; i++) {
#pragma unroll
        for (int j = 0; j < 8; j++) {
            const int gr0 = bm + wm * 64 + i * 16 + qr;
            const int gc  = bn + wn * 64 + j * 8 + qc;
            const float b0 = bias[gc];
            const float b1 = bias[gc + 1];
            float v00 = acc[i][j].x + b0, v01 = acc[i][j].y + b1;
            float v10 = acc[i][j].z + b0, v11 = acc[i][j].w + b1;
            if (ACT == 1) {
                v00 = v00 / (1.0f + expf(-v00));
                v01 = v01 / (1.0f + expf(-v01));
                v10 = v10 / (1.0f + expf(-v10));
                v11 = v11 / (1.0f + expf(-v11));
            }
            if (HAS_ADD) {
                __half2 a0 = *reinterpret_cast<const __half2*>(add + (size_t)gr0 * N + gc);
                __half2 a1 = *reinterpret_cast<const __half2*>(add + (size_t)(gr0 + 8) * N + gc);
                v00 += __half2float(a0.x);
                v01 += __half2float(a0.y);
                v10 += __half2float(a1.x);
                v11 += __half2float(a1.y);
            }
            if (H_OUT) {
                *reinterpret_cast<__half2*>(Ch + (size_t)gr0 * N + gc) =
                    __halves2half2(__float2half_rn(v00), __float2half_rn(v01));
                *reinterpret_cast<__half2*>(Ch + (size_t)(gr0 + 8) * N + gc) =
                    __halves2half2(__float2half_rn(v10), __float2half_rn(v11));
            } else {
                *reinterpret_cast<float2*>(Cf + (size_t)gr0 * N + gc) =
                    make_float2(v00, v01);
                *reinterpret_cast<float2*>(Cf + (size_t)(gr0 + 8) * N + gc) =
                    make_float2(v10, v11);
            }
        }
    }
}

// ---------------------------------------------------------------------------
// Prep kernels
// ---------------------------------------------------------------------------
__global__ void transpose_h(const float* __restrict__ W,
                            __half* __restrict__ T, int K, int N) {
    __shared__ float t[32][33];
    const int n0 = blockIdx.x * 32, k0 = blockIdx.y * 32;
    const int tx = threadIdx.x, ty = threadIdx.y;
#pragma unroll
    for (int dy = 0; dy < 32; dy += 8)
        t[ty + dy][tx] = W[(size_t)(k0 + ty + dy) * N + n0 + tx];
    __syncthreads();
#pragma unroll
    for (int dy = 0; dy < 32; dy += 8) {
        const int n = n0 + ty + dy, k = k0 + tx;
        T[(size_t)n * K + k] = __float2half_rn(t[tx][ty + dy]);
    }
}

__global__ void cvt_f32_h(const float* __restrict__ x, __half* __restrict__ h, int n) {
    int i = blockIdx.x * 256 + threadIdx.x;
    if (i < n) h[i] = __float2half_rn(x[i]);
}

__global__ void transpose32f(const float* __restrict__ in, float* __restrict__ out,
                             int R, int C) {
    __shared__ float t[32][33];
    const size_t boff = (size_t)blockIdx.z * R * C;
    const float* ip = in + boff;
    float* op = out + boff;
    const int r0 = blockIdx.y * 32, c0 = blockIdx.x * 32;
    const int tx = threadIdx.x, ty = threadIdx.y;
#pragma unroll
    for (int dy = 0; dy < 32; dy += 8)
        t[ty + dy][tx] = ip[(size_t)(r0 + ty + dy) * C + c0 + tx];
    __syncthreads();
#pragma unroll
    for (int dy = 0; dy < 32; dy += 8)
        op[(size_t)(c0 + ty + dy) * R + r0 + tx] = t[tx][ty + dy];
}

// fp16 -> fp16 transpose (znewT16 -> znew16)
__global__ void transpose_hh(const __half* __restrict__ in, __half* __restrict__ out,
                             int R, int C) {
    __shared__ __half t[32][34];
    const __half* ip = in + (size_t)blockIdx.z * R * C;
    __half* op = out + (size_t)blockIdx.z * R * C;
    const int r0 = blockIdx.y * 32, c0 = blockIdx.x * 32;
    const int tx = threadIdx.x, ty = threadIdx.y;
#pragma unroll
    for (int dy = 0; dy < 32; dy += 8)
        t[ty + dy][tx] = ip[(size_t)(r0 + ty + dy) * C + c0 + tx];
    __syncthreads();
#pragma unroll
    for (int dy = 0; dy < 32; dy += 8)
        op[(size_t)(c0 + ty + dy) * R + r0 + tx] = t[tx][ty + dy];
}

__global__ void init_twd(float2* __restrict__ twd) {
    int k = blockIdx.x * 256 + threadIdx.x;
    if (k < 1024) {
        double s, c;
        sincos(-6.283185307179586476925286766559 * (double)k / 4096.0, &s, &c);
        twd[k] = make_float2((float)c, (float)s);
    }
}

// ---------------------------------------------------------------------------
// Radix-4 FFT, 4096 points, 256 threads, twiddles from gmem (L1/L2 hot).
// ---------------------------------------------------------------------------
#define PIDX(i) ((i) + ((i) >> 4))

__device__ __forceinline__ float2 cmul(float2 a, float2 b) {
    return make_float2(a.x * b.x - a.y * b.y, a.x * b.y + a.y * b.x);
}
__device__ __forceinline__ int rev4(int p) {
    int b = __brev(p) >> 20;
    return ((b & 0x555) << 1) | ((b >> 1) & 0x555);
}

__device__ void fft4096_dif_pad(float2* sm, const float2* __restrict__ tw) {
    const int tid = threadIdx.x;
    __syncthreads();
#pragma unroll
    for (int u = 0; u < 4; u++) {
        const int j = tid + u * 256;
        float2 x0 = sm[PIDX(j)];
        float2 x1 = sm[PIDX(j + 1024)];
        float2 w1 = __ldg(&tw[j]);
        float2 w2 = cmul(w1, w1);
        float2 w3 = cmul(w2, w1);
        float2 y0 = make_float2(x0.x + x1.x, x0.y + x1.y);
        float2 y1 = make_float2(x0.x + x1.y, x0.y - x1.x);
        float2 y2 = make_float2(x0.x - x1.x, x0.y - x1.y);
        float2 y3 = make_float2(x0.x - x1.y, x0.y + x1.x);
        sm[PIDX(j)]        = y0;
        sm[PIDX(j + 1024)] = cmul(y1, w1);
        sm[PIDX(j + 2048)] = cmul(y2, w2);
        sm[PIDX(j + 3072)] = cmul(y3, w3);
    }
    __syncthreads();
#pragma unroll
    for (int len = 1024; len >= 4; len >>= 2) {
        const int q = len >> 2;
        const int S = NFFT / len;
#pragma unroll
        for (int u = 0; u < 4; u++) {
            const int bf = tid + u * 256;
            const int g  = bf / q;
            const int j  = bf - g * q;
            const int base = g * len + j;
            float2 x0 = sm[PIDX(base)];
            float2 x1 = sm[PIDX(base + q)];
            float2 x2 = sm[PIDX(base + 2 * q)];
            float2 x3 = sm[PIDX(base + 3 * q)];
            float2 t0 = make_float2(x0.x + x2.x, x0.y + x2.y);
            float2 t1 = make_float2(x0.x - x2.x, x0.y - x2.y);
            float2 t2 = make_float2(x1.x + x3.x, x1.y + x3.y);
            float2 t3 = make_float2(x1.x - x3.x, x1.y - x3.y);
            float2 y0 = make_float2(t0.x + t2.x, t0.y + t2.y);
            float2 y2 = make_float2(t0.x - t2.x, t0.y - t2.y);
            float2 y1 = make_float2(t1.x + t3.y, t1.y - t3.x);
            float2 y3 = make_float2(t1.x - t3.y, t1.y + t3.x);
            float2 w1 = __ldg(&tw[j * S]);
            float2 w2 = cmul(w1, w1);
            float2 w3 = cmul(w2, w1);
            sm[PIDX(base)]         = y0;
            sm[PIDX(base + q)]     = cmul(y1, w1);
            sm[PIDX(base + 2 * q)] = cmul(y2, w2);
            sm[PIDX(base + 3 * q)] = cmul(y3, w3);
        }
        __syncthreads();
    }
}

__device__ void fft4096_dit_inv_mul(float2* sm, const float2* __restrict__ tw,
                                    const float2* __restrict__ F) {
    const int tid = threadIdx.x;
    __syncthreads();
#pragma unroll
    for (int u = 0; u < 4; u++) {
        const int g = tid + u * 256;
        const int base = g * 4;
        float2 x0 = sm[PIDX(base)];
        float2 x1 = sm[PIDX(base + 1)];
        float2 x2 = sm[PIDX(base + 2)];
        float2 x3 = sm[PIDX(base + 3)];
        if (F) {
            x0 = cmul(x0, __ldg(&F[base]));
            x1 = cmul(x1, __ldg(&F[base + 1]));
            x2 = cmul(x2, __ldg(&F[base + 2]));
            x3 = cmul(x3, __ldg(&F[base + 3]));
        }
        float2 t0 = make_float2(x0.x + x2.x, x0.y + x2.y);
        float2 t1 = make_float2(x0.x - x2.x, x0.y - x2.y);
        float2 t2 = make_float2(x1.x + x3.x, x1.y + x3.y);
        float2 t3 = make_float2(x1.x - x3.x, x1.y - x3.y);
        sm[PIDX(base)]     = make_float2(t0.x + t2.x, t0.y + t2.y);
        sm[PIDX(base + 2)] = make_float2(t0.x - t2.x, t0.y - t2.y);
        sm[PIDX(base + 1)] = make_float2(t1.x - t3.y, t1.y + t3.x);
        sm[PIDX(base + 3)] = make_float2(t1.x + t3.y, t1.y - t3.x);
    }
    __syncthreads();
#pragma unroll
    for (int st = 1; st < 6; st++) {
        const int len = 4 << (2 * st);
        const int q   = len >> 2;
        const int S   = NFFT / len;
#pragma unroll
        for (int u = 0; u < 4; u++) {
            const int bf = tid + u * 256;
            const int g  = bf / q;
            const int j  = bf - g * q;
            const int base = g * len + j;
            float2 x0 = sm[PIDX(base)];
            float2 x1 = sm[PIDX(base + q)];
            float2 x2 = sm[PIDX(base + 2 * q)];
            float2 x3 = sm[PIDX(base + 3 * q)];
            float2 w1 = __ldg(&tw[j * S]);
            w1.y = -w1.y;
            float2 w2 = cmul(w1, w1);
            float2 w3 = cmul(w1, w2);
            x1 = cmul(x1, w1);
            x2 = cmul(x2, w2);
            x3 = cmul(x3, w3);
            float2 t0 = make_float2(x0.x + x2.x, x0.y + x2.y);
            float2 t1 = make_float2(x0.x - x2.x, x0.y - x2.y);
            float2 t2 = make_float2(x1.x + x3.x, x1.y + x3.y);
            float2 t3 = make_float2(x1.x - x3.x, x1.y - x3.y);
            sm[PIDX(base)]         = make_float2(t0.x + t2.x, t0.y + t2.y);
            sm[PIDX(base + 2 * q)] = make_float2(t0.x - t2.x, t0.y - t2.y);
            sm[PIDX(base + q)]     = make_float2(t1.x - t3.y, t1.y + t3.x);
            sm[PIDX(base + 3 * q)] = make_float2(t1.x + t3.y, t1.y - t3.x);
        }
        __syncthreads();
    }
}

// ---------------------------------------------------------------------------
// Filter spectra: 2 channels per block, full digit-reversed, pre-scaled 1/N.
// ---------------------------------------------------------------------------
__global__ __launch_bounds__(256)
void filter_fft_packed(const float* __restrict__ hfiltT,
                       const float* __restrict__ a,
                       float2* __restrict__ wfh,
                       const float2* __restrict__ twd) {
    __shared__ float2 sd[PIDX(NFFT)];
    const int tid = threadIdx.x;
    const int d0 = blockIdx.x * 2;
    const int d1 = d0 + 1;
    const float ea = expf(a[0]);
    for (int t = tid; t < LEN; t += 256) {
        const float w = expf(-(float)t * ea);
        sd[PIDX(t)] = make_float2(hfiltT[(size_t)d0 * LEN + t] * w,
                                  hfiltT[(size_t)d1 * LEN + t] * w);
    }
    fft4096_dif_pad(sd, twd);
    const float inv = 1.0f / (float)NFFT;
    for (int p = tid; p < NFFT; p += 256) {
        const int k  = rev4(p);
        const int k2 = (NFFT - k) & (NFFT - 1);
        const int p2 = rev4(k2);
        float2 X1 = sd[PIDX(p)];
        float2 X2 = sd[PIDX(p2)];
        wfh[(size_t)d0 * NFFT + p] =
            make_float2(0.5f * inv * (X1.x + X2.x), 0.5f * inv * (X1.y - X2.y));
        wfh[(size_t)d1 * NFFT + p] =
            make_float2(0.5f * inv * (X1.y + X2.y), -0.5f * inv * (X1.x - X2.x));
    }
}

// ---------------------------------------------------------------------------
// FFT convolution over a group of batches (pointers pre-offset by caller).
// Two batches per block; fp16 transposed output.
// ---------------------------------------------------------------------------
__global__ __launch_bounds__(256)
void fftconv_packed(const float* __restrict__ lnzT,
                    const float2* __restrict__ wfh,
                    const float* __restrict__ hidT,
                    __half* __restrict__ znewT16,
                    const float2* __restrict__ twd) {
    __shared__ float2 sd[PIDX(NFFT)];
    const int tid = threadIdx.x;
    const int d  = blockIdx.x & (DIM - 1);
    const int bp = blockIdx.x >> 10;          // batch pair within group
    const int b0 = bp * 2;
    const int b1 = b0 + 1;
    const float* x0 = lnzT + ((size_t)b0 * DIM + d) * LEN;
    const float* x1 = lnzT + ((size_t)b1 * DIM + d) * LEN;
    for (int t = tid; t < LEN; t += 256)
        sd[PIDX(t)] = make_float2(x0[t], x1[t]);

    fft4096_dif_pad(sd, twd);
    fft4096_dit_inv_mul(sd, twd, wfh + (size_t)d * NFFT);

    __half* o0 = znewT16 + ((size_t)b0 * DIM + d) * LEN;
    __half* o1 = znewT16 + ((size_t)b1 * DIM + d) * LEN;
    const float* h = hidT + (size_t)d * LEN;
    for (int t = tid; t < LEN; t += 256) {
        float2 v = sd[PIDX(t)];
        const float hv = h[t];
        o0[t] = __float2half_rn(v.x + hv);
        o1[t] = __float2half_rn(v.y + hv);
    }
}

// ---------------------------------------------------------------------------
// LayerNorm kernels
// ---------------------------------------------------------------------------
__global__ void layernorm_rows(const float* __restrict__ x,
                               const float* __restrict__ gvec,
                               const float* __restrict__ bvec,
                               float* __restrict__ y) {
    const int row = blockIdx.x;
    const int tid = threadIdx.x;
    const float4 v = reinterpret_cast<const float4*>(x + (size_t)row * DIM)[tid];
    float s  = v.x + v.y + v.z + v.w;
    float s2 = v.x * v.x + v.y * v.y + v.z * v.z + v.w * v.w;
    __shared__ float rs[256], rs2[256];
    rs[tid] = s; rs2[tid] = s2;
    __syncthreads();
    for (int o = 128; o > 0; o >>= 1) {
        if (tid < o) { rs[tid] += rs[tid + o]; rs2[tid] += rs2[tid + o]; }
        __syncthreads();
    }
    const float mean = rs[0] * (1.0f / DIM);
    const float var  = rs2[0] * (1.0f / DIM) - mean * mean;
    const float rstd = rsqrtf(var + LN_EPS);
    const float4 gg = reinterpret_cast<const float4*>(gvec)[tid];
    const float4 bb = reinterpret_cast<const float4*>(bvec)[tid];
    float4 o;
    o.x = (v.x - mean) * rstd * gg.x + bb.x;
    o.y = (v.y - mean) * rstd * gg.y + bb.y;
    o.z = (v.z - mean) * rstd * gg.z + bb.z;
    o.w = (v.w - mean) * rstd * gg.w + bb.w;
    reinterpret_cast<float4*>(y + (size_t)row * DIM)[tid] = o;
}

__global__ void layernorm_rows_hh(const __half* __restrict__ x,
                                  const float* __restrict__ gvec,
                                  const float* __restrict__ bvec,
                                  __half* __restrict__ yh) {
    const int row = blockIdx.x;
    const int tid = threadIdx.x;
    const ushort4 raw = reinterpret_cast<const ushort4*>(x + (size_t)row * DIM)[tid];
    const __half* hv = reinterpret_cast<const __half*>(&raw);
    float v[4];
#pragma unroll
    for (int j = 0; j < 4; j++) v[j] = __half2float(hv[j]);
    float s  = v[0] + v[1] + v[2] + v[3];
    float s2 = v[0] * v[0] + v[1] * v[1] + v[2] * v[2] + v[3] * v[3];
    __shared__ float rs[256], rs2[256];
    rs[tid] = s; rs2[tid] = s2;
    __syncthreads();
    for (int o = 128; o > 0; o >>= 1) {
        if (tid < o) { rs[tid] += rs[tid + o]; rs2[tid] += rs2[tid + o]; }
        __syncthreads();
    }
    const float mean = rs[0] * (1.0f / DIM);
    const float var  = rs2[0] * (1.0f / DIM) - mean * mean;
    const float rstd = rsqrtf(var + LN_EPS);
    const float4 gg = reinterpret_cast<const float4*>(gvec)[tid];
    const float4 bb = reinterpret_cast<const float4*>(bvec)[tid];
    __half h[4];
    h[0] = __float2half_rn((v[0] - mean) * rstd * gg.x + bb.x);
    h[1] = __float2half_rn((v[1] - mean) * rstd * gg.y + bb.y);
    h[2] = __float2half_rn((v[2] - mean) * rstd * gg.z + bb.z);
    h[3] = __float2half_rn((v[3] - mean) * rstd * gg.w + bb.w);
    *reinterpret_cast<ushort4*>(yh + (size_t)row * DIM + tid * 4) =
        *reinterpret_cast<ushort4*>(h);
}

// ---------------------------------------------------------------------------
// Launch: forked front halves + batch-pipelined tail (2 groups of 4 batches).
// ---------------------------------------------------------------------------
extern "C" void kernel_launch(void* const* d_in, const int* in_sizes, int n_in,
                              void* d_out, int out_size) {
    const float* z      = (const float*)d_in[0];
    const float* pos    = (const float*)d_in[1];
    const float* a      = (const float*)d_in[2];
    const float* hidden = (const float*)d_in[3];
    const float* ln_g   = (const float*)d_in[4];
    const float* ln_b   = (const float*)d_in[5];
    const float* wp1    = (const float*)d_in[6];
    const float* bp1    = (const float*)d_in[7];
    const float* wp2    = (const float*)d_in[8];
    const float* bp2    = (const float*)d_in[9];
    const float* w1     = (const float*)d_in[10];
    const float* b1     = (const float*)d_in[11];
    const float* w2     = (const float*)d_in[12];
    const float* b2     = (const float*)d_in[13];
    float* out = (float*)d_out;

    float *lnz, *lnzT, *hfilt, *hfiltT, *hidT;
    float2 *wfh, *twd;
    __half *znewT16, *znew16, *X16, *H16, *pos16, *wp1t, *wp2t, *w1t, *w2t;
    cudaGetSymbolAddress((void**)&lnz,     g_lnz);
    cudaGetSymbolAddress((void**)&lnzT,    g_lnzT);
    cudaGetSymbolAddress((void**)&hfilt,   g_hfilt);
    cudaGetSymbolAddress((void**)&hfiltT,  g_hfiltT);
    cudaGetSymbolAddress((void**)&hidT,    g_hidT);
    cudaGetSymbolAddress((void**)&wfh,     g_wfh);
    cudaGetSymbolAddress((void**)&twd,     g_twd);
    cudaGetSymbolAddress((void**)&znewT16, g_znewT16);
    cudaGetSymbolAddress((void**)&znew16,  g_znew16);
    cudaGetSymbolAddress((void**)&X16,     g_X16);
    cudaGetSymbolAddress((void**)&H16,     g_H16);
    cudaGetSymbolAddress((void**)&pos16,   g_pos16);
    cudaGetSymbolAddress((void**)&wp1t,    g_wp1t);
    cudaGetSymbolAddress((void**)&wp2t,    g_wp2t);
    cudaGetSymbolAddress((void**)&w1t,     g_w1t);
    cudaGetSymbolAddress((void**)&w2t,     g_w2t);

    cudaFuncSetAttribute(gemm_mma<1, true,  false>,
                         cudaFuncAttributeMaxDynamicSharedMemorySize, GEMM_SMEM);
    cudaFuncSetAttribute(gemm_mma<0, false, false>,
                         cudaFuncAttributeMaxDynamicSharedMemorySize, GEMM_SMEM);
    cudaFuncSetAttribute(gemm_mma<0, false, true>,
                         cudaFuncAttributeMaxDynamicSharedMemorySize, GEMM_SMEM);

    cudaStream_t s1, s2;
    cudaStreamCreateWithFlags(&s1, cudaStreamNonBlocking);
    cudaStreamCreateWithFlags(&s2, cudaStreamNonBlocking);
    cudaEvent_t e0, eA, eB, eF1, eT1, eT2;
    cudaEventCreateWithFlags(&e0,  cudaEventDisableTiming);
    cudaEventCreateWithFlags(&eA,  cudaEventDisableTiming);
    cudaEventCreateWithFlags(&eB,  cudaEventDisableTiming);
    cudaEventCreateWithFlags(&eF1, cudaEventDisableTiming);
    cudaEventCreateWithFlags(&eT1, cudaEventDisableTiming);
    cudaEventCreateWithFlags(&eT2, cudaEventDisableTiming);

    // root
    init_twd<<<4, 256>>>(twd);
    cudaEventRecord(e0, 0);
    cudaStreamWaitEvent(s1, e0, 0);
    cudaStreamWaitEvent(s2, e0, 0);

    // ── chain A (s1): filter FFN -> filter spectra ──
    transpose_h<<<dim3(DFF / 32, DIM / 32), dim3(32, 8), 0, s1>>>(wp1, wp1t, DIM, DFF);
    transpose_h<<<dim3(DIM / 32, DFF / 32), dim3(32, 8), 0, s1>>>(wp2, wp2t, DFF, DIM);
    cvt_f32_h<<<(LEN * DIM + 255) / 256, 256, 0, s1>>>(pos, pos16, LEN * DIM);
    gemm_mma<1, true, false><<<dim3(DFF / GBN, LEN / GBM), GTHREADS, GEMM_SMEM, s1>>>(
        pos16, wp1t, bp1, nullptr, nullptr, H16, LEN, DFF, DIM);
    gemm_mma<0, false, false><<<dim3(DIM / GBN, LEN / GBM), GTHREADS, GEMM_SMEM, s1>>>(
        H16, wp2t, bp2, nullptr, hfilt, nullptr, LEN, DIM, DFF);
    transpose32f<<<dim3(DIM / 32, LEN / 32, 1), dim3(32, 8), 0, s1>>>(hfilt, hfiltT, LEN, DIM);
    filter_fft_packed<<<DIM / 2, 256, 0, s1>>>(hfiltT, a, wfh, twd);
    cudaEventRecord(eA, s1);

    // ── chain B (s2): LN(z) + transposes + main-weight prep ──
    layernorm_rows<<<BATCH * LEN, 256, 0, s2>>>(z, ln_g, ln_b, lnz);
    transpose32f<<<dim3(DIM / 32, LEN / 32, BATCH), dim3(32, 8), 0, s2>>>(lnz, lnzT, LEN, DIM);
    transpose32f<<<dim3(DIM / 32, LEN / 32, 1), dim3(32, 8), 0, s2>>>(hidden, hidT, LEN, DIM);
    transpose_h<<<dim3(DFF / 32, DIM / 32), dim3(32, 8), 0, s2>>>(w1, w1t, DIM, DFF);
    transpose_h<<<dim3(DIM / 32, DFF / 32), dim3(32, 8), 0, s2>>>(w2, w2t, DFF, DIM);
    cudaEventRecord(eB, s2);

    // cross-join: s1 gets chain-B results, s2 gets chain-A results
    cudaStreamWaitEvent(s1, eB, 0);
    cudaStreamWaitEvent(s2, eA, 0);

    const int GB = BATCH / 2;                 // 4 batches per group
    const size_t offD = (size_t)GB * DIM * LEN;   // group offset, [b][d][t] elems
    const size_t offR = (size_t)GB * LEN * DIM;   // group offset, row-major elems
    const size_t offH = (size_t)GB * LEN * DFF;

    // ── tail group 1 (s1): batches 0-3 ──
    fftconv_packed<<<(GB / 2) * DIM, 256, 0, s1>>>(lnzT, wfh, hidT, znewT16, twd);
    cudaEventRecord(eF1, s1);
    transpose_hh<<<dim3(LEN / 32, DIM / 32, GB), dim3(32, 8), 0, s1>>>(
        znewT16, znew16, DIM, LEN);
    layernorm_rows_hh<<<GB * LEN, 256, 0, s1>>>(znew16, ln_g, ln_b, X16);
    gemm_mma<1, true, false><<<dim3(DFF / GBN, (GB * LEN) / GBM), GTHREADS, GEMM_SMEM, s1>>>(
        X16, w1t, b1, nullptr, nullptr, H16, GB * LEN, DFF, DIM);
    gemm_mma<0, false, true><<<dim3(DIM / GBN, (GB * LEN) / GBM), GTHREADS, GEMM_SMEM, s1>>>(
        H16, w2t, b2, znew16, out, nullptr, GB * LEN, DIM, DFF);
    cudaEventRecord(eT1, s1);

    // ── tail group 2 (s2): batches 4-7, starts once fftconv(G1) clears ──
    cudaStreamWaitEvent(s2, eF1, 0);
    fftconv_packed<<<(GB / 2) * DIM, 256, 0, s2>>>(
        lnzT + offD, wfh, hidT, znewT16 + offD, twd);
    transpose_hh<<<dim3(LEN / 32, DIM / 32, GB), dim3(32, 8), 0, s2>>>(
        znewT16 + offD, znew16 + offR, DIM, LEN);
    layernorm_rows_hh<<<GB * LEN, 256, 0, s2>>>(znew16 + offR, ln_g, ln_b, X16 + offR);
    gemm_mma<1, true, false><<<dim3(DFF / GBN, (GB * LEN) / GBM), GTHREADS, GEMM_SMEM, s2>>>(
        X16 + offR, w1t, b1, nullptr, nullptr, H16 + offH, GB * LEN, DFF, DIM);
    gemm_mma<0, false, true><<<dim3(DIM / GBN, (GB * LEN) / GBM), GTHREADS, GEMM_SMEM, s2>>>(
        H16 + offH, w2t, b2, znew16 + offR, out + offR, nullptr, GB * LEN, DIM, DFF);
    cudaEventRecord(eT2, s2);

    // final join to default stream
    cudaStreamWaitEvent(0, eT1, 0);
    cudaStreamWaitEvent(0, eT2, 0);

    // cleanup — only when NOT capturing
    cudaStreamCaptureStatus cs = cudaStreamCaptureStatusNone;
    cudaStreamIsCapturing(0, &cs);
    if (cs == cudaStreamCaptureStatusNone) {
        cudaStreamDestroy(s1);
        cudaStreamDestroy(s2);
        cudaEventDestroy(e0);
        cudaEventDestroy(eA);
        cudaEventDestroy(eB);
        cudaEventDestroy(eF1);
        cudaEventDestroy(eT1);
        cudaEventDestroy(eT2);
    }
}